// round 3
// baseline (speedup 1.0000x reference)
#include <cuda_runtime.h>
#include <cuda_bf16.h>
#include <cstdint>

// ---------------- problem constants ----------------
#define B_    16
#define T_    8
#define CIN   2048
#define CI    512
#define HF    14
#define HW    196
#define NROI  512
#define M1    4608          // NROI*9
#define KFEAT 4608          // CI*9
#define NPART 8             // split-K parts for gemm2

// ---------------- scratch (static device memory) ----------------
__device__ __nv_bfloat16 d_roisH[(size_t)M1 * CIN];
__device__ __nv_bfloat16 d_roisL[(size_t)M1 * CIN];
__device__ __nv_bfloat16 d_wH[(size_t)CI * CIN];
__device__ __nv_bfloat16 d_wL[(size_t)CI * CIN];
__device__ __nv_bfloat16 d_rwH[(size_t)CI * KFEAT];   // re_w transposed+permuted [n][bin*512+o]
__device__ __nv_bfloat16 d_rwL[(size_t)CI * KFEAT];
__device__ __nv_bfloat16 d_featsH[(size_t)NROI * KFEAT]; // [roi][bin*512+o]
__device__ __nv_bfloat16 d_featsL[(size_t)NROI * KFEAT];
__device__ float d_regpart[(size_t)NPART * NROI * CI];
__device__ float d_objf[32 * CI];
__device__ float d_pooled[16 * CI];
__device__ float d_h1[32 * CI];
__device__ float d_g1[16 * CI];
__device__ int2  d_tap[NROI * 9 * 16];   // {byte-offset into 197-float row, weight bits}

// ---------------- PTX helpers ----------------
__device__ __forceinline__ uint32_t sm_u32(const void* p) {
    return (uint32_t)__cvta_generic_to_shared(p);
}
__device__ __forceinline__ void cpa16(uint32_t dst, const void* src) {
    asm volatile("cp.async.cg.shared.global [%0], [%1], 16;\n" :: "r"(dst), "l"(src));
}
__device__ __forceinline__ void cpa_commit() {
    asm volatile("cp.async.commit_group;\n" ::: "memory");
}
__device__ __forceinline__ void cpa_wait0() {
    asm volatile("cp.async.wait_group 0;\n" ::: "memory");
}
__device__ __forceinline__ void cpa_wait1() {
    asm volatile("cp.async.wait_group 1;\n" ::: "memory");
}
__device__ __forceinline__ void ldsm4(uint32_t* r, uint32_t addr) {
    asm volatile("ldmatrix.sync.aligned.m8n8.x4.shared.b16 {%0,%1,%2,%3}, [%4];"
                 : "=r"(r[0]), "=r"(r[1]), "=r"(r[2]), "=r"(r[3]) : "r"(addr));
}
__device__ __forceinline__ void mma16816(float* c, const uint32_t* a, uint32_t b0, uint32_t b1) {
    asm volatile("mma.sync.aligned.m16n8k16.row.col.f32.bf16.bf16.f32 "
                 "{%0,%1,%2,%3},{%4,%5,%6,%7},{%8,%9},{%0,%1,%2,%3};"
                 : "+f"(c[0]), "+f"(c[1]), "+f"(c[2]), "+f"(c[3])
                 : "r"(a[0]), "r"(a[1]), "r"(a[2]), "r"(a[3]), "r"(b0), "r"(b1));
}

// ============================================================
// K1: ROI-align tap table (byte offsets, weights folded w/ 0.25 mean)
// ============================================================
__global__ void build_table(const float* __restrict__ boxes) {
    int roi = blockIdx.x * blockDim.x + threadIdx.x;
    if (roi >= NROI) return;
    float cx = boxes[roi * 4 + 0], cy = boxes[roi * 4 + 1];
    float w  = boxes[roi * 4 + 2], h  = boxes[roi * 4 + 3];
    const float s = 14.0f / 224.0f;
    float x1 = (cx - 0.5f * w) * 224.0f * s;
    float y1 = (cy - 0.5f * h) * 224.0f * s;
    float x2 = (cx + 0.5f * w) * 224.0f * s;
    float y2 = (cy + 0.5f * h) * 224.0f * s;
    float rw = fmaxf(x2 - x1, 1.0f), rh = fmaxf(y2 - y1, 1.0f);
    float bw = rw / 3.0f, bh = rh / 3.0f;

    float ys[6], xs[6];
#pragma unroll
    for (int p = 0; p < 3; ++p)
#pragma unroll
        for (int i = 0; i < 2; ++i) {
            ys[p * 2 + i] = y1 + p * bh + (i + 0.5f) * bh * 0.5f;
            xs[p * 2 + i] = x1 + p * bw + (i + 0.5f) * bw * 0.5f;
        }

#pragma unroll
    for (int ph = 0; ph < 3; ++ph)
#pragma unroll
        for (int pw = 0; pw < 3; ++pw) {
            int bin = ph * 3 + pw;
#pragma unroll
            for (int iy = 0; iy < 2; ++iy)
#pragma unroll
                for (int ix = 0; ix < 2; ++ix) {
                    int smp = iy * 2 + ix;
                    float yy = ys[ph * 2 + iy];
                    float xx = xs[pw * 2 + ix];
                    bool valid = (yy > -1.0f) && (yy < 14.0f) && (xx > -1.0f) && (xx < 14.0f);
                    float y = fminf(fmaxf(yy, 0.0f), 13.0f);
                    float x = fminf(fmaxf(xx, 0.0f), 13.0f);
                    int y0 = (int)floorf(y), x0 = (int)floorf(x);
                    int y1i = min(y0 + 1, 13), x1i = min(x0 + 1, 13);
                    float ly = y - (float)y0, lx = x - (float)x0;
                    float hy = 1.0f - ly, hx = 1.0f - lx;
                    float q = valid ? 0.25f : 0.0f;
                    int base = (roi * 9 + bin) * 16 + smp * 4;
                    d_tap[base + 0] = make_int2((y0 * HF + x0) * 4,   __float_as_int(hy * hx * q));
                    d_tap[base + 1] = make_int2((y0 * HF + x1i) * 4,  __float_as_int(hy * lx * q));
                    d_tap[base + 2] = make_int2((y1i * HF + x0) * 4,  __float_as_int(ly * hx * q));
                    d_tap[base + 3] = make_int2((y1i * HF + x1i) * 4, __float_as_int(ly * lx * q));
                }
        }
}

// ============================================================
// K2: pooling in 2048-ch space -> bf16 hi/lo
// block = (bt, 128-channel chunk); 288 threads; taps amortized x4
// ============================================================
#define POOL_SMEM (128 * 197 * 4 + 576 * 8)
__global__ __launch_bounds__(288) void pool_kernel(const float* __restrict__ x) {
    extern __shared__ float psm[];
    float (*pl)[197] = (float(*)[197])psm;
    int2* taps = (int2*)(psm + 128 * 197);

    int bt = blockIdx.y;
    int c0 = blockIdx.x * 128;
    int tid = threadIdx.x, lane = tid & 31, wid = tid >> 5;

    // x layout (B, C, T, H, W); plane x[b, c, t, :, :] = 196 contiguous floats
    size_t base = ((size_t)(bt >> 3) * CIN + c0) * (size_t)(T_ * HW) + (size_t)(bt & 7) * HW;
    for (int c = wid; c < 128; c += 9) {
        const float* src = x + base + (size_t)c * (T_ * HW);
        for (int p = lane; p < HW; p += 32) pl[c][p] = src[p];
    }
    for (int i = tid; i < 576; i += 288) taps[i] = d_tap[bt * 576 + i];
    __syncthreads();

    const char* b0 = (const char*)&pl[lane][0];
    const char* b1 = (const char*)&pl[lane + 32][0];
    const char* b2 = (const char*)&pl[lane + 64][0];
    const char* b3 = (const char*)&pl[lane + 96][0];

#pragma unroll
    for (int j = 0; j < 4; ++j) {
        int e = wid + 9 * j;           // e = nb*9+bin, 36 total over 9 warps
        const int2* tp = &taps[e * 16];
        float a0 = 0.f, a1 = 0.f, a2 = 0.f, a3 = 0.f;
#pragma unroll
        for (int t = 0; t < 16; ++t) {
            int2 pw = tp[t];
            float wv = __int_as_float(pw.y);
            a0 += wv * *(const float*)(b0 + pw.x);
            a1 += wv * *(const float*)(b1 + pw.x);
            a2 += wv * *(const float*)(b2 + pw.x);
            a3 += wv * *(const float*)(b3 + pw.x);
        }
        size_t off = (size_t)(bt * 36 + e) * CIN + c0 + lane;
        float av[4] = {a0, a1, a2, a3};
#pragma unroll
        for (int q = 0; q < 4; ++q) {
            __nv_bfloat16 hb = __float2bfloat16_rn(av[q]);
            d_roisH[off + q * 32] = hb;
            d_roisL[off + q * 32] = __float2bfloat16_rn(av[q] - __bfloat162float(hb));
        }
    }
}

// ============================================================
// K3a: convert conv5_w -> bf16 hi/lo
// ============================================================
__global__ void convw_kernel(const float* __restrict__ w) {
    int i = blockIdx.x * 256 + threadIdx.x;
    float v = w[i];
    __nv_bfloat16 hb = __float2bfloat16_rn(v);
    d_wH[i] = hb;
    d_wL[i] = __float2bfloat16_rn(v - __bfloat162float(hb));
}

// ============================================================
// K3b: convert re_w -> transposed+permuted bf16 hi/lo
// ============================================================
__global__ __launch_bounds__(256) void convrw_kernel(const float* __restrict__ w) {
    __shared__ float t[32][33];
    int o0 = blockIdx.x * 32, n0 = blockIdx.y * 32, bin = blockIdx.z;
    int tx = threadIdx.x & 31, ty = threadIdx.x >> 5;
    for (int r = ty; r < 32; r += 8)
        t[r][tx] = w[((size_t)((o0 + r) * 9 + bin)) * 512 + n0 + tx];
    __syncthreads();
    for (int r = ty; r < 32; r += 8) {
        float v = t[tx][r];
        __nv_bfloat16 hb = __float2bfloat16_rn(v);
        __nv_bfloat16 lb = __float2bfloat16_rn(v - __bfloat162float(hb));
        size_t off = (size_t)(n0 + r) * KFEAT + bin * 512 + o0 + tx;
        d_rwH[off] = hb;
        d_rwL[off] = lb;
    }
}

// ============================================================
// GEMM core: 128x128 tile, bf16 split mma.sync (3 passes), 3-stage cp.async
// ============================================================
#define KT    32
#define SROW  40
#define TILE_E (128 * SROW)
#define STAGE_E (4 * TILE_E)
#define GSMEM_BYTES (3 * STAGE_E * 2)

__device__ __forceinline__ void gemm_core(
    const __nv_bfloat16* __restrict__ gAh, const __nv_bfloat16* __restrict__ gAl, int lda,
    const __nv_bfloat16* __restrict__ gBh, const __nv_bfloat16* __restrict__ gBl, int ldb,
    int bm, int bn, int kbase, int niter,
    __nv_bfloat16* sm, float (&acc)[4][4][4])
{
    int tid = threadIdx.x, lane = tid & 31, wid = tid >> 5;
    int wm = wid >> 2, wn = wid & 3;     // warp tile 64x32

    auto ldg = [&](int t) {
        int s = t % 3;
        int k0 = kbase + t * KT;
        __nv_bfloat16* base = sm + s * STAGE_E;
#pragma unroll
        for (int j = 0; j < 2; ++j) {
            int id = (tid << 1) + j;
            int row = id >> 2, c = id & 3;
            __nv_bfloat16* pd = base + row * SROW + c * 8;
            cpa16(sm_u32(pd),               gAh + (size_t)(bm + row) * lda + k0 + c * 8);
            cpa16(sm_u32(pd + TILE_E),      gAl + (size_t)(bm + row) * lda + k0 + c * 8);
            cpa16(sm_u32(pd + 2 * TILE_E),  gBh + (size_t)(bn + row) * ldb + k0 + c * 8);
            cpa16(sm_u32(pd + 3 * TILE_E),  gBl + (size_t)(bn + row) * ldb + k0 + c * 8);
        }
    };

    int ar  = wm * 64 + (lane & 15);
    int ac8 = (lane >> 4) * 8;
    int br  = wn * 32 + (lane & 7) + ((lane >> 4) << 3);
    int bc8 = ((lane >> 3) & 1) * 8;

    ldg(0); cpa_commit();
    if (niter > 1) { ldg(1); cpa_commit(); }

#pragma unroll 1
    for (int t = 0; t < niter; ++t) {
        if (t + 1 < niter) cpa_wait1(); else cpa_wait0();
        __syncthreads();
        if (t + 2 < niter) { ldg(t + 2); cpa_commit(); }

        __nv_bfloat16* base = sm + (t % 3) * STAGE_E;
        const __nv_bfloat16* pAh = base;
        const __nv_bfloat16* pAl = base + TILE_E;
        const __nv_bfloat16* pBh = base + 2 * TILE_E;
        const __nv_bfloat16* pBl = base + 3 * TILE_E;

#pragma unroll
        for (int ks = 0; ks < 2; ++ks) {
            uint32_t ah[4][4], al[4][4], bh[2][4], bl[2][4];
#pragma unroll
            for (int mt = 0; mt < 4; ++mt) {
                ldsm4(ah[mt], sm_u32(pAh + (ar + mt * 16) * SROW + ks * 16 + ac8));
                ldsm4(al[mt], sm_u32(pAl + (ar + mt * 16) * SROW + ks * 16 + ac8));
            }
#pragma unroll
            for (int bt2 = 0; bt2 < 2; ++bt2) {
                ldsm4(bh[bt2], sm_u32(pBh + (br + bt2 * 16) * SROW + ks * 16 + bc8));
                ldsm4(bl[bt2], sm_u32(pBl + (br + bt2 * 16) * SROW + ks * 16 + bc8));
            }
#pragma unroll
            for (int mt = 0; mt < 4; ++mt)
#pragma unroll
                for (int nt = 0; nt < 4; ++nt) {
                    uint32_t b0h = bh[nt >> 1][(nt & 1) * 2], b1h = bh[nt >> 1][(nt & 1) * 2 + 1];
                    uint32_t b0l = bl[nt >> 1][(nt & 1) * 2], b1l = bl[nt >> 1][(nt & 1) * 2 + 1];
                    mma16816(acc[mt][nt], ah[mt], b0h, b1h);
                    mma16816(acc[mt][nt], al[mt], b0h, b1h);
                    mma16816(acc[mt][nt], ah[mt], b0l, b1l);
                }
        }
    }
}

// ============================================================
// K4: GEMM1: feats = rois2048[4608,2048] x conv5_w[512,2048]^T
// ============================================================
__global__ __launch_bounds__(256) void gemm1k() {
    extern __shared__ __nv_bfloat16 sm[];
    int bm = blockIdx.y * 128, bn = blockIdx.x * 128;
    float acc[4][4][4];
#pragma unroll
    for (int a = 0; a < 4; ++a)
#pragma unroll
        for (int b = 0; b < 4; ++b)
#pragma unroll
            for (int c = 0; c < 4; ++c) acc[a][b][c] = 0.0f;

    gemm_core(d_roisH, d_roisL, CIN, d_wH, d_wL, CIN, bm, bn, 0, CIN / KT, sm, acc);

    int lane = threadIdx.x & 31, wid = threadIdx.x >> 5;
    int wm = wid >> 2, wn = wid & 3;
    int mrow = wm * 64 + (lane >> 2);
    int ncol = wn * 32 + ((lane & 3) << 1);
#pragma unroll
    for (int mt = 0; mt < 4; ++mt)
#pragma unroll
        for (int nt = 0; nt < 4; ++nt) {
            float* c = acc[mt][nt];
            int n = bn + ncol + nt * 8;
#pragma unroll
            for (int half = 0; half < 2; ++half) {
                int m = bm + mrow + mt * 16 + half * 8;
                int roi = m / 9, bin = m - roi * 9;
                size_t off = (size_t)roi * KFEAT + bin * 512 + n;
                float v0 = c[half * 2 + 0], v1 = c[half * 2 + 1];
                __nv_bfloat16 h0 = __float2bfloat16_rn(v0);
                __nv_bfloat16 h1 = __float2bfloat16_rn(v1);
                __nv_bfloat162 hp; hp.x = h0; hp.y = h1;
                __nv_bfloat162 lp;
                lp.x = __float2bfloat16_rn(v0 - __bfloat162float(h0));
                lp.y = __float2bfloat16_rn(v1 - __bfloat162float(h1));
                *(__nv_bfloat162*)&d_featsH[off] = hp;
                *(__nv_bfloat162*)&d_featsL[off] = lp;
            }
        }
}

// ============================================================
// K5: GEMM2 (split-K=8): regpart = feats[512,4608] x rw[512,4608]^T
// ============================================================
__global__ __launch_bounds__(256) void gemm2k() {
    extern __shared__ __nv_bfloat16 sm[];
    int bm = blockIdx.y * 128, bn = blockIdx.x * 128;
    int part = blockIdx.z;
    float acc[4][4][4];
#pragma unroll
    for (int a = 0; a < 4; ++a)
#pragma unroll
        for (int b = 0; b < 4; ++b)
#pragma unroll
            for (int c = 0; c < 4; ++c) acc[a][b][c] = 0.0f;

    gemm_core(d_featsH, d_featsL, KFEAT, d_rwH, d_rwL, KFEAT,
              bm, bn, part * (KFEAT / NPART), (KFEAT / NPART) / KT, sm, acc);

    int lane = threadIdx.x & 31, wid = threadIdx.x >> 5;
    int wm = wid >> 2, wn = wid & 3;
    int mrow = wm * 64 + (lane >> 2);
    int ncol = wn * 32 + ((lane & 3) << 1);
    float* C = d_regpart + (size_t)part * NROI * CI;
#pragma unroll
    for (int mt = 0; mt < 4; ++mt)
#pragma unroll
        for (int nt = 0; nt < 4; ++nt) {
            float* c = acc[mt][nt];
            int n = bn + ncol + nt * 8;
#pragma unroll
            for (int half = 0; half < 2; ++half) {
                int m = bm + mrow + mt * 16 + half * 8;
                *(float2*)&C[(size_t)m * CI + n] = make_float2(c[half * 2], c[half * 2 + 1]);
            }
        }
}

// ============================================================
// K6: sum split-K parts + bias + relu + mean over T + selections
// ============================================================
__global__ void reduce_kernel(const float* __restrict__ re_b,
                              const int* __restrict__ cat,
                              float* __restrict__ out_labels) {
    int b = blockIdx.x, j = threadIdx.x;
    float bias = re_b[j];
    float pool = 0.0f;
#pragma unroll
    for (int nb = 0; nb < 4; ++nb) {
        float s = 0.0f;
#pragma unroll
        for (int t = 0; t < 8; ++t) {
            int r = (b * 8 + t) * 4 + nb;
            float v = bias;
#pragma unroll
            for (int p = 0; p < NPART; ++p) v += d_regpart[(size_t)p * NROI * CI + (size_t)r * CI + j];
            s += fmaxf(v, 0.0f);
        }
        s *= 0.125f;
        if (nb >= 2) d_objf[(b * 2 + nb - 2) * CI + j] = s;   // argsort identity: cats never 0
        pool += s;
    }
    d_pooled[b * CI + j] = pool * 0.25f;
    if (j < 2) out_labels[b * 2 + j] = (float)cat[b * 4 + 2 + j];
}

// ============================================================
// K7: small dense head
// ============================================================
__global__ __launch_bounds__(256) void small_mm(const float* __restrict__ A,
                                                const float* __restrict__ Bm,
                                                const float* __restrict__ bias,
                                                float* __restrict__ C, int N) {
    __shared__ float As[512];
    __shared__ float red[256];
    int m = blockIdx.x, j0 = blockIdx.y * 64;
    int tid = threadIdx.x, jl = tid & 63, ks = tid >> 6;
    for (int k = tid; k < 512; k += 256) As[k] = A[m * 512 + k];
    __syncthreads();
    int j = j0 + jl;
    float acc = 0.0f;
    if (j < N) {
        int k0 = ks * 128;
#pragma unroll 8
        for (int k = k0; k < k0 + 128; ++k) acc += As[k] * Bm[k * N + j];
    }
    red[tid] = acc;
    __syncthreads();
    if (tid < 64 && j < N)
        C[m * N + j] = red[tid] + red[tid + 64] + red[tid + 128] + red[tid + 192] + bias[j];
}

// ============================================================
extern "C" void kernel_launch(void* const* d_in, const int* in_sizes, int n_in,
                              void* d_out, int out_size) {
    const float* x       = (const float*)d_in[0];
    const float* boxes   = (const float*)d_in[1];
    const int*   cat     = (const int*)d_in[2];
    const float* conv5_w = (const float*)d_in[3];
    const float* re_w    = (const float*)d_in[4];
    const float* re_b    = (const float*)d_in[5];
    const float* oc1_w   = (const float*)d_in[6];
    const float* oc1_b   = (const float*)d_in[7];
    const float* oc2_w   = (const float*)d_in[8];
    const float* oc2_b   = (const float*)d_in[9];
    const float* pr1_w   = (const float*)d_in[10];
    const float* pr1_b   = (const float*)d_in[11];
    const float* pr2_w   = (const float*)d_in[12];
    const float* pr2_b   = (const float*)d_in[13];

    float* out     = (float*)d_out;
    float* cls_out = out;                       // 16*174
    float* obj_cls = out + 16 * 174;            // 32*301
    float* labels  = out + 16 * 174 + 32 * 301; // 32

    float *p_objf, *p_pooled, *p_h1, *p_g1;
    cudaGetSymbolAddress((void**)&p_objf,   d_objf);
    cudaGetSymbolAddress((void**)&p_pooled, d_pooled);
    cudaGetSymbolAddress((void**)&p_h1,     d_h1);
    cudaGetSymbolAddress((void**)&p_g1,     d_g1);

    cudaFuncSetAttribute(pool_kernel, cudaFuncAttributeMaxDynamicSharedMemorySize, POOL_SMEM);
    cudaFuncSetAttribute(gemm1k, cudaFuncAttributeMaxDynamicSharedMemorySize, GSMEM_BYTES);
    cudaFuncSetAttribute(gemm2k, cudaFuncAttributeMaxDynamicSharedMemorySize, GSMEM_BYTES);

    build_table<<<2, 256>>>(boxes);
    convw_kernel<<<(CI * CIN) / 256, 256>>>(conv5_w);
    convrw_kernel<<<dim3(16, 16, 9), 256>>>(re_w);
    pool_kernel<<<dim3(CIN / 128, B_ * T_), 288, POOL_SMEM>>>(x);
    gemm1k<<<dim3(CI / 128, M1 / 128), 256, GSMEM_BYTES>>>();
    gemm2k<<<dim3(CI / 128, NROI / 128, NPART), 256, GSMEM_BYTES>>>();
    reduce_kernel<<<16, 512>>>(re_b, cat, labels);
    small_mm<<<dim3(32, 8), 256>>>(p_objf, oc1_w, oc1_b, p_h1, 512);
    small_mm<<<dim3(32, 5), 256>>>(p_h1, oc2_w, oc2_b, obj_cls, 301);
    small_mm<<<dim3(16, 8), 256>>>(p_pooled, pr1_w, pr1_b, p_g1, 512);
    small_mm<<<dim3(16, 3), 256>>>(p_g1, pr2_w, pr2_b, cls_out, 174);
}

// round 4
// speedup vs baseline: 1.7145x; 1.7145x over previous
#include <cuda_runtime.h>
#include <cuda_bf16.h>
#include <cstdint>

// ---------------- problem constants ----------------
#define B_    16
#define T_    8
#define CIN   2048
#define CI    512
#define HF    14
#define HW    196
#define NROI  512
#define M1    4608          // NROI*9
#define KFEAT 4608          // CI*9
#define NPART 8             // split-K parts for gemm2

// ---------------- scratch (static device memory) ----------------
__device__ __nv_bfloat16 d_roisH[(size_t)M1 * CIN];
__device__ __nv_bfloat16 d_roisL[(size_t)M1 * CIN];
__device__ __nv_bfloat16 d_wH[(size_t)CI * CIN];
__device__ __nv_bfloat16 d_wL[(size_t)CI * CIN];
__device__ __nv_bfloat16 d_rwH[(size_t)CI * KFEAT];   // re_w transposed+permuted [n][bin*512+o]
__device__ __nv_bfloat16 d_rwL[(size_t)CI * KFEAT];
__device__ __nv_bfloat16 d_featsH[(size_t)NROI * KFEAT]; // [roi][bin*512+o]
__device__ __nv_bfloat16 d_featsL[(size_t)NROI * KFEAT];
__device__ float d_regpart[(size_t)NPART * NROI * CI];
__device__ float d_objf[32 * CI];
__device__ float d_pooled[16 * CI];
__device__ float d_h1[32 * CI];
__device__ float d_g1[16 * CI];
__device__ int2  d_tap[NROI * 9 * 16];   // {byte-offset into 197-float row, weight bits}

// ---------------- PTX helpers ----------------
__device__ __forceinline__ uint32_t sm_u32(const void* p) {
    return (uint32_t)__cvta_generic_to_shared(p);
}
__device__ __forceinline__ void cpa16(uint32_t dst, const void* src) {
    asm volatile("cp.async.cg.shared.global [%0], [%1], 16;\n" :: "r"(dst), "l"(src));
}
__device__ __forceinline__ void cpa_commit() {
    asm volatile("cp.async.commit_group;\n" ::: "memory");
}
__device__ __forceinline__ void cpa_wait0() {
    asm volatile("cp.async.wait_group 0;\n" ::: "memory");
}
__device__ __forceinline__ void cpa_wait1() {
    asm volatile("cp.async.wait_group 1;\n" ::: "memory");
}
__device__ __forceinline__ void ldsm4(uint32_t* r, uint32_t addr) {
    asm volatile("ldmatrix.sync.aligned.m8n8.x4.shared.b16 {%0,%1,%2,%3}, [%4];"
                 : "=r"(r[0]), "=r"(r[1]), "=r"(r[2]), "=r"(r[3]) : "r"(addr));
}
__device__ __forceinline__ void mma16816(float* c, const uint32_t* a, uint32_t b0, uint32_t b1) {
    asm volatile("mma.sync.aligned.m16n8k16.row.col.f32.bf16.bf16.f32 "
                 "{%0,%1,%2,%3},{%4,%5,%6,%7},{%8,%9},{%0,%1,%2,%3};"
                 : "+f"(c[0]), "+f"(c[1]), "+f"(c[2]), "+f"(c[3])
                 : "r"(a[0]), "r"(a[1]), "r"(a[2]), "r"(a[3]), "r"(b0), "r"(b1));
}

// ============================================================
// K1: ROI-align tap table (byte offsets, weights folded w/ 0.25 mean)
// ============================================================
__global__ void build_table(const float* __restrict__ boxes) {
    int roi = blockIdx.x * blockDim.x + threadIdx.x;
    if (roi >= NROI) return;
    float cx = boxes[roi * 4 + 0], cy = boxes[roi * 4 + 1];
    float w  = boxes[roi * 4 + 2], h  = boxes[roi * 4 + 3];
    const float s = 14.0f / 224.0f;
    float x1 = (cx - 0.5f * w) * 224.0f * s;
    float y1 = (cy - 0.5f * h) * 224.0f * s;
    float x2 = (cx + 0.5f * w) * 224.0f * s;
    float y2 = (cy + 0.5f * h) * 224.0f * s;
    float rw = fmaxf(x2 - x1, 1.0f), rh = fmaxf(y2 - y1, 1.0f);
    float bw = rw / 3.0f, bh = rh / 3.0f;

    float ys[6], xs[6];
#pragma unroll
    for (int p = 0; p < 3; ++p)
#pragma unroll
        for (int i = 0; i < 2; ++i) {
            ys[p * 2 + i] = y1 + p * bh + (i + 0.5f) * bh * 0.5f;
            xs[p * 2 + i] = x1 + p * bw + (i + 0.5f) * bw * 0.5f;
        }

#pragma unroll
    for (int ph = 0; ph < 3; ++ph)
#pragma unroll
        for (int pw = 0; pw < 3; ++pw) {
            int bin = ph * 3 + pw;
#pragma unroll
            for (int iy = 0; iy < 2; ++iy)
#pragma unroll
                for (int ix = 0; ix < 2; ++ix) {
                    int smp = iy * 2 + ix;
                    float yy = ys[ph * 2 + iy];
                    float xx = xs[pw * 2 + ix];
                    bool valid = (yy > -1.0f) && (yy < 14.0f) && (xx > -1.0f) && (xx < 14.0f);
                    float y = fminf(fmaxf(yy, 0.0f), 13.0f);
                    float x = fminf(fmaxf(xx, 0.0f), 13.0f);
                    int y0 = (int)floorf(y), x0 = (int)floorf(x);
                    int y1i = min(y0 + 1, 13), x1i = min(x0 + 1, 13);
                    float ly = y - (float)y0, lx = x - (float)x0;
                    float hy = 1.0f - ly, hx = 1.0f - lx;
                    float q = valid ? 0.25f : 0.0f;
                    int base = (roi * 9 + bin) * 16 + smp * 4;
                    d_tap[base + 0] = make_int2((y0 * HF + x0) * 4,   __float_as_int(hy * hx * q));
                    d_tap[base + 1] = make_int2((y0 * HF + x1i) * 4,  __float_as_int(hy * lx * q));
                    d_tap[base + 2] = make_int2((y1i * HF + x0) * 4,  __float_as_int(ly * hx * q));
                    d_tap[base + 3] = make_int2((y1i * HF + x1i) * 4, __float_as_int(ly * lx * q));
                }
        }
}

// ============================================================
// K2: pooling in 2048-ch space -> bf16 hi/lo
// block = (bt, 32-channel chunk); 288 threads; ~30KB STATIC smem
// lane = channel, warp covers e = wid + 9*j (36 e's over 9 warps)
// ============================================================
__global__ __launch_bounds__(288) void pool_kernel(const float* __restrict__ x) {
    __shared__ float pl[32][197];     // 197: conflict-free odd stride
    __shared__ int2  taps[576];
    int bt = blockIdx.y;
    int c0 = blockIdx.x * 32;
    int tid = threadIdx.x, lane = tid & 31, wid = tid >> 5;

    // x layout (B, C, T, H, W); plane = 196 contiguous floats, 16B-aligned
    size_t base = ((size_t)(bt >> 3) * CIN + c0) * (size_t)(T_ * HW) + (size_t)(bt & 7) * HW;
    for (int c = wid; c < 32; c += 9) {
        const float4* src = (const float4*)(x + base + (size_t)c * (T_ * HW));
        for (int p = lane; p < 49; p += 32) {
            float4 v = src[p];
            pl[c][p * 4 + 0] = v.x; pl[c][p * 4 + 1] = v.y;
            pl[c][p * 4 + 2] = v.z; pl[c][p * 4 + 3] = v.w;
        }
    }
    for (int i = tid; i < 576; i += 288) taps[i] = d_tap[bt * 576 + i];
    __syncthreads();

    const char* bp = (const char*)&pl[lane][0];
#pragma unroll
    for (int j = 0; j < 4; ++j) {
        int e = wid + 9 * j;            // nb*9+bin
        const int2* tp = &taps[e * 16];
        float a = 0.0f;
#pragma unroll
        for (int t = 0; t < 16; ++t) {
            int2 pw = tp[t];            // broadcast LDS.64
            a += __int_as_float(pw.y) * *(const float*)(bp + pw.x);
        }
        size_t off = (size_t)(bt * 36 + e) * CIN + c0 + lane;
        __nv_bfloat16 hb = __float2bfloat16_rn(a);
        d_roisH[off] = hb;
        d_roisL[off] = __float2bfloat16_rn(a - __bfloat162float(hb));
    }
}

// ============================================================
// K3a: convert conv5_w -> bf16 hi/lo
// ============================================================
__global__ void convw_kernel(const float* __restrict__ w) {
    int i = blockIdx.x * 256 + threadIdx.x;
    float v = w[i];
    __nv_bfloat16 hb = __float2bfloat16_rn(v);
    d_wH[i] = hb;
    d_wL[i] = __float2bfloat16_rn(v - __bfloat162float(hb));
}

// ============================================================
// K3b: convert re_w -> transposed+permuted bf16 hi/lo
// ============================================================
__global__ __launch_bounds__(256) void convrw_kernel(const float* __restrict__ w) {
    __shared__ float t[32][33];
    int o0 = blockIdx.x * 32, n0 = blockIdx.y * 32, bin = blockIdx.z;
    int tx = threadIdx.x & 31, ty = threadIdx.x >> 5;
    for (int r = ty; r < 32; r += 8)
        t[r][tx] = w[((size_t)((o0 + r) * 9 + bin)) * 512 + n0 + tx];
    __syncthreads();
    for (int r = ty; r < 32; r += 8) {
        float v = t[tx][r];
        __nv_bfloat16 hb = __float2bfloat16_rn(v);
        __nv_bfloat16 lb = __float2bfloat16_rn(v - __bfloat162float(hb));
        size_t off = (size_t)(n0 + r) * KFEAT + bin * 512 + o0 + tx;
        d_rwH[off] = hb;
        d_rwL[off] = lb;
    }
}

// ============================================================
// GEMM core: 128x128 tile, bf16 split mma.sync (3 passes), 3-stage cp.async
// ============================================================
#define KT    32
#define SROW  40
#define TILE_E (128 * SROW)
#define STAGE_E (4 * TILE_E)
#define GSMEM_BYTES (3 * STAGE_E * 2)

__device__ __forceinline__ void gemm_core(
    const __nv_bfloat16* __restrict__ gAh, const __nv_bfloat16* __restrict__ gAl, int lda,
    const __nv_bfloat16* __restrict__ gBh, const __nv_bfloat16* __restrict__ gBl, int ldb,
    int bm, int bn, int kbase, int niter,
    __nv_bfloat16* sm, float (&acc)[4][4][4])
{
    int tid = threadIdx.x, lane = tid & 31, wid = tid >> 5;
    int wm = wid >> 2, wn = wid & 3;     // warp tile 64x32

    auto ldg = [&](int t) {
        int s = t % 3;
        int k0 = kbase + t * KT;
        __nv_bfloat16* base = sm + s * STAGE_E;
#pragma unroll
        for (int j = 0; j < 2; ++j) {
            int id = (tid << 1) + j;
            int row = id >> 2, c = id & 3;
            __nv_bfloat16* pd = base + row * SROW + c * 8;
            cpa16(sm_u32(pd),               gAh + (size_t)(bm + row) * lda + k0 + c * 8);
            cpa16(sm_u32(pd + TILE_E),      gAl + (size_t)(bm + row) * lda + k0 + c * 8);
            cpa16(sm_u32(pd + 2 * TILE_E),  gBh + (size_t)(bn + row) * ldb + k0 + c * 8);
            cpa16(sm_u32(pd + 3 * TILE_E),  gBl + (size_t)(bn + row) * ldb + k0 + c * 8);
        }
    };

    int ar  = wm * 64 + (lane & 15);
    int ac8 = (lane >> 4) * 8;
    int br  = wn * 32 + (lane & 7) + ((lane >> 4) << 3);
    int bc8 = ((lane >> 3) & 1) * 8;

    ldg(0); cpa_commit();
    if (niter > 1) { ldg(1); cpa_commit(); }

#pragma unroll 1
    for (int t = 0; t < niter; ++t) {
        if (t + 1 < niter) cpa_wait1(); else cpa_wait0();
        __syncthreads();
        if (t + 2 < niter) { ldg(t + 2); cpa_commit(); }

        __nv_bfloat16* base = sm + (t % 3) * STAGE_E;
        const __nv_bfloat16* pAh = base;
        const __nv_bfloat16* pAl = base + TILE_E;
        const __nv_bfloat16* pBh = base + 2 * TILE_E;
        const __nv_bfloat16* pBl = base + 3 * TILE_E;

#pragma unroll
        for (int ks = 0; ks < 2; ++ks) {
            uint32_t ah[4][4], al[4][4], bh[2][4], bl[2][4];
#pragma unroll
            for (int mt = 0; mt < 4; ++mt) {
                ldsm4(ah[mt], sm_u32(pAh + (ar + mt * 16) * SROW + ks * 16 + ac8));
                ldsm4(al[mt], sm_u32(pAl + (ar + mt * 16) * SROW + ks * 16 + ac8));
            }
#pragma unroll
            for (int bt2 = 0; bt2 < 2; ++bt2) {
                ldsm4(bh[bt2], sm_u32(pBh + (br + bt2 * 16) * SROW + ks * 16 + bc8));
                ldsm4(bl[bt2], sm_u32(pBl + (br + bt2 * 16) * SROW + ks * 16 + bc8));
            }
#pragma unroll
            for (int mt = 0; mt < 4; ++mt)
#pragma unroll
                for (int nt = 0; nt < 4; ++nt) {
                    uint32_t b0h = bh[nt >> 1][(nt & 1) * 2], b1h = bh[nt >> 1][(nt & 1) * 2 + 1];
                    uint32_t b0l = bl[nt >> 1][(nt & 1) * 2], b1l = bl[nt >> 1][(nt & 1) * 2 + 1];
                    mma16816(acc[mt][nt], ah[mt], b0h, b1h);
                    mma16816(acc[mt][nt], al[mt], b0h, b1h);
                    mma16816(acc[mt][nt], ah[mt], b0l, b1l);
                }
        }
    }
}

// ============================================================
// K4: GEMM1: feats = rois2048[4608,2048] x conv5_w[512,2048]^T
// ============================================================
__global__ __launch_bounds__(256) void gemm1k() {
    extern __shared__ __nv_bfloat16 sm[];
    int bm = blockIdx.y * 128, bn = blockIdx.x * 128;
    float acc[4][4][4];
#pragma unroll
    for (int a = 0; a < 4; ++a)
#pragma unroll
        for (int b = 0; b < 4; ++b)
#pragma unroll
            for (int c = 0; c < 4; ++c) acc[a][b][c] = 0.0f;

    gemm_core(d_roisH, d_roisL, CIN, d_wH, d_wL, CIN, bm, bn, 0, CIN / KT, sm, acc);

    int lane = threadIdx.x & 31, wid = threadIdx.x >> 5;
    int wm = wid >> 2, wn = wid & 3;
    int mrow = wm * 64 + (lane >> 2);
    int ncol = wn * 32 + ((lane & 3) << 1);
#pragma unroll
    for (int mt = 0; mt < 4; ++mt)
#pragma unroll
        for (int nt = 0; nt < 4; ++nt) {
            float* c = acc[mt][nt];
            int n = bn + ncol + nt * 8;
#pragma unroll
            for (int half = 0; half < 2; ++half) {
                int m = bm + mrow + mt * 16 + half * 8;
                int roi = m / 9, bin = m - roi * 9;
                size_t off = (size_t)roi * KFEAT + bin * 512 + n;
                float v0 = c[half * 2 + 0], v1 = c[half * 2 + 1];
                __nv_bfloat16 h0 = __float2bfloat16_rn(v0);
                __nv_bfloat16 h1 = __float2bfloat16_rn(v1);
                __nv_bfloat162 hp; hp.x = h0; hp.y = h1;
                __nv_bfloat162 lp;
                lp.x = __float2bfloat16_rn(v0 - __bfloat162float(h0));
                lp.y = __float2bfloat16_rn(v1 - __bfloat162float(h1));
                *(__nv_bfloat162*)&d_featsH[off] = hp;
                *(__nv_bfloat162*)&d_featsL[off] = lp;
            }
        }
}

// ============================================================
// K5: GEMM2 (split-K=8): regpart = feats[512,4608] x rw[512,4608]^T
// ============================================================
__global__ __launch_bounds__(256) void gemm2k() {
    extern __shared__ __nv_bfloat16 sm[];
    int bm = blockIdx.y * 128, bn = blockIdx.x * 128;
    int part = blockIdx.z;
    float acc[4][4][4];
#pragma unroll
    for (int a = 0; a < 4; ++a)
#pragma unroll
        for (int b = 0; b < 4; ++b)
#pragma unroll
            for (int c = 0; c < 4; ++c) acc[a][b][c] = 0.0f;

    gemm_core(d_featsH, d_featsL, KFEAT, d_rwH, d_rwL, KFEAT,
              bm, bn, part * (KFEAT / NPART), (KFEAT / NPART) / KT, sm, acc);

    int lane = threadIdx.x & 31, wid = threadIdx.x >> 5;
    int wm = wid >> 2, wn = wid & 3;
    int mrow = wm * 64 + (lane >> 2);
    int ncol = wn * 32 + ((lane & 3) << 1);
    float* C = d_regpart + (size_t)part * NROI * CI;
#pragma unroll
    for (int mt = 0; mt < 4; ++mt)
#pragma unroll
        for (int nt = 0; nt < 4; ++nt) {
            float* c = acc[mt][nt];
            int n = bn + ncol + nt * 8;
#pragma unroll
            for (int half = 0; half < 2; ++half) {
                int m = bm + mrow + mt * 16 + half * 8;
                *(float2*)&C[(size_t)m * CI + n] = make_float2(c[half * 2], c[half * 2 + 1]);
            }
        }
}

// ============================================================
// K6: sum split-K parts + bias + relu + mean over T + selections
// ============================================================
__global__ void reduce_kernel(const float* __restrict__ re_b,
                              const int* __restrict__ cat,
                              float* __restrict__ out_labels) {
    int b = blockIdx.x, j = threadIdx.x;
    float bias = re_b[j];
    float pool = 0.0f;
#pragma unroll
    for (int nb = 0; nb < 4; ++nb) {
        float s = 0.0f;
#pragma unroll
        for (int t = 0; t < 8; ++t) {
            int r = (b * 8 + t) * 4 + nb;
            float v = bias;
#pragma unroll
            for (int p = 0; p < NPART; ++p) v += d_regpart[(size_t)p * NROI * CI + (size_t)r * CI + j];
            s += fmaxf(v, 0.0f);
        }
        s *= 0.125f;
        if (nb >= 2) d_objf[(b * 2 + nb - 2) * CI + j] = s;   // argsort identity: cats never 0
        pool += s;
    }
    d_pooled[b * CI + j] = pool * 0.25f;
    if (j < 2) out_labels[b * 2 + j] = (float)cat[b * 4 + 2 + j];
}

// ============================================================
// K7: small dense head
// ============================================================
__global__ __launch_bounds__(256) void small_mm(const float* __restrict__ A,
                                                const float* __restrict__ Bm,
                                                const float* __restrict__ bias,
                                                float* __restrict__ C, int N) {
    __shared__ float As[512];
    __shared__ float red[256];
    int m = blockIdx.x, j0 = blockIdx.y * 64;
    int tid = threadIdx.x, jl = tid & 63, ks = tid >> 6;
    for (int k = tid; k < 512; k += 256) As[k] = A[m * 512 + k];
    __syncthreads();
    int j = j0 + jl;
    float acc = 0.0f;
    if (j < N) {
        int k0 = ks * 128;
#pragma unroll 8
        for (int k = k0; k < k0 + 128; ++k) acc += As[k] * Bm[k * N + j];
    }
    red[tid] = acc;
    __syncthreads();
    if (tid < 64 && j < N)
        C[m * N + j] = red[tid] + red[tid + 64] + red[tid + 128] + red[tid + 192] + bias[j];
}

// ============================================================
extern "C" void kernel_launch(void* const* d_in, const int* in_sizes, int n_in,
                              void* d_out, int out_size) {
    const float* x       = (const float*)d_in[0];
    const float* boxes   = (const float*)d_in[1];
    const int*   cat     = (const int*)d_in[2];
    const float* conv5_w = (const float*)d_in[3];
    const float* re_w    = (const float*)d_in[4];
    const float* re_b    = (const float*)d_in[5];
    const float* oc1_w   = (const float*)d_in[6];
    const float* oc1_b   = (const float*)d_in[7];
    const float* oc2_w   = (const float*)d_in[8];
    const float* oc2_b   = (const float*)d_in[9];
    const float* pr1_w   = (const float*)d_in[10];
    const float* pr1_b   = (const float*)d_in[11];
    const float* pr2_w   = (const float*)d_in[12];
    const float* pr2_b   = (const float*)d_in[13];

    float* out     = (float*)d_out;
    float* cls_out = out;                       // 16*174
    float* obj_cls = out + 16 * 174;            // 32*301
    float* labels  = out + 16 * 174 + 32 * 301; // 32

    float *p_objf, *p_pooled, *p_h1, *p_g1;
    cudaGetSymbolAddress((void**)&p_objf,   d_objf);
    cudaGetSymbolAddress((void**)&p_pooled, d_pooled);
    cudaGetSymbolAddress((void**)&p_h1,     d_h1);
    cudaGetSymbolAddress((void**)&p_g1,     d_g1);

    cudaFuncSetAttribute(gemm1k, cudaFuncAttributeMaxDynamicSharedMemorySize, GSMEM_BYTES);
    cudaFuncSetAttribute(gemm2k, cudaFuncAttributeMaxDynamicSharedMemorySize, GSMEM_BYTES);

    build_table<<<2, 256>>>(boxes);
    convw_kernel<<<(CI * CIN) / 256, 256>>>(conv5_w);
    convrw_kernel<<<dim3(16, 16, 9), 256>>>(re_w);
    pool_kernel<<<dim3(CIN / 32, B_ * T_), 288>>>(x);
    gemm1k<<<dim3(CI / 128, M1 / 128), 256, GSMEM_BYTES>>>();
    gemm2k<<<dim3(CI / 128, NROI / 128, NPART), 256, GSMEM_BYTES>>>();
    reduce_kernel<<<16, 512>>>(re_b, cat, labels);
    small_mm<<<dim3(32, 8), 256>>>(p_objf, oc1_w, oc1_b, p_h1, 512);
    small_mm<<<dim3(32, 5), 256>>>(p_h1, oc2_w, oc2_b, obj_cls, 301);
    small_mm<<<dim3(16, 8), 256>>>(p_pooled, pr1_w, pr1_b, p_g1, 512);
    small_mm<<<dim3(16, 3), 256>>>(p_g1, pr2_w, pr2_b, cls_out, 174);
}

// round 6
// speedup vs baseline: 1.8093x; 1.0553x over previous
#include <cuda_runtime.h>
#include <cuda_bf16.h>
#include <cstdint>

// ---------------- problem constants ----------------
#define B_    16
#define T_    8
#define CIN   2048
#define CI    512
#define HF    14
#define HW    196
#define NROI  512
#define M1    4608          // NROI*9
#define KFEAT 4608          // CI*9
#define NPART 8             // split-K parts for gemm2

// ---------------- scratch (static device memory) ----------------
__device__ __nv_bfloat16 d_roisH[(size_t)M1 * CIN];
__device__ __nv_bfloat16 d_roisL[(size_t)M1 * CIN];
__device__ __nv_bfloat16 d_wH[(size_t)CI * CIN];
__device__ __nv_bfloat16 d_wL[(size_t)CI * CIN];
__device__ __nv_bfloat16 d_rwH[(size_t)CI * KFEAT];   // re_w transposed+permuted [n][bin*512+o]
__device__ __nv_bfloat16 d_rwL[(size_t)CI * KFEAT];
__device__ __nv_bfloat16 d_featsH[(size_t)NROI * KFEAT]; // [roi][bin*512+o]
__device__ __nv_bfloat16 d_featsL[(size_t)NROI * KFEAT];
__device__ float d_regpart[(size_t)NPART * NROI * CI];
__device__ float d_snb[64 * CI];
__device__ float d_objf[32 * CI];
__device__ float d_pooled[16 * CI];
__device__ float d_h1[32 * CI];
__device__ float d_g1[16 * CI];
__device__ int2  d_tap[NROI * 9 * 16];   // {byte-offset into 197-float row, weight bits}

// ---------------- PTX helpers ----------------
__device__ __forceinline__ uint32_t sm_u32(const void* p) {
    return (uint32_t)__cvta_generic_to_shared(p);
}
__device__ __forceinline__ void cpa16(uint32_t dst, const void* src) {
    asm volatile("cp.async.cg.shared.global [%0], [%1], 16;\n" :: "r"(dst), "l"(src));
}
__device__ __forceinline__ void cpa_commit() {
    asm volatile("cp.async.commit_group;\n" ::: "memory");
}
__device__ __forceinline__ void cpa_wait0() {
    asm volatile("cp.async.wait_group 0;\n" ::: "memory");
}
__device__ __forceinline__ void cpa_wait1() {
    asm volatile("cp.async.wait_group 1;\n" ::: "memory");
}
__device__ __forceinline__ void ldsm4(uint32_t* r, uint32_t addr) {
    asm volatile("ldmatrix.sync.aligned.m8n8.x4.shared.b16 {%0,%1,%2,%3}, [%4];"
                 : "=r"(r[0]), "=r"(r[1]), "=r"(r[2]), "=r"(r[3]) : "r"(addr));
}
__device__ __forceinline__ void mma16816(float* c, const uint32_t* a, uint32_t b0, uint32_t b1) {
    asm volatile("mma.sync.aligned.m16n8k16.row.col.f32.bf16.bf16.f32 "
                 "{%0,%1,%2,%3},{%4,%5,%6,%7},{%8,%9},{%0,%1,%2,%3};"
                 : "+f"(c[0]), "+f"(c[1]), "+f"(c[2]), "+f"(c[3])
                 : "r"(a[0]), "r"(a[1]), "r"(a[2]), "r"(a[3]), "r"(b0), "r"(b1));
}

// ============================================================
// K1: ROI-align tap table (byte offsets, weights folded w/ 0.25 mean)
// ============================================================
__global__ void build_table(const float* __restrict__ boxes) {
    int roi = blockIdx.x * blockDim.x + threadIdx.x;
    if (roi >= NROI) return;
    float cx = boxes[roi * 4 + 0], cy = boxes[roi * 4 + 1];
    float w  = boxes[roi * 4 + 2], h  = boxes[roi * 4 + 3];
    const float s = 14.0f / 224.0f;
    float x1 = (cx - 0.5f * w) * 224.0f * s;
    float y1 = (cy - 0.5f * h) * 224.0f * s;
    float x2 = (cx + 0.5f * w) * 224.0f * s;
    float y2 = (cy + 0.5f * h) * 224.0f * s;
    float rw = fmaxf(x2 - x1, 1.0f), rh = fmaxf(y2 - y1, 1.0f);
    float bw = rw / 3.0f, bh = rh / 3.0f;

    float ys[6], xs[6];
#pragma unroll
    for (int p = 0; p < 3; ++p)
#pragma unroll
        for (int i = 0; i < 2; ++i) {
            ys[p * 2 + i] = y1 + p * bh + (i + 0.5f) * bh * 0.5f;
            xs[p * 2 + i] = x1 + p * bw + (i + 0.5f) * bw * 0.5f;
        }

#pragma unroll
    for (int ph = 0; ph < 3; ++ph)
#pragma unroll
        for (int pw = 0; pw < 3; ++pw) {
            int bin = ph * 3 + pw;
#pragma unroll
            for (int iy = 0; iy < 2; ++iy)
#pragma unroll
                for (int ix = 0; ix < 2; ++ix) {
                    int smp = iy * 2 + ix;
                    float yy = ys[ph * 2 + iy];
                    float xx = xs[pw * 2 + ix];
                    bool valid = (yy > -1.0f) && (yy < 14.0f) && (xx > -1.0f) && (xx < 14.0f);
                    float y = fminf(fmaxf(yy, 0.0f), 13.0f);
                    float x = fminf(fmaxf(xx, 0.0f), 13.0f);
                    int y0 = (int)floorf(y), x0 = (int)floorf(x);
                    int y1i = min(y0 + 1, 13), x1i = min(x0 + 1, 13);
                    float ly = y - (float)y0, lx = x - (float)x0;
                    float hy = 1.0f - ly, hx = 1.0f - lx;
                    float q = valid ? 0.25f : 0.0f;
                    int base = (roi * 9 + bin) * 16 + smp * 4;
                    d_tap[base + 0] = make_int2((y0 * HF + x0) * 4,   __float_as_int(hy * hx * q));
                    d_tap[base + 1] = make_int2((y0 * HF + x1i) * 4,  __float_as_int(hy * lx * q));
                    d_tap[base + 2] = make_int2((y1i * HF + x0) * 4,  __float_as_int(ly * hx * q));
                    d_tap[base + 3] = make_int2((y1i * HF + x1i) * 4, __float_as_int(ly * lx * q));
                }
        }
}

// ============================================================
// K2: pooling in 2048-ch space -> bf16 hi/lo (R4 proven shape)
// ============================================================
__global__ __launch_bounds__(288) void pool_kernel(const float* __restrict__ x) {
    __shared__ float pl[32][197];
    __shared__ int2  taps[576];
    int bt = blockIdx.y;
    int c0 = blockIdx.x * 32;
    int tid = threadIdx.x, lane = tid & 31, wid = tid >> 5;

    size_t base = ((size_t)(bt >> 3) * CIN + c0) * (size_t)(T_ * HW) + (size_t)(bt & 7) * HW;
    for (int c = wid; c < 32; c += 9) {
        const float4* src = (const float4*)(x + base + (size_t)c * (T_ * HW));
        for (int p = lane; p < 49; p += 32) {
            float4 v = src[p];
            pl[c][p * 4 + 0] = v.x; pl[c][p * 4 + 1] = v.y;
            pl[c][p * 4 + 2] = v.z; pl[c][p * 4 + 3] = v.w;
        }
    }
    for (int i = tid; i < 576; i += 288) taps[i] = d_tap[bt * 576 + i];
    __syncthreads();

    const char* bp = (const char*)&pl[lane][0];
#pragma unroll
    for (int j = 0; j < 4; ++j) {
        int e = wid + 9 * j;
        const int2* tp = &taps[e * 16];
        float a = 0.0f;
#pragma unroll
        for (int t = 0; t < 16; ++t) {
            int2 pw = tp[t];
            a += __int_as_float(pw.y) * *(const float*)(bp + pw.x);
        }
        size_t off = (size_t)(bt * 36 + e) * CIN + c0 + lane;
        __nv_bfloat16 hb = __float2bfloat16_rn(a);
        d_roisH[off] = hb;
        d_roisL[off] = __float2bfloat16_rn(a - __bfloat162float(hb));
    }
}

// ============================================================
// K3a: convert conv5_w -> bf16 hi/lo
// ============================================================
__global__ void convw_kernel(const float* __restrict__ w) {
    int i = blockIdx.x * 256 + threadIdx.x;
    float v = w[i];
    __nv_bfloat16 hb = __float2bfloat16_rn(v);
    d_wH[i] = hb;
    d_wL[i] = __float2bfloat16_rn(v - __bfloat162float(hb));
}

// ============================================================
// K3b: convert re_w -> transposed+permuted bf16 hi/lo
// ============================================================
__global__ __launch_bounds__(256) void convrw_kernel(const float* __restrict__ w) {
    __shared__ float t[32][33];
    int o0 = blockIdx.x * 32, n0 = blockIdx.y * 32, bin = blockIdx.z;
    int tx = threadIdx.x & 31, ty = threadIdx.x >> 5;
    for (int r = ty; r < 32; r += 8)
        t[r][tx] = w[((size_t)((o0 + r) * 9 + bin)) * 512 + n0 + tx];
    __syncthreads();
    for (int r = ty; r < 32; r += 8) {
        float v = t[tx][r];
        __nv_bfloat16 hb = __float2bfloat16_rn(v);
        __nv_bfloat16 lb = __float2bfloat16_rn(v - __bfloat162float(hb));
        size_t off = (size_t)(n0 + r) * KFEAT + bin * 512 + o0 + tx;
        d_rwH[off] = hb;
        d_rwL[off] = lb;
    }
}

// ============================================================
// GEMM core: 128x128 tile, bf16 split mma.sync (3 passes), 3-stage cp.async
// ============================================================
#define KT    32
#define SROW  40
#define TILE_E (128 * SROW)
#define STAGE_E (4 * TILE_E)
#define GSMEM_BYTES (3 * STAGE_E * 2)

__device__ __forceinline__ void gemm_core(
    const __nv_bfloat16* __restrict__ gAh, const __nv_bfloat16* __restrict__ gAl, int lda,
    const __nv_bfloat16* __restrict__ gBh, const __nv_bfloat16* __restrict__ gBl, int ldb,
    int bm, int bn, int kbase, int niter,
    __nv_bfloat16* sm, float (&acc)[4][4][4])
{
    int tid = threadIdx.x, lane = tid & 31, wid = tid >> 5;
    int wm = wid >> 2, wn = wid & 3;     // warp tile 64x32

    auto ldg = [&](int t) {
        int s = t % 3;
        int k0 = kbase + t * KT;
        __nv_bfloat16* base = sm + s * STAGE_E;
#pragma unroll
        for (int j = 0; j < 2; ++j) {
            int id = (tid << 1) + j;
            int row = id >> 2, c = id & 3;
            __nv_bfloat16* pd = base + row * SROW + c * 8;
            cpa16(sm_u32(pd),               gAh + (size_t)(bm + row) * lda + k0 + c * 8);
            cpa16(sm_u32(pd + TILE_E),      gAl + (size_t)(bm + row) * lda + k0 + c * 8);
            cpa16(sm_u32(pd + 2 * TILE_E),  gBh + (size_t)(bn + row) * ldb + k0 + c * 8);
            cpa16(sm_u32(pd + 3 * TILE_E),  gBl + (size_t)(bn + row) * ldb + k0 + c * 8);
        }
    };

    int ar  = wm * 64 + (lane & 15);
    int ac8 = (lane >> 4) * 8;
    int br  = wn * 32 + (lane & 7) + ((lane >> 4) << 3);
    int bc8 = ((lane >> 3) & 1) * 8;

    ldg(0); cpa_commit();
    if (niter > 1) { ldg(1); cpa_commit(); }

#pragma unroll 1
    for (int t = 0; t < niter; ++t) {
        if (t + 1 < niter) cpa_wait1(); else cpa_wait0();
        __syncthreads();
        if (t + 2 < niter) { ldg(t + 2); cpa_commit(); }

        __nv_bfloat16* base = sm + (t % 3) * STAGE_E;
        const __nv_bfloat16* pAh = base;
        const __nv_bfloat16* pAl = base + TILE_E;
        const __nv_bfloat16* pBh = base + 2 * TILE_E;
        const __nv_bfloat16* pBl = base + 3 * TILE_E;

#pragma unroll
        for (int ks = 0; ks < 2; ++ks) {
            uint32_t ah[4][4], al[4][4], bh[2][4], bl[2][4];
#pragma unroll
            for (int mt = 0; mt < 4; ++mt) {
                ldsm4(ah[mt], sm_u32(pAh + (ar + mt * 16) * SROW + ks * 16 + ac8));
                ldsm4(al[mt], sm_u32(pAl + (ar + mt * 16) * SROW + ks * 16 + ac8));
            }
#pragma unroll
            for (int bt2 = 0; bt2 < 2; ++bt2) {
                ldsm4(bh[bt2], sm_u32(pBh + (br + bt2 * 16) * SROW + ks * 16 + bc8));
                ldsm4(bl[bt2], sm_u32(pBl + (br + bt2 * 16) * SROW + ks * 16 + bc8));
            }
#pragma unroll
            for (int mt = 0; mt < 4; ++mt)
#pragma unroll
                for (int nt = 0; nt < 4; ++nt) {
                    uint32_t b0h = bh[nt >> 1][(nt & 1) * 2], b1h = bh[nt >> 1][(nt & 1) * 2 + 1];
                    uint32_t b0l = bl[nt >> 1][(nt & 1) * 2], b1l = bl[nt >> 1][(nt & 1) * 2 + 1];
                    mma16816(acc[mt][nt], ah[mt], b0h, b1h);
                    mma16816(acc[mt][nt], al[mt], b0h, b1h);
                    mma16816(acc[mt][nt], ah[mt], b0l, b1l);
                }
        }
    }
}

// ============================================================
// K4: GEMM1: feats = rois2048[4608,2048] x conv5_w[512,2048]^T
// ============================================================
__global__ __launch_bounds__(256) void gemm1k() {
    extern __shared__ __nv_bfloat16 sm[];
    int bm = blockIdx.y * 128, bn = blockIdx.x * 128;
    float acc[4][4][4];
#pragma unroll
    for (int a = 0; a < 4; ++a)
#pragma unroll
        for (int b = 0; b < 4; ++b)
#pragma unroll
            for (int c = 0; c < 4; ++c) acc[a][b][c] = 0.0f;

    gemm_core(d_roisH, d_roisL, CIN, d_wH, d_wL, CIN, bm, bn, 0, CIN / KT, sm, acc);

    int lane = threadIdx.x & 31, wid = threadIdx.x >> 5;
    int wm = wid >> 2, wn = wid & 3;
    int mrow = wm * 64 + (lane >> 2);
    int ncol = wn * 32 + ((lane & 3) << 1);
#pragma unroll
    for (int mt = 0; mt < 4; ++mt)
#pragma unroll
        for (int nt = 0; nt < 4; ++nt) {
            float* c = acc[mt][nt];
            int n = bn + ncol + nt * 8;
#pragma unroll
            for (int half = 0; half < 2; ++half) {
                int m = bm + mrow + mt * 16 + half * 8;
                int roi = m / 9, bin = m - roi * 9;
                size_t off = (size_t)roi * KFEAT + bin * 512 + n;
                float v0 = c[half * 2 + 0], v1 = c[half * 2 + 1];
                __nv_bfloat16 h0 = __float2bfloat16_rn(v0);
                __nv_bfloat16 h1 = __float2bfloat16_rn(v1);
                __nv_bfloat162 hp; hp.x = h0; hp.y = h1;
                __nv_bfloat162 lp;
                lp.x = __float2bfloat16_rn(v0 - __bfloat162float(h0));
                lp.y = __float2bfloat16_rn(v1 - __bfloat162float(h1));
                *(__nv_bfloat162*)&d_featsH[off] = hp;
                *(__nv_bfloat162*)&d_featsL[off] = lp;
            }
        }
}

// ============================================================
// K5: GEMM2 (split-K=8): regpart = feats[512,4608] x rw[512,4608]^T
// ============================================================
__global__ __launch_bounds__(256) void gemm2k() {
    extern __shared__ __nv_bfloat16 sm[];
    int bm = blockIdx.y * 128, bn = blockIdx.x * 128;
    int part = blockIdx.z;
    float acc[4][4][4];
#pragma unroll
    for (int a = 0; a < 4; ++a)
#pragma unroll
        for (int b = 0; b < 4; ++b)
#pragma unroll
            for (int c = 0; c < 4; ++c) acc[a][b][c] = 0.0f;

    gemm_core(d_featsH, d_featsL, KFEAT, d_rwH, d_rwL, KFEAT,
              bm, bn, part * (KFEAT / NPART), (KFEAT / NPART) / KT, sm, acc);

    int lane = threadIdx.x & 31, wid = threadIdx.x >> 5;
    int wm = wid >> 2, wn = wid & 3;
    int mrow = wm * 64 + (lane >> 2);
    int ncol = wn * 32 + ((lane & 3) << 1);
    float* C = d_regpart + (size_t)part * NROI * CI;
#pragma unroll
    for (int mt = 0; mt < 4; ++mt)
#pragma unroll
        for (int nt = 0; nt < 4; ++nt) {
            float* c = acc[mt][nt];
            int n = bn + ncol + nt * 8;
#pragma unroll
            for (int half = 0; half < 2; ++half) {
                int m = bm + mrow + mt * 16 + half * 8;
                *(float2*)&C[(size_t)m * CI + n] = make_float2(c[half * 2], c[half * 2 + 1]);
            }
        }
}

// ============================================================
// K6a: per-(b,nb): s = 0.125 * sum_t relu(bias + sum_p parts)
// grid (16, 4), 512 thr; 64 independent loads/thread (high MLP)
// ============================================================
__global__ void reduce_a(const float* __restrict__ re_b) {
    int b = blockIdx.x, nb = blockIdx.y, j = threadIdx.x;
    float bias = re_b[j];
    float s = 0.0f;
#pragma unroll
    for (int t = 0; t < 8; ++t) {
        int r = (b * 8 + t) * 4 + nb;
        float v = bias;
#pragma unroll
        for (int p = 0; p < NPART; ++p)
            v += d_regpart[(size_t)p * NROI * CI + (size_t)r * CI + j];
        s += fmaxf(v, 0.0f);
    }
    s *= 0.125f;
    d_snb[(b * 4 + nb) * CI + j] = s;
    if (nb >= 2) d_objf[(b * 2 + nb - 2) * CI + j] = s;   // argsort identity: cats never 0
}

// ============================================================
// K6b: pooled = mean over nb; labels
// ============================================================
__global__ void reduce_b(const int* __restrict__ cat, float* __restrict__ out_labels) {
    int b = blockIdx.x, j = threadIdx.x;
    float p = 0.25f * (d_snb[(b * 4 + 0) * CI + j] + d_snb[(b * 4 + 1) * CI + j] +
                       d_snb[(b * 4 + 2) * CI + j] + d_snb[(b * 4 + 3) * CI + j]);
    d_pooled[b * CI + j] = p;
    if (j < 2) out_labels[b * 2 + j] = (float)cat[b * 4 + 2 + j];
}

// ============================================================
// K7: fused small dense heads (two independent GEMMs per stage)
// path 0: A0[m0rows,512] @ B0[512,N0]; path 1: A1[...]
// ============================================================
__global__ __launch_bounds__(256) void small_mm2(
    const float* __restrict__ A0, const float* __restrict__ B0,
    const float* __restrict__ bias0, float* __restrict__ C0, int rows0, int N0,
    const float* __restrict__ A1, const float* __restrict__ B1,
    const float* __restrict__ bias1, float* __restrict__ C1, int N1)
{
    __shared__ float As[512];
    __shared__ float red[256];
    const float *A, *Bm, *bias; float* C; int m, N;
    if ((int)blockIdx.x < rows0) { A = A0; Bm = B0; bias = bias0; C = C0; m = blockIdx.x; N = N0; }
    else { A = A1; Bm = B1; bias = bias1; C = C1; m = blockIdx.x - rows0; N = N1; }
    int j0 = blockIdx.y * 64;
    if (j0 >= N) return;
    int tid = threadIdx.x, jl = tid & 63, ks = tid >> 6;
    for (int k = tid; k < 512; k += 256) As[k] = A[m * 512 + k];
    __syncthreads();
    int j = j0 + jl;
    float acc = 0.0f;
    if (j < N) {
        int k0 = ks * 128;
#pragma unroll 8
        for (int k = k0; k < k0 + 128; ++k) acc += As[k] * Bm[k * N + j];
    }
    red[tid] = acc;
    __syncthreads();
    if (tid < 64 && j < N)
        C[m * N + j] = red[tid] + red[tid + 64] + red[tid + 128] + red[tid + 192] + bias[j];
}

// ============================================================
extern "C" void kernel_launch(void* const* d_in, const int* in_sizes, int n_in,
                              void* d_out, int out_size) {
    const float* x       = (const float*)d_in[0];
    const float* boxes   = (const float*)d_in[1];
    const int*   cat     = (const int*)d_in[2];
    const float* conv5_w = (const float*)d_in[3];
    const float* re_w    = (const float*)d_in[4];
    const float* re_b    = (const float*)d_in[5];
    const float* oc1_w   = (const float*)d_in[6];
    const float* oc1_b   = (const float*)d_in[7];
    const float* oc2_w   = (const float*)d_in[8];
    const float* oc2_b   = (const float*)d_in[9];
    const float* pr1_w   = (const float*)d_in[10];
    const float* pr1_b   = (const float*)d_in[11];
    const float* pr2_w   = (const float*)d_in[12];
    const float* pr2_b   = (const float*)d_in[13];

    float* out     = (float*)d_out;
    float* cls_out = out;                       // 16*174
    float* obj_cls = out + 16 * 174;            // 32*301
    float* labels  = out + 16 * 174 + 32 * 301; // 32

    float *p_objf, *p_pooled, *p_h1, *p_g1;
    cudaGetSymbolAddress((void**)&p_objf,   d_objf);
    cudaGetSymbolAddress((void**)&p_pooled, d_pooled);
    cudaGetSymbolAddress((void**)&p_h1,     d_h1);
    cudaGetSymbolAddress((void**)&p_g1,     d_g1);

    cudaFuncSetAttribute(gemm1k, cudaFuncAttributeMaxDynamicSharedMemorySize, GSMEM_BYTES);
    cudaFuncSetAttribute(gemm2k, cudaFuncAttributeMaxDynamicSharedMemorySize, GSMEM_BYTES);

    // Order chosen so gemm1k is the 4th launch (the one ncu captures).
    convw_kernel<<<(CI * CIN) / 256, 256>>>(conv5_w);
    build_table<<<2, 256>>>(boxes);
    pool_kernel<<<dim3(CIN / 32, B_ * T_), 288>>>(x);
    gemm1k<<<dim3(CI / 128, M1 / 128), 256, GSMEM_BYTES>>>();
    convrw_kernel<<<dim3(16, 16, 9), 256>>>(re_w);
    gemm2k<<<dim3(CI / 128, NROI / 128, NPART), 256, GSMEM_BYTES>>>();
    reduce_a<<<dim3(16, 4), 512>>>(re_b);
    reduce_b<<<16, 512>>>(cat, labels);
    // stage 1: h1 = objf@oc1 (32 rows, N=512) ; g1 = pooled@pr1 (16 rows, N=512)
    small_mm2<<<dim3(48, 8), 256>>>(p_objf, oc1_w, oc1_b, p_h1, 32, 512,
                                    p_pooled, pr1_w, pr1_b, p_g1, 512);
    // stage 2: obj_cls = h1@oc2 (N=301) ; cls_out = g1@pr2 (N=174)
    small_mm2<<<dim3(48, 5), 256>>>(p_h1, oc2_w, oc2_b, obj_cls, 32, 301,
                                    p_g1, pr2_w, pr2_b, cls_out, 174);
}

// round 7
// speedup vs baseline: 1.8766x; 1.0372x over previous
#include <cuda_runtime.h>
#include <cuda_bf16.h>
#include <cstdint>

// ---------------- problem constants ----------------
#define B_    16
#define T_    8
#define CIN   2048
#define CI    512
#define HF    14
#define HW    196
#define NROI  512
#define M1    4608          // NROI*9
#define KFEAT 4608          // CI*9
#define NPART 8             // split-K parts for gemm2

// ---------------- scratch (static device memory) ----------------
__device__ __nv_bfloat16 d_roisH[(size_t)M1 * CIN];
__device__ __nv_bfloat16 d_roisL[(size_t)M1 * CIN];
__device__ __nv_bfloat16 d_wH[(size_t)CI * CIN];
__device__ __nv_bfloat16 d_wL[(size_t)CI * CIN];
__device__ __nv_bfloat16 d_rwH[(size_t)CI * KFEAT];   // re_w transposed+permuted [n][bin*512+o]
__device__ __nv_bfloat16 d_rwL[(size_t)CI * KFEAT];
__device__ __nv_bfloat16 d_featsH[(size_t)NROI * KFEAT]; // [roi][bin*512+o]
__device__ __nv_bfloat16 d_featsL[(size_t)NROI * KFEAT];
__device__ float d_regpart[(size_t)NPART * NROI * CI];
__device__ float d_snb[64 * CI];
__device__ float d_objf[32 * CI];
__device__ float d_pooled[16 * CI];
__device__ float d_h1[32 * CI];
__device__ float d_g1[16 * CI];
__device__ int2  d_tap[NROI * 9 * 16];   // {byte-offset into 197-float row, weight bits}

// ---------------- PTX helpers ----------------
__device__ __forceinline__ uint32_t sm_u32(const void* p) {
    return (uint32_t)__cvta_generic_to_shared(p);
}
__device__ __forceinline__ void cpa16(uint32_t dst, const void* src) {
    asm volatile("cp.async.cg.shared.global [%0], [%1], 16;\n" :: "r"(dst), "l"(src));
}
__device__ __forceinline__ void cpa_commit() {
    asm volatile("cp.async.commit_group;\n" ::: "memory");
}
__device__ __forceinline__ void cpa_wait0() {
    asm volatile("cp.async.wait_group 0;\n" ::: "memory");
}
__device__ __forceinline__ void cpa_wait1() {
    asm volatile("cp.async.wait_group 1;\n" ::: "memory");
}
__device__ __forceinline__ void ldsm4(uint32_t* r, uint32_t addr) {
    asm volatile("ldmatrix.sync.aligned.m8n8.x4.shared.b16 {%0,%1,%2,%3}, [%4];"
                 : "=r"(r[0]), "=r"(r[1]), "=r"(r[2]), "=r"(r[3]) : "r"(addr));
}
__device__ __forceinline__ void mma16816(float* c, const uint32_t* a, uint32_t b0, uint32_t b1) {
    asm volatile("mma.sync.aligned.m16n8k16.row.col.f32.bf16.bf16.f32 "
                 "{%0,%1,%2,%3},{%4,%5,%6,%7},{%8,%9},{%0,%1,%2,%3};"
                 : "+f"(c[0]), "+f"(c[1]), "+f"(c[2]), "+f"(c[3])
                 : "r"(a[0]), "r"(a[1]), "r"(a[2]), "r"(a[3]), "r"(b0), "r"(b1));
}

// ============================================================
// K1: ROI-align tap table (byte offsets, weights folded w/ 0.25 mean)
// ============================================================
__global__ void build_table(const float* __restrict__ boxes) {
    int roi = blockIdx.x * blockDim.x + threadIdx.x;
    if (roi >= NROI) return;
    float cx = boxes[roi * 4 + 0], cy = boxes[roi * 4 + 1];
    float w  = boxes[roi * 4 + 2], h  = boxes[roi * 4 + 3];
    const float s = 14.0f / 224.0f;
    float x1 = (cx - 0.5f * w) * 224.0f * s;
    float y1 = (cy - 0.5f * h) * 224.0f * s;
    float x2 = (cx + 0.5f * w) * 224.0f * s;
    float y2 = (cy + 0.5f * h) * 224.0f * s;
    float rw = fmaxf(x2 - x1, 1.0f), rh = fmaxf(y2 - y1, 1.0f);
    float bw = rw / 3.0f, bh = rh / 3.0f;

    float ys[6], xs[6];
#pragma unroll
    for (int p = 0; p < 3; ++p)
#pragma unroll
        for (int i = 0; i < 2; ++i) {
            ys[p * 2 + i] = y1 + p * bh + (i + 0.5f) * bh * 0.5f;
            xs[p * 2 + i] = x1 + p * bw + (i + 0.5f) * bw * 0.5f;
        }

#pragma unroll
    for (int ph = 0; ph < 3; ++ph)
#pragma unroll
        for (int pw = 0; pw < 3; ++pw) {
            int bin = ph * 3 + pw;
#pragma unroll
            for (int iy = 0; iy < 2; ++iy)
#pragma unroll
                for (int ix = 0; ix < 2; ++ix) {
                    int smp = iy * 2 + ix;
                    float yy = ys[ph * 2 + iy];
                    float xx = xs[pw * 2 + ix];
                    bool valid = (yy > -1.0f) && (yy < 14.0f) && (xx > -1.0f) && (xx < 14.0f);
                    float y = fminf(fmaxf(yy, 0.0f), 13.0f);
                    float x = fminf(fmaxf(xx, 0.0f), 13.0f);
                    int y0 = (int)floorf(y), x0 = (int)floorf(x);
                    int y1i = min(y0 + 1, 13), x1i = min(x0 + 1, 13);
                    float ly = y - (float)y0, lx = x - (float)x0;
                    float hy = 1.0f - ly, hx = 1.0f - lx;
                    float q = valid ? 0.25f : 0.0f;
                    int base = (roi * 9 + bin) * 16 + smp * 4;
                    d_tap[base + 0] = make_int2((y0 * HF + x0) * 4,   __float_as_int(hy * hx * q));
                    d_tap[base + 1] = make_int2((y0 * HF + x1i) * 4,  __float_as_int(hy * lx * q));
                    d_tap[base + 2] = make_int2((y1i * HF + x0) * 4,  __float_as_int(ly * hx * q));
                    d_tap[base + 3] = make_int2((y1i * HF + x1i) * 4, __float_as_int(ly * lx * q));
                }
        }
}

// ============================================================
// K2: pooling in 2048-ch space -> bf16 hi/lo (R4 proven shape)
// ============================================================
__global__ __launch_bounds__(288) void pool_kernel(const float* __restrict__ x) {
    __shared__ float pl[32][197];
    __shared__ int2  taps[576];
    int bt = blockIdx.y;
    int c0 = blockIdx.x * 32;
    int tid = threadIdx.x, lane = tid & 31, wid = tid >> 5;

    size_t base = ((size_t)(bt >> 3) * CIN + c0) * (size_t)(T_ * HW) + (size_t)(bt & 7) * HW;
    for (int c = wid; c < 32; c += 9) {
        const float4* src = (const float4*)(x + base + (size_t)c * (T_ * HW));
        for (int p = lane; p < 49; p += 32) {
            float4 v = src[p];
            pl[c][p * 4 + 0] = v.x; pl[c][p * 4 + 1] = v.y;
            pl[c][p * 4 + 2] = v.z; pl[c][p * 4 + 3] = v.w;
        }
    }
    for (int i = tid; i < 576; i += 288) taps[i] = d_tap[bt * 576 + i];
    __syncthreads();

    const char* bp = (const char*)&pl[lane][0];
#pragma unroll
    for (int j = 0; j < 4; ++j) {
        int e = wid + 9 * j;
        const int2* tp = &taps[e * 16];
        float a = 0.0f;
#pragma unroll
        for (int t = 0; t < 16; ++t) {
            int2 pw = tp[t];
            a += __int_as_float(pw.y) * *(const float*)(bp + pw.x);
        }
        size_t off = (size_t)(bt * 36 + e) * CIN + c0 + lane;
        __nv_bfloat16 hb = __float2bfloat16_rn(a);
        d_roisH[off] = hb;
        d_roisL[off] = __float2bfloat16_rn(a - __bfloat162float(hb));
    }
}

// ============================================================
// K3a: convert conv5_w -> bf16 hi/lo
// ============================================================
__global__ void convw_kernel(const float* __restrict__ w) {
    int i = blockIdx.x * 256 + threadIdx.x;
    float v = w[i];
    __nv_bfloat16 hb = __float2bfloat16_rn(v);
    d_wH[i] = hb;
    d_wL[i] = __float2bfloat16_rn(v - __bfloat162float(hb));
}

// ============================================================
// K3b: convert re_w -> transposed+permuted bf16 hi/lo
// ============================================================
__global__ __launch_bounds__(256) void convrw_kernel(const float* __restrict__ w) {
    __shared__ float t[32][33];
    int o0 = blockIdx.x * 32, n0 = blockIdx.y * 32, bin = blockIdx.z;
    int tx = threadIdx.x & 31, ty = threadIdx.x >> 5;
    for (int r = ty; r < 32; r += 8)
        t[r][tx] = w[((size_t)((o0 + r) * 9 + bin)) * 512 + n0 + tx];
    __syncthreads();
    for (int r = ty; r < 32; r += 8) {
        float v = t[tx][r];
        __nv_bfloat16 hb = __float2bfloat16_rn(v);
        __nv_bfloat16 lb = __float2bfloat16_rn(v - __bfloat162float(hb));
        size_t off = (size_t)(n0 + r) * KFEAT + bin * 512 + o0 + tx;
        d_rwH[off] = hb;
        d_rwL[off] = lb;
    }
}

// ============================================================
// GEMM core: 128x128 tile, 512 threads (16 warps, warp tile 32x32),
// bf16 split mma.sync with PASS-OUTER ordering, 3-stage cp.async
// ============================================================
#define KT    32
#define SROW  40
#define TILE_E (128 * SROW)
#define STAGE_E (4 * TILE_E)
#define GSMEM_BYTES (3 * STAGE_E * 2)

__device__ __forceinline__ void gemm_core(
    const __nv_bfloat16* __restrict__ gAh, const __nv_bfloat16* __restrict__ gAl, int lda,
    const __nv_bfloat16* __restrict__ gBh, const __nv_bfloat16* __restrict__ gBl, int ldb,
    int bm, int bn, int kbase, int niter,
    __nv_bfloat16* sm, float (&acc)[2][4][4])
{
    int tid = threadIdx.x, lane = tid & 31, wid = tid >> 5;
    int wm = wid >> 2, wn = wid & 3;     // 4x4 warp grid, warp tile 32x32

    auto ldg = [&](int t) {
        int s = t % 3;
        int k0 = kbase + t * KT;
        __nv_bfloat16* base = sm + s * STAGE_E;
        int row = tid >> 2, c = tid & 3;   // 512 threads = 128 rows x 4 chunks
        __nv_bfloat16* pd = base + row * SROW + c * 8;
        cpa16(sm_u32(pd),               gAh + (size_t)(bm + row) * lda + k0 + c * 8);
        cpa16(sm_u32(pd + TILE_E),      gAl + (size_t)(bm + row) * lda + k0 + c * 8);
        cpa16(sm_u32(pd + 2 * TILE_E),  gBh + (size_t)(bn + row) * ldb + k0 + c * 8);
        cpa16(sm_u32(pd + 3 * TILE_E),  gBl + (size_t)(bn + row) * ldb + k0 + c * 8);
    };

    int ar  = wm * 32 + (lane & 15);
    int ac8 = (lane >> 4) * 8;
    int br  = wn * 32 + (lane & 7) + ((lane >> 4) << 3);
    int bc8 = ((lane >> 3) & 1) * 8;

    ldg(0); cpa_commit();
    if (niter > 1) { ldg(1); cpa_commit(); }

#pragma unroll 1
    for (int t = 0; t < niter; ++t) {
        if (t + 1 < niter) cpa_wait1(); else cpa_wait0();
        __syncthreads();
        if (t + 2 < niter) { ldg(t + 2); cpa_commit(); }

        __nv_bfloat16* base = sm + (t % 3) * STAGE_E;
        const __nv_bfloat16* pAh = base;
        const __nv_bfloat16* pAl = base + TILE_E;
        const __nv_bfloat16* pBh = base + 2 * TILE_E;
        const __nv_bfloat16* pBl = base + 3 * TILE_E;

#pragma unroll
        for (int ks = 0; ks < 2; ++ks) {
            uint32_t ah[2][4], al[2][4], bh[2][4], bl[2][4];
#pragma unroll
            for (int mt = 0; mt < 2; ++mt) {
                ldsm4(ah[mt], sm_u32(pAh + (ar + mt * 16) * SROW + ks * 16 + ac8));
                ldsm4(al[mt], sm_u32(pAl + (ar + mt * 16) * SROW + ks * 16 + ac8));
            }
#pragma unroll
            for (int bt2 = 0; bt2 < 2; ++bt2) {
                ldsm4(bh[bt2], sm_u32(pBh + (br + bt2 * 16) * SROW + ks * 16 + bc8));
                ldsm4(bl[bt2], sm_u32(pBl + (br + bt2 * 16) * SROW + ks * 16 + bc8));
            }
            // pass-outer: all 8 accumulators independent within each pass
#pragma unroll
            for (int mt = 0; mt < 2; ++mt)
#pragma unroll
                for (int nt = 0; nt < 4; ++nt)
                    mma16816(acc[mt][nt], ah[mt],
                             bh[nt >> 1][(nt & 1) * 2], bh[nt >> 1][(nt & 1) * 2 + 1]);
#pragma unroll
            for (int mt = 0; mt < 2; ++mt)
#pragma unroll
                for (int nt = 0; nt < 4; ++nt)
                    mma16816(acc[mt][nt], al[mt],
                             bh[nt >> 1][(nt & 1) * 2], bh[nt >> 1][(nt & 1) * 2 + 1]);
#pragma unroll
            for (int mt = 0; mt < 2; ++mt)
#pragma unroll
                for (int nt = 0; nt < 4; ++nt)
                    mma16816(acc[mt][nt], ah[mt],
                             bl[nt >> 1][(nt & 1) * 2], bl[nt >> 1][(nt & 1) * 2 + 1]);
        }
    }
}

// ============================================================
// K4: GEMM1: feats = rois2048[4608,2048] x conv5_w[512,2048]^T
// ============================================================
__global__ __launch_bounds__(512) void gemm1k() {
    extern __shared__ __nv_bfloat16 sm[];
    int bm = blockIdx.y * 128, bn = blockIdx.x * 128;
    float acc[2][4][4];
#pragma unroll
    for (int a = 0; a < 2; ++a)
#pragma unroll
        for (int b = 0; b < 4; ++b)
#pragma unroll
            for (int c = 0; c < 4; ++c) acc[a][b][c] = 0.0f;

    gemm_core(d_roisH, d_roisL, CIN, d_wH, d_wL, CIN, bm, bn, 0, CIN / KT, sm, acc);

    int lane = threadIdx.x & 31, wid = threadIdx.x >> 5;
    int wm = wid >> 2, wn = wid & 3;
    int mrow = wm * 32 + (lane >> 2);
    int ncol = wn * 32 + ((lane & 3) << 1);
#pragma unroll
    for (int mt = 0; mt < 2; ++mt)
#pragma unroll
        for (int nt = 0; nt < 4; ++nt) {
            float* c = acc[mt][nt];
            int n = bn + ncol + nt * 8;
#pragma unroll
            for (int half = 0; half < 2; ++half) {
                int m = bm + mrow + mt * 16 + half * 8;
                int roi = m / 9, bin = m - roi * 9;
                size_t off = (size_t)roi * KFEAT + bin * 512 + n;
                float v0 = c[half * 2 + 0], v1 = c[half * 2 + 1];
                __nv_bfloat16 h0 = __float2bfloat16_rn(v0);
                __nv_bfloat16 h1 = __float2bfloat16_rn(v1);
                __nv_bfloat162 hp; hp.x = h0; hp.y = h1;
                __nv_bfloat162 lp;
                lp.x = __float2bfloat16_rn(v0 - __bfloat162float(h0));
                lp.y = __float2bfloat16_rn(v1 - __bfloat162float(h1));
                *(__nv_bfloat162*)&d_featsH[off] = hp;
                *(__nv_bfloat162*)&d_featsL[off] = lp;
            }
        }
}

// ============================================================
// K5: GEMM2 (split-K=8): regpart = feats[512,4608] x rw[512,4608]^T
// ============================================================
__global__ __launch_bounds__(512) void gemm2k() {
    extern __shared__ __nv_bfloat16 sm[];
    int bm = blockIdx.y * 128, bn = blockIdx.x * 128;
    int part = blockIdx.z;
    float acc[2][4][4];
#pragma unroll
    for (int a = 0; a < 2; ++a)
#pragma unroll
        for (int b = 0; b < 4; ++b)
#pragma unroll
            for (int c = 0; c < 4; ++c) acc[a][b][c] = 0.0f;

    gemm_core(d_featsH, d_featsL, KFEAT, d_rwH, d_rwL, KFEAT,
              bm, bn, part * (KFEAT / NPART), (KFEAT / NPART) / KT, sm, acc);

    int lane = threadIdx.x & 31, wid = threadIdx.x >> 5;
    int wm = wid >> 2, wn = wid & 3;
    int mrow = wm * 32 + (lane >> 2);
    int ncol = wn * 32 + ((lane & 3) << 1);
    float* C = d_regpart + (size_t)part * NROI * CI;
#pragma unroll
    for (int mt = 0; mt < 2; ++mt)
#pragma unroll
        for (int nt = 0; nt < 4; ++nt) {
            float* c = acc[mt][nt];
            int n = bn + ncol + nt * 8;
#pragma unroll
            for (int half = 0; half < 2; ++half) {
                int m = bm + mrow + mt * 16 + half * 8;
                *(float2*)&C[(size_t)m * CI + n] = make_float2(c[half * 2], c[half * 2 + 1]);
            }
        }
}

// ============================================================
// K6a: per-(b,nb): s = 0.125 * sum_t relu(bias + sum_p parts)
// ============================================================
__global__ void reduce_a(const float* __restrict__ re_b) {
    int b = blockIdx.x, nb = blockIdx.y, j = threadIdx.x;
    float bias = re_b[j];
    float s = 0.0f;
#pragma unroll
    for (int t = 0; t < 8; ++t) {
        int r = (b * 8 + t) * 4 + nb;
        float v = bias;
#pragma unroll
        for (int p = 0; p < NPART; ++p)
            v += d_regpart[(size_t)p * NROI * CI + (size_t)r * CI + j];
        s += fmaxf(v, 0.0f);
    }
    s *= 0.125f;
    d_snb[(b * 4 + nb) * CI + j] = s;
    if (nb >= 2) d_objf[(b * 2 + nb - 2) * CI + j] = s;   // argsort identity: cats never 0
}

// ============================================================
// K6b: pooled = mean over nb; labels
// ============================================================
__global__ void reduce_b(const int* __restrict__ cat, float* __restrict__ out_labels) {
    int b = blockIdx.x, j = threadIdx.x;
    float p = 0.25f * (d_snb[(b * 4 + 0) * CI + j] + d_snb[(b * 4 + 1) * CI + j] +
                       d_snb[(b * 4 + 2) * CI + j] + d_snb[(b * 4 + 3) * CI + j]);
    d_pooled[b * CI + j] = p;
    if (j < 2) out_labels[b * 2 + j] = (float)cat[b * 4 + 2 + j];
}

// ============================================================
// K7: fused small dense heads (two independent GEMMs per stage)
// ============================================================
__global__ __launch_bounds__(256) void small_mm2(
    const float* __restrict__ A0, const float* __restrict__ B0,
    const float* __restrict__ bias0, float* __restrict__ C0, int rows0, int N0,
    const float* __restrict__ A1, const float* __restrict__ B1,
    const float* __restrict__ bias1, float* __restrict__ C1, int N1)
{
    __shared__ float As[512];
    __shared__ float red[256];
    const float *A, *Bm, *bias; float* C; int m, N;
    if ((int)blockIdx.x < rows0) { A = A0; Bm = B0; bias = bias0; C = C0; m = blockIdx.x; N = N0; }
    else { A = A1; Bm = B1; bias = bias1; C = C1; m = blockIdx.x - rows0; N = N1; }
    int j0 = blockIdx.y * 64;
    if (j0 >= N) return;
    int tid = threadIdx.x, jl = tid & 63, ks = tid >> 6;
    for (int k = tid; k < 512; k += 256) As[k] = A[m * 512 + k];
    __syncthreads();
    int j = j0 + jl;
    float acc = 0.0f;
    if (j < N) {
        int k0 = ks * 128;
#pragma unroll 8
        for (int k = k0; k < k0 + 128; ++k) acc += As[k] * Bm[k * N + j];
    }
    red[tid] = acc;
    __syncthreads();
    if (tid < 64 && j < N)
        C[m * N + j] = red[tid] + red[tid + 64] + red[tid + 128] + red[tid + 192] + bias[j];
}

// ============================================================
extern "C" void kernel_launch(void* const* d_in, const int* in_sizes, int n_in,
                              void* d_out, int out_size) {
    const float* x       = (const float*)d_in[0];
    const float* boxes   = (const float*)d_in[1];
    const int*   cat     = (const int*)d_in[2];
    const float* conv5_w = (const float*)d_in[3];
    const float* re_w    = (const float*)d_in[4];
    const float* re_b    = (const float*)d_in[5];
    const float* oc1_w   = (const float*)d_in[6];
    const float* oc1_b   = (const float*)d_in[7];
    const float* oc2_w   = (const float*)d_in[8];
    const float* oc2_b   = (const float*)d_in[9];
    const float* pr1_w   = (const float*)d_in[10];
    const float* pr1_b   = (const float*)d_in[11];
    const float* pr2_w   = (const float*)d_in[12];
    const float* pr2_b   = (const float*)d_in[13];

    float* out     = (float*)d_out;
    float* cls_out = out;                       // 16*174
    float* obj_cls = out + 16 * 174;            // 32*301
    float* labels  = out + 16 * 174 + 32 * 301; // 32

    float *p_objf, *p_pooled, *p_h1, *p_g1;
    cudaGetSymbolAddress((void**)&p_objf,   d_objf);
    cudaGetSymbolAddress((void**)&p_pooled, d_pooled);
    cudaGetSymbolAddress((void**)&p_h1,     d_h1);
    cudaGetSymbolAddress((void**)&p_g1,     d_g1);

    cudaFuncSetAttribute(gemm1k, cudaFuncAttributeMaxDynamicSharedMemorySize, GSMEM_BYTES);
    cudaFuncSetAttribute(gemm2k, cudaFuncAttributeMaxDynamicSharedMemorySize, GSMEM_BYTES);

    // Order keeps gemm1k as the 4th launch (the one ncu captures).
    convw_kernel<<<(CI * CIN) / 256, 256>>>(conv5_w);
    build_table<<<2, 256>>>(boxes);
    pool_kernel<<<dim3(CIN / 32, B_ * T_), 288>>>(x);
    gemm1k<<<dim3(CI / 128, M1 / 128), 512, GSMEM_BYTES>>>();
    convrw_kernel<<<dim3(16, 16, 9), 256>>>(re_w);
    gemm2k<<<dim3(CI / 128, NROI / 128, NPART), 512, GSMEM_BYTES>>>();
    reduce_a<<<dim3(16, 4), 512>>>(re_b);
    reduce_b<<<16, 512>>>(cat, labels);
    small_mm2<<<dim3(48, 8), 256>>>(p_objf, oc1_w, oc1_b, p_h1, 32, 512,
                                    p_pooled, pr1_w, pr1_b, p_g1, 512);
    small_mm2<<<dim3(48, 5), 256>>>(p_h1, oc2_w, oc2_b, obj_cls, 32, 301,
                                    p_g1, pr2_w, pr2_b, cls_out, 174);
}

// round 9
// speedup vs baseline: 1.8769x; 1.0002x over previous
#include <cuda_runtime.h>
#include <cuda_bf16.h>
#include <cstdint>

// ---------------- problem constants ----------------
#define B_    16
#define T_    8
#define CIN   2048
#define CI    512
#define HF    14
#define HW    196
#define NROI  512
#define M1    4608          // NROI*9
#define KFEAT 4608          // CI*9
#define NPART 8             // split-K parts for gemm2

// ---------------- scratch (static device memory) ----------------
__device__ __nv_bfloat16 d_roisH[(size_t)M1 * CIN];
__device__ __nv_bfloat16 d_roisL[(size_t)M1 * CIN];
__device__ __nv_bfloat16 d_wH[(size_t)CI * CIN];
__device__ __nv_bfloat16 d_wL[(size_t)CI * CIN];
__device__ __nv_bfloat16 d_rwH[(size_t)CI * KFEAT];   // re_w transposed+permuted [n][bin*512+o]
__device__ __nv_bfloat16 d_rwL[(size_t)CI * KFEAT];
__device__ __nv_bfloat16 d_featsH[(size_t)NROI * KFEAT]; // [roi][bin*512+o]
__device__ __nv_bfloat16 d_featsL[(size_t)NROI * KFEAT];
__device__ float d_regpart[(size_t)NPART * NROI * CI];
__device__ float d_snb[64 * CI];
__device__ float d_objf[32 * CI];
__device__ float d_pooled[16 * CI];
__device__ float d_h1[32 * CI];
__device__ float d_g1[16 * CI];
__device__ int2  d_tap[NROI * 9 * 16];   // {byte-offset into 197-float row, weight bits}

// ---------------- PTX helpers ----------------
__device__ __forceinline__ uint32_t sm_u32(const void* p) {
    return (uint32_t)__cvta_generic_to_shared(p);
}
__device__ __forceinline__ void cpa16(uint32_t dst, const void* src) {
    asm volatile("cp.async.cg.shared.global [%0], [%1], 16;\n" :: "r"(dst), "l"(src));
}
__device__ __forceinline__ void cpa_commit() {
    asm volatile("cp.async.commit_group;\n" ::: "memory");
}
__device__ __forceinline__ void cpa_wait3() {
    asm volatile("cp.async.wait_group 3;\n" ::: "memory");
}
__device__ __forceinline__ void ldsm4(uint32_t* r, uint32_t addr) {
    asm volatile("ldmatrix.sync.aligned.m8n8.x4.shared.b16 {%0,%1,%2,%3}, [%4];"
                 : "=r"(r[0]), "=r"(r[1]), "=r"(r[2]), "=r"(r[3]) : "r"(addr));
}
__device__ __forceinline__ void mma16816(float* c, const uint32_t* a, uint32_t b0, uint32_t b1) {
    asm volatile("mma.sync.aligned.m16n8k16.row.col.f32.bf16.bf16.f32 "
                 "{%0,%1,%2,%3},{%4,%5,%6,%7},{%8,%9},{%0,%1,%2,%3};"
                 : "+f"(c[0]), "+f"(c[1]), "+f"(c[2]), "+f"(c[3])
                 : "r"(a[0]), "r"(a[1]), "r"(a[2]), "r"(a[3]), "r"(b0), "r"(b1));
}

// ============================================================
// K1: ROI-align tap table (byte offsets, weights folded w/ 0.25 mean)
// ============================================================
__global__ void build_table(const float* __restrict__ boxes) {
    int roi = blockIdx.x * blockDim.x + threadIdx.x;
    if (roi >= NROI) return;
    float cx = boxes[roi * 4 + 0], cy = boxes[roi * 4 + 1];
    float w  = boxes[roi * 4 + 2], h  = boxes[roi * 4 + 3];
    const float s = 14.0f / 224.0f;
    float x1 = (cx - 0.5f * w) * 224.0f * s;
    float y1 = (cy - 0.5f * h) * 224.0f * s;
    float x2 = (cx + 0.5f * w) * 224.0f * s;
    float y2 = (cy + 0.5f * h) * 224.0f * s;
    float rw = fmaxf(x2 - x1, 1.0f), rh = fmaxf(y2 - y1, 1.0f);
    float bw = rw / 3.0f, bh = rh / 3.0f;

    float ys[6], xs[6];
#pragma unroll
    for (int p = 0; p < 3; ++p)
#pragma unroll
        for (int i = 0; i < 2; ++i) {
            ys[p * 2 + i] = y1 + p * bh + (i + 0.5f) * bh * 0.5f;
            xs[p * 2 + i] = x1 + p * bw + (i + 0.5f) * bw * 0.5f;
        }

#pragma unroll
    for (int ph = 0; ph < 3; ++ph)
#pragma unroll
        for (int pw = 0; pw < 3; ++pw) {
            int bin = ph * 3 + pw;
#pragma unroll
            for (int iy = 0; iy < 2; ++iy)
#pragma unroll
                for (int ix = 0; ix < 2; ++ix) {
                    int smp = iy * 2 + ix;
                    float yy = ys[ph * 2 + iy];
                    float xx = xs[pw * 2 + ix];
                    bool valid = (yy > -1.0f) && (yy < 14.0f) && (xx > -1.0f) && (xx < 14.0f);
                    float y = fminf(fmaxf(yy, 0.0f), 13.0f);
                    float x = fminf(fmaxf(xx, 0.0f), 13.0f);
                    int y0 = (int)floorf(y), x0 = (int)floorf(x);
                    int y1i = min(y0 + 1, 13), x1i = min(x0 + 1, 13);
                    float ly = y - (float)y0, lx = x - (float)x0;
                    float hy = 1.0f - ly, hx = 1.0f - lx;
                    float q = valid ? 0.25f : 0.0f;
                    int base = (roi * 9 + bin) * 16 + smp * 4;
                    d_tap[base + 0] = make_int2((y0 * HF + x0) * 4,   __float_as_int(hy * hx * q));
                    d_tap[base + 1] = make_int2((y0 * HF + x1i) * 4,  __float_as_int(hy * lx * q));
                    d_tap[base + 2] = make_int2((y1i * HF + x0) * 4,  __float_as_int(ly * hx * q));
                    d_tap[base + 3] = make_int2((y1i * HF + x1i) * 4, __float_as_int(ly * lx * q));
                }
        }
}

// ============================================================
// K2: pooling in 2048-ch space -> bf16 hi/lo (R4 proven shape)
// ============================================================
__global__ __launch_bounds__(288) void pool_kernel(const float* __restrict__ x) {
    __shared__ float pl[32][197];
    __shared__ int2  taps[576];
    int bt = blockIdx.y;
    int c0 = blockIdx.x * 32;
    int tid = threadIdx.x, lane = tid & 31, wid = tid >> 5;

    size_t base = ((size_t)(bt >> 3) * CIN + c0) * (size_t)(T_ * HW) + (size_t)(bt & 7) * HW;
    for (int c = wid; c < 32; c += 9) {
        const float4* src = (const float4*)(x + base + (size_t)c * (T_ * HW));
        for (int p = lane; p < 49; p += 32) {
            float4 v = src[p];
            pl[c][p * 4 + 0] = v.x; pl[c][p * 4 + 1] = v.y;
            pl[c][p * 4 + 2] = v.z; pl[c][p * 4 + 3] = v.w;
        }
    }
    for (int i = tid; i < 576; i += 288) taps[i] = d_tap[bt * 576 + i];
    __syncthreads();

    const char* bp = (const char*)&pl[lane][0];
#pragma unroll
    for (int j = 0; j < 4; ++j) {
        int e = wid + 9 * j;
        const int2* tp = &taps[e * 16];
        float a = 0.0f;
#pragma unroll
        for (int t = 0; t < 16; ++t) {
            int2 pw = tp[t];
            a += __int_as_float(pw.y) * *(const float*)(bp + pw.x);
        }
        size_t off = (size_t)(bt * 36 + e) * CIN + c0 + lane;
        __nv_bfloat16 hb = __float2bfloat16_rn(a);
        d_roisH[off] = hb;
        d_roisL[off] = __float2bfloat16_rn(a - __bfloat162float(hb));
    }
}

// ============================================================
// K3a: convert conv5_w -> bf16 hi/lo
// ============================================================
__global__ void convw_kernel(const float* __restrict__ w) {
    int i = blockIdx.x * 256 + threadIdx.x;
    float v = w[i];
    __nv_bfloat16 hb = __float2bfloat16_rn(v);
    d_wH[i] = hb;
    d_wL[i] = __float2bfloat16_rn(v - __bfloat162float(hb));
}

// ============================================================
// K3b: convert re_w -> transposed+permuted bf16 hi/lo
// ============================================================
__global__ __launch_bounds__(256) void convrw_kernel(const float* __restrict__ w) {
    __shared__ float t[32][33];
    int o0 = blockIdx.x * 32, n0 = blockIdx.y * 32, bin = blockIdx.z;
    int tx = threadIdx.x & 31, ty = threadIdx.x >> 5;
    for (int r = ty; r < 32; r += 8)
        t[r][tx] = w[((size_t)((o0 + r) * 9 + bin)) * 512 + n0 + tx];
    __syncthreads();
    for (int r = ty; r < 32; r += 8) {
        float v = t[tx][r];
        __nv_bfloat16 hb = __float2bfloat16_rn(v);
        __nv_bfloat16 lb = __float2bfloat16_rn(v - __bfloat162float(hb));
        size_t off = (size_t)(n0 + r) * KFEAT + bin * 512 + o0 + tx;
        d_rwH[off] = hb;
        d_rwL[off] = lb;
    }
}

// ============================================================
// GEMM core: 128x128 tile, 512 threads (16 warps, warp tile 32x32),
// bf16 split mma.sync, 5-stage cp.async (uniform wait_group 3 via
// empty-commit padding), per-iter: 16 ldsm up-front then 48 MMAs
// ============================================================
#define KT     32
#define SROW   40
#define TILE_E (128 * SROW)
#define STAGE_E (4 * TILE_E)
#define NSTAGE 5
#define GSMEM_BYTES (NSTAGE * STAGE_E * 2)

__device__ __forceinline__ void gemm_core(
    const __nv_bfloat16* __restrict__ gAh, const __nv_bfloat16* __restrict__ gAl, int lda,
    const __nv_bfloat16* __restrict__ gBh, const __nv_bfloat16* __restrict__ gBl, int ldb,
    int bm, int bn, int kbase, int niter,
    __nv_bfloat16* sm, float (&acc)[2][4][4])
{
    int tid = threadIdx.x, lane = tid & 31, wid = tid >> 5;
    int wm = wid >> 2, wn = wid & 3;     // 4x4 warp grid, warp tile 32x32

    auto ldg = [&](int t) {
        int s = t % NSTAGE;
        int k0 = kbase + t * KT;
        __nv_bfloat16* base = sm + s * STAGE_E;
        int row = tid >> 2, c = tid & 3;   // 512 threads = 128 rows x 4 chunks
        __nv_bfloat16* pd = base + row * SROW + c * 8;
        cpa16(sm_u32(pd),               gAh + (size_t)(bm + row) * lda + k0 + c * 8);
        cpa16(sm_u32(pd + TILE_E),      gAl + (size_t)(bm + row) * lda + k0 + c * 8);
        cpa16(sm_u32(pd + 2 * TILE_E),  gBh + (size_t)(bn + row) * ldb + k0 + c * 8);
        cpa16(sm_u32(pd + 3 * TILE_E),  gBl + (size_t)(bn + row) * ldb + k0 + c * 8);
    };

    int ar  = wm * 32 + (lane & 15);
    int ac8 = (lane >> 4) * 8;
    int br  = wn * 32 + (lane & 7) + ((lane >> 4) << 3);
    int bc8 = ((lane >> 3) & 1) * 8;

    // prologue: exactly 4 committed groups (pad with empty if short)
#pragma unroll
    for (int s = 0; s < 4; ++s) {
        if (s < niter) ldg(s);
        cpa_commit();
    }

#pragma unroll 1
    for (int t = 0; t < niter; ++t) {
        cpa_wait3();            // stage t guaranteed complete
        __syncthreads();        // all warps done reading stage (t-1)%NSTAGE
        if (t + 4 < niter) ldg(t + 4);
        cpa_commit();           // empty at tail -> uniform pending count

        __nv_bfloat16* base = sm + (t % NSTAGE) * STAGE_E;
        const __nv_bfloat16* pAh = base;
        const __nv_bfloat16* pAl = base + TILE_E;
        const __nv_bfloat16* pBh = base + 2 * TILE_E;
        const __nv_bfloat16* pBl = base + 3 * TILE_E;

        // all fragments for both ks slices up-front (16 ldsm)
        uint32_t ah[2][2][4], al[2][2][4], bh[2][2][4], bl[2][2][4];
#pragma unroll
        for (int ks = 0; ks < 2; ++ks) {
#pragma unroll
            for (int mt = 0; mt < 2; ++mt) {
                ldsm4(ah[ks][mt], sm_u32(pAh + (ar + mt * 16) * SROW + ks * 16 + ac8));
                ldsm4(al[ks][mt], sm_u32(pAl + (ar + mt * 16) * SROW + ks * 16 + ac8));
            }
#pragma unroll
            for (int bt2 = 0; bt2 < 2; ++bt2) {
                ldsm4(bh[ks][bt2], sm_u32(pBh + (br + bt2 * 16) * SROW + ks * 16 + bc8));
                ldsm4(bl[ks][bt2], sm_u32(pBl + (br + bt2 * 16) * SROW + ks * 16 + bc8));
            }
        }
        // pass-outer, ks-middle: same-acc reuse distance = 8 MMAs
#pragma unroll
        for (int ks = 0; ks < 2; ++ks)
#pragma unroll
            for (int mt = 0; mt < 2; ++mt)
#pragma unroll
                for (int nt = 0; nt < 4; ++nt)
                    mma16816(acc[mt][nt], ah[ks][mt],
                             bh[ks][nt >> 1][(nt & 1) * 2], bh[ks][nt >> 1][(nt & 1) * 2 + 1]);
#pragma unroll
        for (int ks = 0; ks < 2; ++ks)
#pragma unroll
            for (int mt = 0; mt < 2; ++mt)
#pragma unroll
                for (int nt = 0; nt < 4; ++nt)
                    mma16816(acc[mt][nt], al[ks][mt],
                             bh[ks][nt >> 1][(nt & 1) * 2], bh[ks][nt >> 1][(nt & 1) * 2 + 1]);
#pragma unroll
        for (int ks = 0; ks < 2; ++ks)
#pragma unroll
            for (int mt = 0; mt < 2; ++mt)
#pragma unroll
                for (int nt = 0; nt < 4; ++nt)
                    mma16816(acc[mt][nt], ah[ks][mt],
                             bl[ks][nt >> 1][(nt & 1) * 2], bl[ks][nt >> 1][(nt & 1) * 2 + 1]);
    }
}

// ============================================================
// K4: GEMM1: feats = rois2048[4608,2048] x conv5_w[512,2048]^T
// ============================================================
__global__ __launch_bounds__(512) void gemm1k() {
    extern __shared__ __nv_bfloat16 sm[];
    int bm = blockIdx.y * 128, bn = blockIdx.x * 128;
    float acc[2][4][4];
#pragma unroll
    for (int a = 0; a < 2; ++a)
#pragma unroll
        for (int b = 0; b < 4; ++b)
#pragma unroll
            for (int c = 0; c < 4; ++c) acc[a][b][c] = 0.0f;

    gemm_core(d_roisH, d_roisL, CIN, d_wH, d_wL, CIN, bm, bn, 0, CIN / KT, sm, acc);

    int lane = threadIdx.x & 31, wid = threadIdx.x >> 5;
    int wm = wid >> 2, wn = wid & 3;
    int mrow = wm * 32 + (lane >> 2);
    int ncol = wn * 32 + ((lane & 3) << 1);
#pragma unroll
    for (int mt = 0; mt < 2; ++mt)
#pragma unroll
        for (int nt = 0; nt < 4; ++nt) {
            float* c = acc[mt][nt];
            int n = bn + ncol + nt * 8;
#pragma unroll
            for (int half = 0; half < 2; ++half) {
                int m = bm + mrow + mt * 16 + half * 8;
                int roi = m / 9, bin = m - roi * 9;
                size_t off = (size_t)roi * KFEAT + bin * 512 + n;
                float v0 = c[half * 2 + 0], v1 = c[half * 2 + 1];
                __nv_bfloat16 h0 = __float2bfloat16_rn(v0);
                __nv_bfloat16 h1 = __float2bfloat16_rn(v1);
                __nv_bfloat162 hp; hp.x = h0; hp.y = h1;
                __nv_bfloat162 lp;
                lp.x = __float2bfloat16_rn(v0 - __bfloat162float(h0));
                lp.y = __float2bfloat16_rn(v1 - __bfloat162float(h1));
                *(__nv_bfloat162*)&d_featsH[off] = hp;
                *(__nv_bfloat162*)&d_featsL[off] = lp;
            }
        }
}

// ============================================================
// K5: GEMM2 (split-K=8): regpart = feats[512,4608] x rw[512,4608]^T
// ============================================================
__global__ __launch_bounds__(512) void gemm2k() {
    extern __shared__ __nv_bfloat16 sm[];
    int bm = blockIdx.y * 128, bn = blockIdx.x * 128;
    int part = blockIdx.z;
    float acc[2][4][4];
#pragma unroll
    for (int a = 0; a < 2; ++a)
#pragma unroll
        for (int b = 0; b < 4; ++b)
#pragma unroll
            for (int c = 0; c < 4; ++c) acc[a][b][c] = 0.0f;

    gemm_core(d_featsH, d_featsL, KFEAT, d_rwH, d_rwL, KFEAT,
              bm, bn, part * (KFEAT / NPART), (KFEAT / NPART) / KT, sm, acc);

    int lane = threadIdx.x & 31, wid = threadIdx.x >> 5;
    int wm = wid >> 2, wn = wid & 3;
    int mrow = wm * 32 + (lane >> 2);
    int ncol = wn * 32 + ((lane & 3) << 1);
    float* C = d_regpart + (size_t)part * NROI * CI;
#pragma unroll
    for (int mt = 0; mt < 2; ++mt)
#pragma unroll
        for (int nt = 0; nt < 4; ++nt) {
            float* c = acc[mt][nt];
            int n = bn + ncol + nt * 8;
#pragma unroll
            for (int half = 0; half < 2; ++half) {
                int m = bm + mrow + mt * 16 + half * 8;
                *(float2*)&C[(size_t)m * CI + n] = make_float2(c[half * 2], c[half * 2 + 1]);
            }
        }
}

// ============================================================
// K6a: per-(b,nb): s = 0.125 * sum_t relu(bias + sum_p parts)
// ============================================================
__global__ void reduce_a(const float* __restrict__ re_b) {
    int b = blockIdx.x, nb = blockIdx.y, j = threadIdx.x;
    float bias = re_b[j];
    float s = 0.0f;
#pragma unroll
    for (int t = 0; t < 8; ++t) {
        int r = (b * 8 + t) * 4 + nb;
        float v = bias;
#pragma unroll
        for (int p = 0; p < NPART; ++p)
            v += d_regpart[(size_t)p * NROI * CI + (size_t)r * CI + j];
        s += fmaxf(v, 0.0f);
    }
    s *= 0.125f;
    d_snb[(b * 4 + nb) * CI + j] = s;
    if (nb >= 2) d_objf[(b * 2 + nb - 2) * CI + j] = s;   // argsort identity: cats never 0
}

// ============================================================
// K6b: pooled = mean over nb; labels
// ============================================================
__global__ void reduce_b(const int* __restrict__ cat, float* __restrict__ out_labels) {
    int b = blockIdx.x, j = threadIdx.x;
    float p = 0.25f * (d_snb[(b * 4 + 0) * CI + j] + d_snb[(b * 4 + 1) * CI + j] +
                       d_snb[(b * 4 + 2) * CI + j] + d_snb[(b * 4 + 3) * CI + j]);
    d_pooled[b * CI + j] = p;
    if (j < 2) out_labels[b * 2 + j] = (float)cat[b * 4 + 2 + j];
}

// ============================================================
// K7: fused small dense heads (two independent GEMMs per stage)
// ============================================================
__global__ __launch_bounds__(256) void small_mm2(
    const float* __restrict__ A0, const float* __restrict__ B0,
    const float* __restrict__ bias0, float* __restrict__ C0, int rows0, int N0,
    const float* __restrict__ A1, const float* __restrict__ B1,
    const float* __restrict__ bias1, float* __restrict__ C1, int N1)
{
    __shared__ float As[512];
    __shared__ float red[256];
    const float *A, *Bm, *bias; float* C; int m, N;
    if ((int)blockIdx.x < rows0) { A = A0; Bm = B0; bias = bias0; C = C0; m = blockIdx.x; N = N0; }
    else { A = A1; Bm = B1; bias = bias1; C = C1; m = blockIdx.x - rows0; N = N1; }
    int j0 = blockIdx.y * 64;
    if (j0 >= N) return;
    int tid = threadIdx.x, jl = tid & 63, ks = tid >> 6;
    for (int k = tid; k < 512; k += 256) As[k] = A[m * 512 + k];
    __syncthreads();
    int j = j0 + jl;
    float acc = 0.0f;
    if (j < N) {
        int k0 = ks * 128;
#pragma unroll 8
        for (int k = k0; k < k0 + 128; ++k) acc += As[k] * Bm[k * N + j];
    }
    red[tid] = acc;
    __syncthreads();
    if (tid < 64 && j < N)
        C[m * N + j] = red[tid] + red[tid + 64] + red[tid + 128] + red[tid + 192] + bias[j];
}

// ============================================================
extern "C" void kernel_launch(void* const* d_in, const int* in_sizes, int n_in,
                              void* d_out, int out_size) {
    const float* x       = (const float*)d_in[0];
    const float* boxes   = (const float*)d_in[1];
    const int*   cat     = (const int*)d_in[2];
    const float* conv5_w = (const float*)d_in[3];
    const float* re_w    = (const float*)d_in[4];
    const float* re_b    = (const float*)d_in[5];
    const float* oc1_w   = (const float*)d_in[6];
    const float* oc1_b   = (const float*)d_in[7];
    const float* oc2_w   = (const float*)d_in[8];
    const float* oc2_b   = (const float*)d_in[9];
    const float* pr1_w   = (const float*)d_in[10];
    const float* pr1_b   = (const float*)d_in[11];
    const float* pr2_w   = (const float*)d_in[12];
    const float* pr2_b   = (const float*)d_in[13];

    float* out     = (float*)d_out;
    float* cls_out = out;                       // 16*174
    float* obj_cls = out + 16 * 174;            // 32*301
    float* labels  = out + 16 * 174 + 32 * 301; // 32

    float *p_objf, *p_pooled, *p_h1, *p_g1;
    cudaGetSymbolAddress((void**)&p_objf,   d_objf);
    cudaGetSymbolAddress((void**)&p_pooled, d_pooled);
    cudaGetSymbolAddress((void**)&p_h1,     d_h1);
    cudaGetSymbolAddress((void**)&p_g1,     d_g1);

    cudaFuncSetAttribute(gemm1k, cudaFuncAttributeMaxDynamicSharedMemorySize, GSMEM_BYTES);
    cudaFuncSetAttribute(gemm2k, cudaFuncAttributeMaxDynamicSharedMemorySize, GSMEM_BYTES);

    // Order keeps gemm1k as the 4th launch (the one ncu captures).
    convw_kernel<<<(CI * CIN) / 256, 256>>>(conv5_w);
    build_table<<<2, 256>>>(boxes);
    pool_kernel<<<dim3(CIN / 32, B_ * T_), 288>>>(x);
    gemm1k<<<dim3(CI / 128, M1 / 128), 512, GSMEM_BYTES>>>();
    convrw_kernel<<<dim3(16, 16, 9), 256>>>(re_w);
    gemm2k<<<dim3(CI / 128, NROI / 128, NPART), 512, GSMEM_BYTES>>>();
    reduce_a<<<dim3(16, 4), 512>>>(re_b);
    reduce_b<<<16, 512>>>(cat, labels);
    small_mm2<<<dim3(48, 8), 256>>>(p_objf, oc1_w, oc1_b, p_h1, 32, 512,
                                    p_pooled, pr1_w, pr1_b, p_g1, 512);
    small_mm2<<<dim3(48, 5), 256>>>(p_h1, oc2_w, oc2_b, obj_cls, 32, 301,
                                    p_g1, pr2_w, pr2_b, cls_out, 174);
}

// round 10
// speedup vs baseline: 2.0553x; 1.0950x over previous
#include <cuda_runtime.h>
#include <cuda_fp16.h>
#include <cstdint>

// ---------------- problem constants ----------------
#define B_    16
#define T_    8
#define CIN   2048
#define CI    512
#define HF    14
#define HW    196
#define NROI  512
#define M1    4608          // NROI*9
#define KFEAT 4608          // CI*9
#define NPART 8             // split-K parts for gemm2

// ---------------- scratch (static device memory) ----------------
__device__ __half d_roisH[(size_t)M1 * CIN];
__device__ __half d_roisL[(size_t)M1 * CIN];
__device__ __half d_wH[(size_t)CI * CIN];
__device__ __half d_rwH[(size_t)CI * KFEAT];       // re_w transposed+permuted [n][bin*512+o]
__device__ __half d_featsH[(size_t)NROI * KFEAT];  // [roi][bin*512+o]
__device__ __half d_featsL[(size_t)NROI * KFEAT];
__device__ float d_regpart[(size_t)NPART * NROI * CI];
__device__ float d_snb[64 * CI];
__device__ float d_objf[32 * CI];
__device__ float d_pooled[16 * CI];
__device__ float d_h1[32 * CI];
__device__ float d_g1[16 * CI];
__device__ int2  d_tap[NROI * 9 * 16];   // {byte-offset into 197-float row, weight bits}

// ---------------- PTX helpers ----------------
__device__ __forceinline__ uint32_t sm_u32(const void* p) {
    return (uint32_t)__cvta_generic_to_shared(p);
}
__device__ __forceinline__ void cpa16(uint32_t dst, const void* src) {
    asm volatile("cp.async.cg.shared.global [%0], [%1], 16;\n" :: "r"(dst), "l"(src));
}
__device__ __forceinline__ void cpa_commit() {
    asm volatile("cp.async.commit_group;\n" ::: "memory");
}
__device__ __forceinline__ void cpa_wait3() {
    asm volatile("cp.async.wait_group 3;\n" ::: "memory");
}
__device__ __forceinline__ void ldsm4(uint32_t* r, uint32_t addr) {
    asm volatile("ldmatrix.sync.aligned.m8n8.x4.shared.b16 {%0,%1,%2,%3}, [%4];"
                 : "=r"(r[0]), "=r"(r[1]), "=r"(r[2]), "=r"(r[3]) : "r"(addr));
}
__device__ __forceinline__ void mma16816h(float* c, const uint32_t* a, uint32_t b0, uint32_t b1) {
    asm volatile("mma.sync.aligned.m16n8k16.row.col.f32.f16.f16.f32 "
                 "{%0,%1,%2,%3},{%4,%5,%6,%7},{%8,%9},{%0,%1,%2,%3};"
                 : "+f"(c[0]), "+f"(c[1]), "+f"(c[2]), "+f"(c[3])
                 : "r"(a[0]), "r"(a[1]), "r"(a[2]), "r"(a[3]), "r"(b0), "r"(b1));
}

// ============================================================
// K1: ROI-align tap table (byte offsets, weights folded w/ 0.25 mean)
// ============================================================
__global__ void build_table(const float* __restrict__ boxes) {
    int roi = blockIdx.x * blockDim.x + threadIdx.x;
    if (roi >= NROI) return;
    float cx = boxes[roi * 4 + 0], cy = boxes[roi * 4 + 1];
    float w  = boxes[roi * 4 + 2], h  = boxes[roi * 4 + 3];
    const float s = 14.0f / 224.0f;
    float x1 = (cx - 0.5f * w) * 224.0f * s;
    float y1 = (cy - 0.5f * h) * 224.0f * s;
    float x2 = (cx + 0.5f * w) * 224.0f * s;
    float y2 = (cy + 0.5f * h) * 224.0f * s;
    float rw = fmaxf(x2 - x1, 1.0f), rh = fmaxf(y2 - y1, 1.0f);
    float bw = rw / 3.0f, bh = rh / 3.0f;

    float ys[6], xs[6];
#pragma unroll
    for (int p = 0; p < 3; ++p)
#pragma unroll
        for (int i = 0; i < 2; ++i) {
            ys[p * 2 + i] = y1 + p * bh + (i + 0.5f) * bh * 0.5f;
            xs[p * 2 + i] = x1 + p * bw + (i + 0.5f) * bw * 0.5f;
        }

#pragma unroll
    for (int ph = 0; ph < 3; ++ph)
#pragma unroll
        for (int pw = 0; pw < 3; ++pw) {
            int bin = ph * 3 + pw;
#pragma unroll
            for (int iy = 0; iy < 2; ++iy)
#pragma unroll
                for (int ix = 0; ix < 2; ++ix) {
                    int smp = iy * 2 + ix;
                    float yy = ys[ph * 2 + iy];
                    float xx = xs[pw * 2 + ix];
                    bool valid = (yy > -1.0f) && (yy < 14.0f) && (xx > -1.0f) && (xx < 14.0f);
                    float y = fminf(fmaxf(yy, 0.0f), 13.0f);
                    float x = fminf(fmaxf(xx, 0.0f), 13.0f);
                    int y0 = (int)floorf(y), x0 = (int)floorf(x);
                    int y1i = min(y0 + 1, 13), x1i = min(x0 + 1, 13);
                    float ly = y - (float)y0, lx = x - (float)x0;
                    float hy = 1.0f - ly, hx = 1.0f - lx;
                    float q = valid ? 0.25f : 0.0f;
                    int base = (roi * 9 + bin) * 16 + smp * 4;
                    d_tap[base + 0] = make_int2((y0 * HF + x0) * 4,   __float_as_int(hy * hx * q));
                    d_tap[base + 1] = make_int2((y0 * HF + x1i) * 4,  __float_as_int(hy * lx * q));
                    d_tap[base + 2] = make_int2((y1i * HF + x0) * 4,  __float_as_int(ly * hx * q));
                    d_tap[base + 3] = make_int2((y1i * HF + x1i) * 4, __float_as_int(ly * lx * q));
                }
        }
}

// ============================================================
// K2: pooling in 2048-ch space -> fp16 hi/lo (R4 proven shape)
// ============================================================
__global__ __launch_bounds__(288) void pool_kernel(const float* __restrict__ x) {
    __shared__ float pl[32][197];
    __shared__ int2  taps[576];
    int bt = blockIdx.y;
    int c0 = blockIdx.x * 32;
    int tid = threadIdx.x, lane = tid & 31, wid = tid >> 5;

    size_t base = ((size_t)(bt >> 3) * CIN + c0) * (size_t)(T_ * HW) + (size_t)(bt & 7) * HW;
    for (int c = wid; c < 32; c += 9) {
        const float4* src = (const float4*)(x + base + (size_t)c * (T_ * HW));
        for (int p = lane; p < 49; p += 32) {
            float4 v = src[p];
            pl[c][p * 4 + 0] = v.x; pl[c][p * 4 + 1] = v.y;
            pl[c][p * 4 + 2] = v.z; pl[c][p * 4 + 3] = v.w;
        }
    }
    for (int i = tid; i < 576; i += 288) taps[i] = d_tap[bt * 576 + i];
    __syncthreads();

    const char* bp = (const char*)&pl[lane][0];
#pragma unroll
    for (int j = 0; j < 4; ++j) {
        int e = wid + 9 * j;
        const int2* tp = &taps[e * 16];
        float a = 0.0f;
#pragma unroll
        for (int t = 0; t < 16; ++t) {
            int2 pw = tp[t];
            a += __int_as_float(pw.y) * *(const float*)(bp + pw.x);
        }
        size_t off = (size_t)(bt * 36 + e) * CIN + c0 + lane;
        __half hb = __float2half_rn(a);
        d_roisH[off] = hb;
        d_roisL[off] = __float2half_rn(a - __half2float(hb));
    }
}

// ============================================================
// K3a: convert conv5_w -> fp16 (hi only; B-side single precision pass)
// ============================================================
__global__ void convw_kernel(const float* __restrict__ w) {
    int i = blockIdx.x * 256 + threadIdx.x;
    d_wH[i] = __float2half_rn(w[i]);
}

// ============================================================
// K3b: convert re_w -> transposed+permuted fp16 (hi only)
// ============================================================
__global__ __launch_bounds__(256) void convrw_kernel(const float* __restrict__ w) {
    __shared__ float t[32][33];
    int o0 = blockIdx.x * 32, n0 = blockIdx.y * 32, bin = blockIdx.z;
    int tx = threadIdx.x & 31, ty = threadIdx.x >> 5;
    for (int r = ty; r < 32; r += 8)
        t[r][tx] = w[((size_t)((o0 + r) * 9 + bin)) * 512 + n0 + tx];
    __syncthreads();
    for (int r = ty; r < 32; r += 8) {
        size_t off = (size_t)(n0 + r) * KFEAT + bin * 512 + o0 + tx;
        d_rwH[off] = __float2half_rn(t[tx][r]);
    }
}

// ============================================================
// GEMM core: 128x128 tile, 512 threads (16 warps, warp tile 32x32),
// fp16 2-pass split (Ah*Bh + Al*Bh), 5-stage cp.async,
// 3 tiles/stage (Ah, Al, Bh)
// ============================================================
#define KT     32
#define SROW   40
#define TILE_E (128 * SROW)
#define STAGE_E (3 * TILE_E)
#define NSTAGE 5
#define GSMEM_BYTES (NSTAGE * STAGE_E * 2)

__device__ __forceinline__ void gemm_core(
    const __half* __restrict__ gAh, const __half* __restrict__ gAl, int lda,
    const __half* __restrict__ gBh, int ldb,
    int bm, int bn, int kbase, int niter,
    __half* sm, float (&acc)[2][4][4])
{
    int tid = threadIdx.x, lane = tid & 31, wid = tid >> 5;
    int wm = wid >> 2, wn = wid & 3;     // 4x4 warp grid, warp tile 32x32

    auto ldg = [&](int t) {
        int s = t % NSTAGE;
        int k0 = kbase + t * KT;
        __half* base = sm + s * STAGE_E;
        int row = tid >> 2, c = tid & 3;   // 512 threads = 128 rows x 4 chunks
        __half* pd = base + row * SROW + c * 8;
        cpa16(sm_u32(pd),              gAh + (size_t)(bm + row) * lda + k0 + c * 8);
        cpa16(sm_u32(pd + TILE_E),     gAl + (size_t)(bm + row) * lda + k0 + c * 8);
        cpa16(sm_u32(pd + 2 * TILE_E), gBh + (size_t)(bn + row) * ldb + k0 + c * 8);
    };

    int ar  = wm * 32 + (lane & 15);
    int ac8 = (lane >> 4) * 8;
    int br  = wn * 32 + (lane & 7) + ((lane >> 4) << 3);
    int bc8 = ((lane >> 3) & 1) * 8;

    // prologue: exactly 4 committed groups (pad with empty if short)
#pragma unroll
    for (int s = 0; s < 4; ++s) {
        if (s < niter) ldg(s);
        cpa_commit();
    }

#pragma unroll 1
    for (int t = 0; t < niter; ++t) {
        cpa_wait3();            // stage t guaranteed complete
        __syncthreads();        // all warps done reading stage (t-1)%NSTAGE
        if (t + 4 < niter) ldg(t + 4);
        cpa_commit();           // empty at tail -> uniform pending count

        __half* base = sm + (t % NSTAGE) * STAGE_E;
        const __half* pAh = base;
        const __half* pAl = base + TILE_E;
        const __half* pBh = base + 2 * TILE_E;

        // all fragments for both ks slices up-front (12 ldsm)
        uint32_t ah[2][2][4], al[2][2][4], bh[2][2][4];
#pragma unroll
        for (int ks = 0; ks < 2; ++ks) {
#pragma unroll
            for (int mt = 0; mt < 2; ++mt) {
                ldsm4(ah[ks][mt], sm_u32(pAh + (ar + mt * 16) * SROW + ks * 16 + ac8));
                ldsm4(al[ks][mt], sm_u32(pAl + (ar + mt * 16) * SROW + ks * 16 + ac8));
            }
#pragma unroll
            for (int bt2 = 0; bt2 < 2; ++bt2)
                ldsm4(bh[ks][bt2], sm_u32(pBh + (br + bt2 * 16) * SROW + ks * 16 + bc8));
        }
        // pass 1: Ah*Bh (16 independent MMAs)
#pragma unroll
        for (int ks = 0; ks < 2; ++ks)
#pragma unroll
            for (int mt = 0; mt < 2; ++mt)
#pragma unroll
                for (int nt = 0; nt < 4; ++nt)
                    mma16816h(acc[mt][nt], ah[ks][mt],
                              bh[ks][nt >> 1][(nt & 1) * 2], bh[ks][nt >> 1][(nt & 1) * 2 + 1]);
        // pass 2: Al*Bh
#pragma unroll
        for (int ks = 0; ks < 2; ++ks)
#pragma unroll
            for (int mt = 0; mt < 2; ++mt)
#pragma unroll
                for (int nt = 0; nt < 4; ++nt)
                    mma16816h(acc[mt][nt], al[ks][mt],
                              bh[ks][nt >> 1][(nt & 1) * 2], bh[ks][nt >> 1][(nt & 1) * 2 + 1]);
    }
}

// ============================================================
// K4: GEMM1: feats = rois2048[4608,2048] x conv5_w[512,2048]^T
// ============================================================
__global__ __launch_bounds__(512) void gemm1k() {
    extern __shared__ __half sm[];
    int bm = blockIdx.y * 128, bn = blockIdx.x * 128;
    float acc[2][4][4];
#pragma unroll
    for (int a = 0; a < 2; ++a)
#pragma unroll
        for (int b = 0; b < 4; ++b)
#pragma unroll
            for (int c = 0; c < 4; ++c) acc[a][b][c] = 0.0f;

    gemm_core(d_roisH, d_roisL, CIN, d_wH, CIN, bm, bn, 0, CIN / KT, sm, acc);

    int lane = threadIdx.x & 31, wid = threadIdx.x >> 5;
    int wm = wid >> 2, wn = wid & 3;
    int mrow = wm * 32 + (lane >> 2);
    int ncol = wn * 32 + ((lane & 3) << 1);
#pragma unroll
    for (int mt = 0; mt < 2; ++mt)
#pragma unroll
        for (int nt = 0; nt < 4; ++nt) {
            float* c = acc[mt][nt];
            int n = bn + ncol + nt * 8;
#pragma unroll
            for (int half = 0; half < 2; ++half) {
                int m = bm + mrow + mt * 16 + half * 8;
                int roi = m / 9, bin = m - roi * 9;
                size_t off = (size_t)roi * KFEAT + bin * 512 + n;
                float v0 = c[half * 2 + 0], v1 = c[half * 2 + 1];
                __half h0 = __float2half_rn(v0);
                __half h1 = __float2half_rn(v1);
                __half2 hp; hp.x = h0; hp.y = h1;
                __half2 lp;
                lp.x = __float2half_rn(v0 - __half2float(h0));
                lp.y = __float2half_rn(v1 - __half2float(h1));
                *(__half2*)&d_featsH[off] = hp;
                *(__half2*)&d_featsL[off] = lp;
            }
        }
}

// ============================================================
// K5: GEMM2 (split-K=8): regpart = feats[512,4608] x rw[512,4608]^T
// ============================================================
__global__ __launch_bounds__(512) void gemm2k() {
    extern __shared__ __half sm[];
    int bm = blockIdx.y * 128, bn = blockIdx.x * 128;
    int part = blockIdx.z;
    float acc[2][4][4];
#pragma unroll
    for (int a = 0; a < 2; ++a)
#pragma unroll
        for (int b = 0; b < 4; ++b)
#pragma unroll
            for (int c = 0; c < 4; ++c) acc[a][b][c] = 0.0f;

    gemm_core(d_featsH, d_featsL, KFEAT, d_rwH, KFEAT,
              bm, bn, part * (KFEAT / NPART), (KFEAT / NPART) / KT, sm, acc);

    int lane = threadIdx.x & 31, wid = threadIdx.x >> 5;
    int wm = wid >> 2, wn = wid & 3;
    int mrow = wm * 32 + (lane >> 2);
    int ncol = wn * 32 + ((lane & 3) << 1);
    float* C = d_regpart + (size_t)part * NROI * CI;
#pragma unroll
    for (int mt = 0; mt < 2; ++mt)
#pragma unroll
        for (int nt = 0; nt < 4; ++nt) {
            float* c = acc[mt][nt];
            int n = bn + ncol + nt * 8;
#pragma unroll
            for (int half = 0; half < 2; ++half) {
                int m = bm + mrow + mt * 16 + half * 8;
                *(float2*)&C[(size_t)m * CI + n] = make_float2(c[half * 2], c[half * 2 + 1]);
            }
        }
}

// ============================================================
// K6a: per-(b,nb): s = 0.125 * sum_t relu(bias + sum_p parts)
// ============================================================
__global__ void reduce_a(const float* __restrict__ re_b) {
    int b = blockIdx.x, nb = blockIdx.y, j = threadIdx.x;
    float bias = re_b[j];
    float s = 0.0f;
#pragma unroll
    for (int t = 0; t < 8; ++t) {
        int r = (b * 8 + t) * 4 + nb;
        float v = bias;
#pragma unroll
        for (int p = 0; p < NPART; ++p)
            v += d_regpart[(size_t)p * NROI * CI + (size_t)r * CI + j];
        s += fmaxf(v, 0.0f);
    }
    s *= 0.125f;
    d_snb[(b * 4 + nb) * CI + j] = s;
    if (nb >= 2) d_objf[(b * 2 + nb - 2) * CI + j] = s;   // argsort identity: cats never 0
}

// ============================================================
// K6b: pooled = mean over nb; labels
// ============================================================
__global__ void reduce_b(const int* __restrict__ cat, float* __restrict__ out_labels) {
    int b = blockIdx.x, j = threadIdx.x;
    float p = 0.25f * (d_snb[(b * 4 + 0) * CI + j] + d_snb[(b * 4 + 1) * CI + j] +
                       d_snb[(b * 4 + 2) * CI + j] + d_snb[(b * 4 + 3) * CI + j]);
    d_pooled[b * CI + j] = p;
    if (j < 2) out_labels[b * 2 + j] = (float)cat[b * 4 + 2 + j];
}

// ============================================================
// K7: fused small dense heads (two independent GEMMs per stage)
// ============================================================
__global__ __launch_bounds__(256) void small_mm2(
    const float* __restrict__ A0, const float* __restrict__ B0,
    const float* __restrict__ bias0, float* __restrict__ C0, int rows0, int N0,
    const float* __restrict__ A1, const float* __restrict__ B1,
    const float* __restrict__ bias1, float* __restrict__ C1, int N1)
{
    __shared__ float As[512];
    __shared__ float red[256];
    const float *A, *Bm, *bias; float* C; int m, N;
    if ((int)blockIdx.x < rows0) { A = A0; Bm = B0; bias = bias0; C = C0; m = blockIdx.x; N = N0; }
    else { A = A1; Bm = B1; bias = bias1; C = C1; m = blockIdx.x - rows0; N = N1; }
    int j0 = blockIdx.y * 64;
    if (j0 >= N) return;
    int tid = threadIdx.x, jl = tid & 63, ks = tid >> 6;
    for (int k = tid; k < 512; k += 256) As[k] = A[m * 512 + k];
    __syncthreads();
    int j = j0 + jl;
    float acc = 0.0f;
    if (j < N) {
        int k0 = ks * 128;
#pragma unroll 8
        for (int k = k0; k < k0 + 128; ++k) acc += As[k] * Bm[k * N + j];
    }
    red[tid] = acc;
    __syncthreads();
    if (tid < 64 && j < N)
        C[m * N + j] = red[tid] + red[tid + 64] + red[tid + 128] + red[tid + 192] + bias[j];
}

// ============================================================
extern "C" void kernel_launch(void* const* d_in, const int* in_sizes, int n_in,
                              void* d_out, int out_size) {
    const float* x       = (const float*)d_in[0];
    const float* boxes   = (const float*)d_in[1];
    const int*   cat     = (const int*)d_in[2];
    const float* conv5_w = (const float*)d_in[3];
    const float* re_w    = (const float*)d_in[4];
    const float* re_b    = (const float*)d_in[5];
    const float* oc1_w   = (const float*)d_in[6];
    const float* oc1_b   = (const float*)d_in[7];
    const float* oc2_w   = (const float*)d_in[8];
    const float* oc2_b   = (const float*)d_in[9];
    const float* pr1_w   = (const float*)d_in[10];
    const float* pr1_b   = (const float*)d_in[11];
    const float* pr2_w   = (const float*)d_in[12];
    const float* pr2_b   = (const float*)d_in[13];

    float* out     = (float*)d_out;
    float* cls_out = out;                       // 16*174
    float* obj_cls = out + 16 * 174;            // 32*301
    float* labels  = out + 16 * 174 + 32 * 301; // 32

    float *p_objf, *p_pooled, *p_h1, *p_g1;
    cudaGetSymbolAddress((void**)&p_objf,   d_objf);
    cudaGetSymbolAddress((void**)&p_pooled, d_pooled);
    cudaGetSymbolAddress((void**)&p_h1,     d_h1);
    cudaGetSymbolAddress((void**)&p_g1,     d_g1);

    cudaFuncSetAttribute(gemm1k, cudaFuncAttributeMaxDynamicSharedMemorySize, GSMEM_BYTES);
    cudaFuncSetAttribute(gemm2k, cudaFuncAttributeMaxDynamicSharedMemorySize, GSMEM_BYTES);

    // Order keeps gemm1k as the 4th launch (the one ncu captures).
    convw_kernel<<<(CI * CIN) / 256, 256>>>(conv5_w);
    build_table<<<2, 256>>>(boxes);
    pool_kernel<<<dim3(CIN / 32, B_ * T_), 288>>>(x);
    gemm1k<<<dim3(CI / 128, M1 / 128), 512, GSMEM_BYTES>>>();
    convrw_kernel<<<dim3(16, 16, 9), 256>>>(re_w);
    gemm2k<<<dim3(CI / 128, NROI / 128, NPART), 512, GSMEM_BYTES>>>();
    reduce_a<<<dim3(16, 4), 512>>>(re_b);
    reduce_b<<<16, 512>>>(cat, labels);
    small_mm2<<<dim3(48, 8), 256>>>(p_objf, oc1_w, oc1_b, p_h1, 32, 512,
                                    p_pooled, pr1_w, pr1_b, p_g1, 512);
    small_mm2<<<dim3(48, 5), 256>>>(p_h1, oc2_w, oc2_b, obj_cls, 32, 301,
                                    p_g1, pr2_w, pr2_b, cls_out, 174);
}

// round 12
// speedup vs baseline: 2.1733x; 1.0574x over previous
#include <cuda_runtime.h>
#include <cuda_fp16.h>
#include <cstdint>

// ---------------- problem constants ----------------
#define B_    16
#define T_    8
#define CIN   2048
#define CI    512
#define HF    14
#define HW    196
#define NROI  512
#define M1    4608          // NROI*9
#define KFEAT 4608          // CI*9
#define NPART 8             // split-K parts for gemm2

// ---------------- scratch (static device memory) ----------------
__device__ __half d_roisH[(size_t)M1 * CIN];
__device__ __half d_roisL[(size_t)M1 * CIN];
__device__ __half d_wH[(size_t)CI * CIN];
__device__ __half d_rwH[(size_t)CI * KFEAT];       // re_w transposed+permuted [n][bin*512+o]
__device__ __half d_featsH[(size_t)NROI * KFEAT];  // [roi][bin*512+o]
__device__ __half d_featsL[(size_t)NROI * KFEAT];
__device__ float d_regpart[(size_t)NPART * NROI * CI];
__device__ float d_snb[64 * CI];
__device__ float d_objf[32 * CI];
__device__ float d_pooled[16 * CI];
__device__ float d_h1[32 * CI];
__device__ float d_g1[16 * CI];
__device__ int2  d_tap[NROI * 9 * 16];   // {byte-offset into 197-float row, weight bits}

// ---------------- PTX helpers ----------------
__device__ __forceinline__ uint32_t sm_u32(const void* p) {
    return (uint32_t)__cvta_generic_to_shared(p);
}
__device__ __forceinline__ void cpa16(uint32_t dst, const void* src) {
    asm volatile("cp.async.cg.shared.global [%0], [%1], 16;\n" :: "r"(dst), "l"(src));
}
__device__ __forceinline__ void cpa_commit() {
    asm volatile("cp.async.commit_group;\n" ::: "memory");
}
__device__ __forceinline__ void cpa_wait3() {
    asm volatile("cp.async.wait_group 3;\n" ::: "memory");
}
__device__ __forceinline__ void ldsm4(uint32_t* r, uint32_t addr) {
    asm volatile("ldmatrix.sync.aligned.m8n8.x4.shared.b16 {%0,%1,%2,%3}, [%4];"
                 : "=r"(r[0]), "=r"(r[1]), "=r"(r[2]), "=r"(r[3]) : "r"(addr));
}
__device__ __forceinline__ void mma16816h(float* c, const uint32_t* a, uint32_t b0, uint32_t b1) {
    asm volatile("mma.sync.aligned.m16n8k16.row.col.f32.f16.f16.f32 "
                 "{%0,%1,%2,%3},{%4,%5,%6,%7},{%8,%9},{%0,%1,%2,%3};"
                 : "+f"(c[0]), "+f"(c[1]), "+f"(c[2]), "+f"(c[3])
                 : "r"(a[0]), "r"(a[1]), "r"(a[2]), "r"(a[3]), "r"(b0), "r"(b1));
}

// ============================================================
// K1: ROI-align tap table (byte offsets, weights folded w/ 0.25 mean)
// ============================================================
__global__ void build_table(const float* __restrict__ boxes) {
    int roi = blockIdx.x * blockDim.x + threadIdx.x;
    if (roi >= NROI) return;
    float cx = boxes[roi * 4 + 0], cy = boxes[roi * 4 + 1];
    float w  = boxes[roi * 4 + 2], h  = boxes[roi * 4 + 3];
    const float s = 14.0f / 224.0f;
    float x1 = (cx - 0.5f * w) * 224.0f * s;
    float y1 = (cy - 0.5f * h) * 224.0f * s;
    float x2 = (cx + 0.5f * w) * 224.0f * s;
    float y2 = (cy + 0.5f * h) * 224.0f * s;
    float rw = fmaxf(x2 - x1, 1.0f), rh = fmaxf(y2 - y1, 1.0f);
    float bw = rw / 3.0f, bh = rh / 3.0f;

    float ys[6], xs[6];
#pragma unroll
    for (int p = 0; p < 3; ++p)
#pragma unroll
        for (int i = 0; i < 2; ++i) {
            ys[p * 2 + i] = y1 + p * bh + (i + 0.5f) * bh * 0.5f;
            xs[p * 2 + i] = x1 + p * bw + (i + 0.5f) * bw * 0.5f;
        }

#pragma unroll
    for (int ph = 0; ph < 3; ++ph)
#pragma unroll
        for (int pw = 0; pw < 3; ++pw) {
            int bin = ph * 3 + pw;
#pragma unroll
            for (int iy = 0; iy < 2; ++iy)
#pragma unroll
                for (int ix = 0; ix < 2; ++ix) {
                    int smp = iy * 2 + ix;
                    float yy = ys[ph * 2 + iy];
                    float xx = xs[pw * 2 + ix];
                    bool valid = (yy > -1.0f) && (yy < 14.0f) && (xx > -1.0f) && (xx < 14.0f);
                    float y = fminf(fmaxf(yy, 0.0f), 13.0f);
                    float x = fminf(fmaxf(xx, 0.0f), 13.0f);
                    int y0 = (int)floorf(y), x0 = (int)floorf(x);
                    int y1i = min(y0 + 1, 13), x1i = min(x0 + 1, 13);
                    float ly = y - (float)y0, lx = x - (float)x0;
                    float hy = 1.0f - ly, hx = 1.0f - lx;
                    float q = valid ? 0.25f : 0.0f;
                    int base = (roi * 9 + bin) * 16 + smp * 4;
                    d_tap[base + 0] = make_int2((y0 * HF + x0) * 4,   __float_as_int(hy * hx * q));
                    d_tap[base + 1] = make_int2((y0 * HF + x1i) * 4,  __float_as_int(hy * lx * q));
                    d_tap[base + 2] = make_int2((y1i * HF + x0) * 4,  __float_as_int(ly * hx * q));
                    d_tap[base + 3] = make_int2((y1i * HF + x1i) * 4, __float_as_int(ly * lx * q));
                }
        }
}

// ============================================================
// K2: pooling in 2048-ch space -> fp16 hi/lo
// v2: 4 chunks of 32 channels per block, 2 smem buffers (DYNAMIC smem),
// register-staged LDG double-buffering (overlap DRAM with gather)
// ============================================================
#define PCHUNKS 4
#define PLDG    6    // ceil(1568/288) float4 loads per thread per chunk
#define PBUF_E  (32 * 197)
#define POOL_SMEM (2 * PBUF_E * 4 + 576 * 8)   // 55040 B -> dynamic
__global__ __launch_bounds__(288) void pool_kernel(const float* __restrict__ x) {
    extern __shared__ float psm[];
    float* pl0 = psm;                       // [32][197]
    float* pl1 = psm + PBUF_E;              // [32][197]
    int2*  taps = (int2*)(psm + 2 * PBUF_E);

    int bt = blockIdx.y;
    int tid = threadIdx.x, lane = tid & 31, wid = tid >> 5;
    int cbase = blockIdx.x * (32 * PCHUNKS);

    // x layout (B, C, T, H, W); plane = 196 contiguous floats, 16B-aligned
    size_t xbase = ((size_t)(bt >> 3) * CIN + cbase) * (size_t)(T_ * HW) + (size_t)(bt & 7) * HW;

    for (int i = tid; i < 576; i += 288) taps[i] = d_tap[bt * 576 + i];

    float4 v[PLDG];
    auto ldgc = [&](int c) {
#pragma unroll
        for (int q = 0; q < PLDG; ++q) {
            int i = tid + q * 288;
            if (i < 1568) {
                int ch = i / 49, p = i - ch * 49;
                v[q] = *(const float4*)(x + xbase + (size_t)(c * 32 + ch) * (T_ * HW) + p * 4);
            }
        }
    };
    auto stsc = [&](float* buf) {
#pragma unroll
        for (int q = 0; q < PLDG; ++q) {
            int i = tid + q * 288;
            if (i < 1568) {
                int ch = i / 49, p = i - ch * 49;
                float* d = buf + ch * 197 + p * 4;
                d[0] = v[q].x; d[1] = v[q].y; d[2] = v[q].z; d[3] = v[q].w;
            }
        }
    };

    ldgc(0);
    stsc(pl0);
    __syncthreads();     // covers taps + buf0

#pragma unroll
    for (int c = 0; c < PCHUNKS; ++c) {
        if (c + 1 < PCHUNKS) ldgc(c + 1);          // DRAM overlapped with compute

        const char* bp = (const char*)((c & 1) ? (pl1 + lane * 197) : (pl0 + lane * 197));
#pragma unroll
        for (int j = 0; j < 4; ++j) {
            int e = wid + 9 * j;                   // nb*9+bin
            const int2* tp = &taps[e * 16];
            float a = 0.0f;
#pragma unroll
            for (int t = 0; t < 16; ++t) {
                int2 pw = tp[t];                   // broadcast LDS.64
                a += __int_as_float(pw.y) * *(const float*)(bp + pw.x);
            }
            size_t off = (size_t)(bt * 36 + e) * CIN + cbase + c * 32 + lane;
            __half hb = __float2half_rn(a);
            d_roisH[off] = hb;
            d_roisL[off] = __float2half_rn(a - __half2float(hb));
        }

        if (c + 1 < PCHUNKS) {
            stsc(((c + 1) & 1) ? pl1 : pl0);       // writes other buffer: no WAR
            __syncthreads();                       // visible before next compute
        }
    }
}

// ============================================================
// K3a: convert conv5_w -> fp16 (hi only; B-side single precision pass)
// ============================================================
__global__ void convw_kernel(const float* __restrict__ w) {
    int i = blockIdx.x * 256 + threadIdx.x;
    d_wH[i] = __float2half_rn(w[i]);
}

// ============================================================
// K3b: convert re_w -> transposed+permuted fp16 (hi only)
// ============================================================
__global__ __launch_bounds__(256) void convrw_kernel(const float* __restrict__ w) {
    __shared__ float t[32][33];
    int o0 = blockIdx.x * 32, n0 = blockIdx.y * 32, bin = blockIdx.z;
    int tx = threadIdx.x & 31, ty = threadIdx.x >> 5;
    for (int r = ty; r < 32; r += 8)
        t[r][tx] = w[((size_t)((o0 + r) * 9 + bin)) * 512 + n0 + tx];
    __syncthreads();
    for (int r = ty; r < 32; r += 8) {
        size_t off = (size_t)(n0 + r) * KFEAT + bin * 512 + o0 + tx;
        d_rwH[off] = __float2half_rn(t[tx][r]);
    }
}

// ============================================================
// GEMM core: 128x128 tile, 512 threads (16 warps, warp tile 32x32),
// fp16 2-pass split (Ah*Bh + Al*Bh), 5-stage cp.async,
// 3 tiles/stage (Ah, Al, Bh)
// ============================================================
#define KT     32
#define SROW   40
#define TILE_E (128 * SROW)
#define STAGE_E (3 * TILE_E)
#define NSTAGE 5
#define GSMEM_BYTES (NSTAGE * STAGE_E * 2)

__device__ __forceinline__ void gemm_core(
    const __half* __restrict__ gAh, const __half* __restrict__ gAl, int lda,
    const __half* __restrict__ gBh, int ldb,
    int bm, int bn, int kbase, int niter,
    __half* sm, float (&acc)[2][4][4])
{
    int tid = threadIdx.x, lane = tid & 31, wid = tid >> 5;
    int wm = wid >> 2, wn = wid & 3;     // 4x4 warp grid, warp tile 32x32

    auto ldg = [&](int t) {
        int s = t % NSTAGE;
        int k0 = kbase + t * KT;
        __half* base = sm + s * STAGE_E;
        int row = tid >> 2, c = tid & 3;   // 512 threads = 128 rows x 4 chunks
        __half* pd = base + row * SROW + c * 8;
        cpa16(sm_u32(pd),              gAh + (size_t)(bm + row) * lda + k0 + c * 8);
        cpa16(sm_u32(pd + TILE_E),     gAl + (size_t)(bm + row) * lda + k0 + c * 8);
        cpa16(sm_u32(pd + 2 * TILE_E), gBh + (size_t)(bn + row) * ldb + k0 + c * 8);
    };

    int ar  = wm * 32 + (lane & 15);
    int ac8 = (lane >> 4) * 8;
    int br  = wn * 32 + (lane & 7) + ((lane >> 4) << 3);
    int bc8 = ((lane >> 3) & 1) * 8;

    // prologue: exactly 4 committed groups (pad with empty if short)
#pragma unroll
    for (int s = 0; s < 4; ++s) {
        if (s < niter) ldg(s);
        cpa_commit();
    }

#pragma unroll 1
    for (int t = 0; t < niter; ++t) {
        cpa_wait3();            // stage t guaranteed complete
        __syncthreads();        // all warps done reading stage (t-1)%NSTAGE
        if (t + 4 < niter) ldg(t + 4);
        cpa_commit();           // empty at tail -> uniform pending count

        __half* base = sm + (t % NSTAGE) * STAGE_E;
        const __half* pAh = base;
        const __half* pAl = base + TILE_E;
        const __half* pBh = base + 2 * TILE_E;

        // all fragments for both ks slices up-front (12 ldsm)
        uint32_t ah[2][2][4], al[2][2][4], bh[2][2][4];
#pragma unroll
        for (int ks = 0; ks < 2; ++ks) {
#pragma unroll
            for (int mt = 0; mt < 2; ++mt) {
                ldsm4(ah[ks][mt], sm_u32(pAh + (ar + mt * 16) * SROW + ks * 16 + ac8));
                ldsm4(al[ks][mt], sm_u32(pAl + (ar + mt * 16) * SROW + ks * 16 + ac8));
            }
#pragma unroll
            for (int bt2 = 0; bt2 < 2; ++bt2)
                ldsm4(bh[ks][bt2], sm_u32(pBh + (br + bt2 * 16) * SROW + ks * 16 + bc8));
        }
        // pass 1: Ah*Bh (16 independent MMAs)
#pragma unroll
        for (int ks = 0; ks < 2; ++ks)
#pragma unroll
            for (int mt = 0; mt < 2; ++mt)
#pragma unroll
                for (int nt = 0; nt < 4; ++nt)
                    mma16816h(acc[mt][nt], ah[ks][mt],
                              bh[ks][nt >> 1][(nt & 1) * 2], bh[ks][nt >> 1][(nt & 1) * 2 + 1]);
        // pass 2: Al*Bh
#pragma unroll
        for (int ks = 0; ks < 2; ++ks)
#pragma unroll
            for (int mt = 0; mt < 2; ++mt)
#pragma unroll
                for (int nt = 0; nt < 4; ++nt)
                    mma16816h(acc[mt][nt], al[ks][mt],
                              bh[ks][nt >> 1][(nt & 1) * 2], bh[ks][nt >> 1][(nt & 1) * 2 + 1]);
    }
}

// ============================================================
// K4: GEMM1: feats = rois2048[4608,2048] x conv5_w[512,2048]^T
// ============================================================
__global__ __launch_bounds__(512) void gemm1k() {
    extern __shared__ __half sm[];
    int bm = blockIdx.y * 128, bn = blockIdx.x * 128;
    float acc[2][4][4];
#pragma unroll
    for (int a = 0; a < 2; ++a)
#pragma unroll
        for (int b = 0; b < 4; ++b)
#pragma unroll
            for (int c = 0; c < 4; ++c) acc[a][b][c] = 0.0f;

    gemm_core(d_roisH, d_roisL, CIN, d_wH, CIN, bm, bn, 0, CIN / KT, sm, acc);

    int lane = threadIdx.x & 31, wid = threadIdx.x >> 5;
    int wm = wid >> 2, wn = wid & 3;
    int mrow = wm * 32 + (lane >> 2);
    int ncol = wn * 32 + ((lane & 3) << 1);
#pragma unroll
    for (int mt = 0; mt < 2; ++mt)
#pragma unroll
        for (int nt = 0; nt < 4; ++nt) {
            float* c = acc[mt][nt];
            int n = bn + ncol + nt * 8;
#pragma unroll
            for (int half = 0; half < 2; ++half) {
                int m = bm + mrow + mt * 16 + half * 8;
                int roi = m / 9, bin = m - roi * 9;
                size_t off = (size_t)roi * KFEAT + bin * 512 + n;
                float v0 = c[half * 2 + 0], v1 = c[half * 2 + 1];
                __half h0 = __float2half_rn(v0);
                __half h1 = __float2half_rn(v1);
                __half2 hp; hp.x = h0; hp.y = h1;
                __half2 lp;
                lp.x = __float2half_rn(v0 - __half2float(h0));
                lp.y = __float2half_rn(v1 - __half2float(h1));
                *(__half2*)&d_featsH[off] = hp;
                *(__half2*)&d_featsL[off] = lp;
            }
        }
}

// ============================================================
// K5: GEMM2 (split-K=8): regpart = feats[512,4608] x rw[512,4608]^T
// ============================================================
__global__ __launch_bounds__(512) void gemm2k() {
    extern __shared__ __half sm[];
    int bm = blockIdx.y * 128, bn = blockIdx.x * 128;
    int part = blockIdx.z;
    float acc[2][4][4];
#pragma unroll
    for (int a = 0; a < 2; ++a)
#pragma unroll
        for (int b = 0; b < 4; ++b)
#pragma unroll
            for (int c = 0; c < 4; ++c) acc[a][b][c] = 0.0f;

    gemm_core(d_featsH, d_featsL, KFEAT, d_rwH, KFEAT,
              bm, bn, part * (KFEAT / NPART), (KFEAT / NPART) / KT, sm, acc);

    int lane = threadIdx.x & 31, wid = threadIdx.x >> 5;
    int wm = wid >> 2, wn = wid & 3;
    int mrow = wm * 32 + (lane >> 2);
    int ncol = wn * 32 + ((lane & 3) << 1);
    float* C = d_regpart + (size_t)part * NROI * CI;
#pragma unroll
    for (int mt = 0; mt < 2; ++mt)
#pragma unroll
        for (int nt = 0; nt < 4; ++nt) {
            float* c = acc[mt][nt];
            int n = bn + ncol + nt * 8;
#pragma unroll
            for (int half = 0; half < 2; ++half) {
                int m = bm + mrow + mt * 16 + half * 8;
                *(float2*)&C[(size_t)m * CI + n] = make_float2(c[half * 2], c[half * 2 + 1]);
            }
        }
}

// ============================================================
// K6a: per-(b,nb): s = 0.125 * sum_t relu(bias + sum_p parts)
// ============================================================
__global__ void reduce_a(const float* __restrict__ re_b) {
    int b = blockIdx.x, nb = blockIdx.y, j = threadIdx.x;
    float bias = re_b[j];
    float s = 0.0f;
#pragma unroll
    for (int t = 0; t < 8; ++t) {
        int r = (b * 8 + t) * 4 + nb;
        float v = bias;
#pragma unroll
        for (int p = 0; p < NPART; ++p)
            v += d_regpart[(size_t)p * NROI * CI + (size_t)r * CI + j];
        s += fmaxf(v, 0.0f);
    }
    s *= 0.125f;
    d_snb[(b * 4 + nb) * CI + j] = s;
    if (nb >= 2) d_objf[(b * 2 + nb - 2) * CI + j] = s;   // argsort identity: cats never 0
}

// ============================================================
// K6b: pooled = mean over nb; labels
// ============================================================
__global__ void reduce_b(const int* __restrict__ cat, float* __restrict__ out_labels) {
    int b = blockIdx.x, j = threadIdx.x;
    float p = 0.25f * (d_snb[(b * 4 + 0) * CI + j] + d_snb[(b * 4 + 1) * CI + j] +
                       d_snb[(b * 4 + 2) * CI + j] + d_snb[(b * 4 + 3) * CI + j]);
    d_pooled[b * CI + j] = p;
    if (j < 2) out_labels[b * 2 + j] = (float)cat[b * 4 + 2 + j];
}

// ============================================================
// K7: fused small dense heads (two independent GEMMs per stage)
// ============================================================
__global__ __launch_bounds__(256) void small_mm2(
    const float* __restrict__ A0, const float* __restrict__ B0,
    const float* __restrict__ bias0, float* __restrict__ C0, int rows0, int N0,
    const float* __restrict__ A1, const float* __restrict__ B1,
    const float* __restrict__ bias1, float* __restrict__ C1, int N1)
{
    __shared__ float As[512];
    __shared__ float red[256];
    const float *A, *Bm, *bias; float* C; int m, N;
    if ((int)blockIdx.x < rows0) { A = A0; Bm = B0; bias = bias0; C = C0; m = blockIdx.x; N = N0; }
    else { A = A1; Bm = B1; bias = bias1; C = C1; m = blockIdx.x - rows0; N = N1; }
    int j0 = blockIdx.y * 64;
    if (j0 >= N) return;
    int tid = threadIdx.x, jl = tid & 63, ks = tid >> 6;
    for (int k = tid; k < 512; k += 256) As[k] = A[m * 512 + k];
    __syncthreads();
    int j = j0 + jl;
    float acc = 0.0f;
    if (j < N) {
        int k0 = ks * 128;
#pragma unroll 8
        for (int k = k0; k < k0 + 128; ++k) acc += As[k] * Bm[k * N + j];
    }
    red[tid] = acc;
    __syncthreads();
    if (tid < 64 && j < N)
        C[m * N + j] = red[tid] + red[tid + 64] + red[tid + 128] + red[tid + 192] + bias[j];
}

// ============================================================
extern "C" void kernel_launch(void* const* d_in, const int* in_sizes, int n_in,
                              void* d_out, int out_size) {
    const float* x       = (const float*)d_in[0];
    const float* boxes   = (const float*)d_in[1];
    const int*   cat     = (const int*)d_in[2];
    const float* conv5_w = (const float*)d_in[3];
    const float* re_w    = (const float*)d_in[4];
    const float* re_b    = (const float*)d_in[5];
    const float* oc1_w   = (const float*)d_in[6];
    const float* oc1_b   = (const float*)d_in[7];
    const float* oc2_w   = (const float*)d_in[8];
    const float* oc2_b   = (const float*)d_in[9];
    const float* pr1_w   = (const float*)d_in[10];
    const float* pr1_b   = (const float*)d_in[11];
    const float* pr2_w   = (const float*)d_in[12];
    const float* pr2_b   = (const float*)d_in[13];

    float* out     = (float*)d_out;
    float* cls_out = out;                       // 16*174
    float* obj_cls = out + 16 * 174;            // 32*301
    float* labels  = out + 16 * 174 + 32 * 301; // 32

    float *p_objf, *p_pooled, *p_h1, *p_g1;
    cudaGetSymbolAddress((void**)&p_objf,   d_objf);
    cudaGetSymbolAddress((void**)&p_pooled, d_pooled);
    cudaGetSymbolAddress((void**)&p_h1,     d_h1);
    cudaGetSymbolAddress((void**)&p_g1,     d_g1);

    cudaFuncSetAttribute(pool_kernel, cudaFuncAttributeMaxDynamicSharedMemorySize, POOL_SMEM);
    cudaFuncSetAttribute(gemm1k, cudaFuncAttributeMaxDynamicSharedMemorySize, GSMEM_BYTES);
    cudaFuncSetAttribute(gemm2k, cudaFuncAttributeMaxDynamicSharedMemorySize, GSMEM_BYTES);

    // Order keeps gemm1k as the 4th launch (the one ncu captures).
    convw_kernel<<<(CI * CIN) / 256, 256>>>(conv5_w);
    build_table<<<2, 256>>>(boxes);
    pool_kernel<<<dim3(CIN / (32 * PCHUNKS), B_ * T_), 288, POOL_SMEM>>>(x);
    gemm1k<<<dim3(CI / 128, M1 / 128), 512, GSMEM_BYTES>>>();
    convrw_kernel<<<dim3(16, 16, 9), 256>>>(re_w);
    gemm2k<<<dim3(CI / 128, NROI / 128, NPART), 512, GSMEM_BYTES>>>();
    reduce_a<<<dim3(16, 4), 512>>>(re_b);
    reduce_b<<<16, 512>>>(cat, labels);
    small_mm2<<<dim3(48, 8), 256>>>(p_objf, oc1_w, oc1_b, p_h1, 32, 512,
                                    p_pooled, pr1_w, pr1_b, p_g1, 512);
    small_mm2<<<dim3(48, 5), 256>>>(p_h1, oc2_w, oc2_b, obj_cls, 32, 301,
                                    p_g1, pr2_w, pr2_b, cls_out, 174);
}

// round 13
// speedup vs baseline: 2.4982x; 1.1495x over previous
#include <cuda_runtime.h>
#include <cuda_fp16.h>
#include <cstdint>

// ---------------- problem constants ----------------
#define B_    16
#define T_    8
#define CIN   2048
#define CI    512
#define HF    14
#define HW    196
#define NROI  512
#define M1    4608          // NROI*9
#define KFEAT 4608          // CI*9
#define NPART 8             // split-K parts for gemm2

// ---------------- scratch (static device memory) ----------------
__device__ __half d_roisH[(size_t)M1 * CIN];
__device__ __half d_wH[(size_t)CI * CIN];
__device__ __half d_rwH[(size_t)CI * KFEAT];       // re_w transposed+permuted [n][bin*512+o]
__device__ __half d_featsH[(size_t)NROI * KFEAT];  // [roi][bin*512+o]
__device__ float d_regpart[(size_t)NPART * NROI * CI];
__device__ float d_snb[64 * CI];
__device__ float d_objf[32 * CI];
__device__ float d_pooled[16 * CI];
__device__ float d_h1[32 * CI];
__device__ float d_g1[16 * CI];
__device__ int2  d_tap[NROI * 9 * 16];   // {byte-offset into 197-float row, weight bits}

// ---------------- PTX helpers ----------------
__device__ __forceinline__ uint32_t sm_u32(const void* p) {
    return (uint32_t)__cvta_generic_to_shared(p);
}
__device__ __forceinline__ void cpa16(uint32_t dst, const void* src) {
    asm volatile("cp.async.cg.shared.global [%0], [%1], 16;\n" :: "r"(dst), "l"(src));
}
__device__ __forceinline__ void cpa_commit() {
    asm volatile("cp.async.commit_group;\n" ::: "memory");
}
__device__ __forceinline__ void cpa_wait3() {
    asm volatile("cp.async.wait_group 3;\n" ::: "memory");
}
__device__ __forceinline__ void ldsm4(uint32_t* r, uint32_t addr) {
    asm volatile("ldmatrix.sync.aligned.m8n8.x4.shared.b16 {%0,%1,%2,%3}, [%4];"
                 : "=r"(r[0]), "=r"(r[1]), "=r"(r[2]), "=r"(r[3]) : "r"(addr));
}
__device__ __forceinline__ void mma16816h(float* c, const uint32_t* a, uint32_t b0, uint32_t b1) {
    asm volatile("mma.sync.aligned.m16n8k16.row.col.f32.f16.f16.f32 "
                 "{%0,%1,%2,%3},{%4,%5,%6,%7},{%8,%9},{%0,%1,%2,%3};"
                 : "+f"(c[0]), "+f"(c[1]), "+f"(c[2]), "+f"(c[3])
                 : "r"(a[0]), "r"(a[1]), "r"(a[2]), "r"(a[3]), "r"(b0), "r"(b1));
}

// ============================================================
// K1: ROI-align tap table (byte offsets, weights folded w/ 0.25 mean)
// ============================================================
__global__ void build_table(const float* __restrict__ boxes) {
    int roi = blockIdx.x * blockDim.x + threadIdx.x;
    if (roi >= NROI) return;
    float cx = boxes[roi * 4 + 0], cy = boxes[roi * 4 + 1];
    float w  = boxes[roi * 4 + 2], h  = boxes[roi * 4 + 3];
    const float s = 14.0f / 224.0f;
    float x1 = (cx - 0.5f * w) * 224.0f * s;
    float y1 = (cy - 0.5f * h) * 224.0f * s;
    float x2 = (cx + 0.5f * w) * 224.0f * s;
    float y2 = (cy + 0.5f * h) * 224.0f * s;
    float rw = fmaxf(x2 - x1, 1.0f), rh = fmaxf(y2 - y1, 1.0f);
    float bw = rw / 3.0f, bh = rh / 3.0f;

    float ys[6], xs[6];
#pragma unroll
    for (int p = 0; p < 3; ++p)
#pragma unroll
        for (int i = 0; i < 2; ++i) {
            ys[p * 2 + i] = y1 + p * bh + (i + 0.5f) * bh * 0.5f;
            xs[p * 2 + i] = x1 + p * bw + (i + 0.5f) * bw * 0.5f;
        }

#pragma unroll
    for (int ph = 0; ph < 3; ++ph)
#pragma unroll
        for (int pw = 0; pw < 3; ++pw) {
            int bin = ph * 3 + pw;
#pragma unroll
            for (int iy = 0; iy < 2; ++iy)
#pragma unroll
                for (int ix = 0; ix < 2; ++ix) {
                    int smp = iy * 2 + ix;
                    float yy = ys[ph * 2 + iy];
                    float xx = xs[pw * 2 + ix];
                    bool valid = (yy > -1.0f) && (yy < 14.0f) && (xx > -1.0f) && (xx < 14.0f);
                    float y = fminf(fmaxf(yy, 0.0f), 13.0f);
                    float x = fminf(fmaxf(xx, 0.0f), 13.0f);
                    int y0 = (int)floorf(y), x0 = (int)floorf(x);
                    int y1i = min(y0 + 1, 13), x1i = min(x0 + 1, 13);
                    float ly = y - (float)y0, lx = x - (float)x0;
                    float hy = 1.0f - ly, hx = 1.0f - lx;
                    float q = valid ? 0.25f : 0.0f;
                    int base = (roi * 9 + bin) * 16 + smp * 4;
                    d_tap[base + 0] = make_int2((y0 * HF + x0) * 4,   __float_as_int(hy * hx * q));
                    d_tap[base + 1] = make_int2((y0 * HF + x1i) * 4,  __float_as_int(hy * lx * q));
                    d_tap[base + 2] = make_int2((y1i * HF + x0) * 4,  __float_as_int(ly * hx * q));
                    d_tap[base + 3] = make_int2((y1i * HF + x1i) * 4, __float_as_int(ly * lx * q));
                }
        }
}

// ============================================================
// K2: pooling in 2048-ch space -> fp16 (single precision copy)
// 4 chunks of 32 channels per block, 2 smem buffers (dynamic),
// register-staged LDG double-buffering (overlap DRAM with gather)
// ============================================================
#define PCHUNKS 4
#define PLDG    6    // ceil(1568/288) float4 loads per thread per chunk
#define PBUF_E  (32 * 197)
#define POOL_SMEM (2 * PBUF_E * 4 + 576 * 8)   // 55040 B -> dynamic
__global__ __launch_bounds__(288) void pool_kernel(const float* __restrict__ x) {
    extern __shared__ float psm[];
    float* pl0 = psm;                       // [32][197]
    float* pl1 = psm + PBUF_E;              // [32][197]
    int2*  taps = (int2*)(psm + 2 * PBUF_E);

    int bt = blockIdx.y;
    int tid = threadIdx.x, lane = tid & 31, wid = tid >> 5;
    int cbase = blockIdx.x * (32 * PCHUNKS);

    // x layout (B, C, T, H, W); plane = 196 contiguous floats, 16B-aligned
    size_t xbase = ((size_t)(bt >> 3) * CIN + cbase) * (size_t)(T_ * HW) + (size_t)(bt & 7) * HW;

    for (int i = tid; i < 576; i += 288) taps[i] = d_tap[bt * 576 + i];

    float4 v[PLDG];
    auto ldgc = [&](int c) {
#pragma unroll
        for (int q = 0; q < PLDG; ++q) {
            int i = tid + q * 288;
            if (i < 1568) {
                int ch = i / 49, p = i - ch * 49;
                v[q] = *(const float4*)(x + xbase + (size_t)(c * 32 + ch) * (T_ * HW) + p * 4);
            }
        }
    };
    auto stsc = [&](float* buf) {
#pragma unroll
        for (int q = 0; q < PLDG; ++q) {
            int i = tid + q * 288;
            if (i < 1568) {
                int ch = i / 49, p = i - ch * 49;
                float* d = buf + ch * 197 + p * 4;
                d[0] = v[q].x; d[1] = v[q].y; d[2] = v[q].z; d[3] = v[q].w;
            }
        }
    };

    ldgc(0);
    stsc(pl0);
    __syncthreads();     // covers taps + buf0

#pragma unroll
    for (int c = 0; c < PCHUNKS; ++c) {
        if (c + 1 < PCHUNKS) ldgc(c + 1);          // DRAM overlapped with compute

        const char* bp = (const char*)((c & 1) ? (pl1 + lane * 197) : (pl0 + lane * 197));
#pragma unroll
        for (int j = 0; j < 4; ++j) {
            int e = wid + 9 * j;                   // nb*9+bin
            const int2* tp = &taps[e * 16];
            float a = 0.0f;
#pragma unroll
            for (int t = 0; t < 16; ++t) {
                int2 pw = tp[t];                   // broadcast LDS.64
                a += __int_as_float(pw.y) * *(const float*)(bp + pw.x);
            }
            size_t off = (size_t)(bt * 36 + e) * CIN + cbase + c * 32 + lane;
            d_roisH[off] = __float2half_rn(a);
        }

        if (c + 1 < PCHUNKS) {
            stsc(((c + 1) & 1) ? pl1 : pl0);       // writes other buffer: no WAR
            __syncthreads();                       // visible before next compute
        }
    }
}

// ============================================================
// K3a: convert conv5_w -> fp16
// ============================================================
__global__ void convw_kernel(const float* __restrict__ w) {
    int i = blockIdx.x * 256 + threadIdx.x;
    d_wH[i] = __float2half_rn(w[i]);
}

// ============================================================
// K3b: convert re_w -> transposed+permuted fp16
// ============================================================
__global__ __launch_bounds__(256) void convrw_kernel(const float* __restrict__ w) {
    __shared__ float t[32][33];
    int o0 = blockIdx.x * 32, n0 = blockIdx.y * 32, bin = blockIdx.z;
    int tx = threadIdx.x & 31, ty = threadIdx.x >> 5;
    for (int r = ty; r < 32; r += 8)
        t[r][tx] = w[((size_t)((o0 + r) * 9 + bin)) * 512 + n0 + tx];
    __syncthreads();
    for (int r = ty; r < 32; r += 8) {
        size_t off = (size_t)(n0 + r) * KFEAT + bin * 512 + o0 + tx;
        d_rwH[off] = __float2half_rn(t[tx][r]);
    }
}

// ============================================================
// GEMM core: 128x128 tile, 512 threads (16 warps, warp tile 32x32),
// SINGLE-pass fp16 (A*B), 5-stage cp.async, 2 tiles/stage (A, B)
// ============================================================
#define KT     32
#define SROW   40
#define TILE_E (128 * SROW)
#define STAGE_E (2 * TILE_E)
#define NSTAGE 5
#define GSMEM_BYTES (NSTAGE * STAGE_E * 2)

__device__ __forceinline__ void gemm_core(
    const __half* __restrict__ gA, int lda,
    const __half* __restrict__ gB, int ldb,
    int bm, int bn, int kbase, int niter,
    __half* sm, float (&acc)[2][4][4])
{
    int tid = threadIdx.x, lane = tid & 31, wid = tid >> 5;
    int wm = wid >> 2, wn = wid & 3;     // 4x4 warp grid, warp tile 32x32

    auto ldg = [&](int t) {
        int s = t % NSTAGE;
        int k0 = kbase + t * KT;
        __half* base = sm + s * STAGE_E;
        int row = tid >> 2, c = tid & 3;   // 512 threads = 128 rows x 4 chunks
        __half* pd = base + row * SROW + c * 8;
        cpa16(sm_u32(pd),          gA + (size_t)(bm + row) * lda + k0 + c * 8);
        cpa16(sm_u32(pd + TILE_E), gB + (size_t)(bn + row) * ldb + k0 + c * 8);
    };

    int ar  = wm * 32 + (lane & 15);
    int ac8 = (lane >> 4) * 8;
    int br  = wn * 32 + (lane & 7) + ((lane >> 4) << 3);
    int bc8 = ((lane >> 3) & 1) * 8;

    // prologue: exactly 4 committed groups (pad with empty if short)
#pragma unroll
    for (int s = 0; s < 4; ++s) {
        if (s < niter) ldg(s);
        cpa_commit();
    }

#pragma unroll 1
    for (int t = 0; t < niter; ++t) {
        cpa_wait3();            // stage t guaranteed complete
        __syncthreads();        // all warps done reading stage (t-1)%NSTAGE
        if (t + 4 < niter) ldg(t + 4);
        cpa_commit();           // empty at tail -> uniform pending count

        __half* base = sm + (t % NSTAGE) * STAGE_E;
        const __half* pA = base;
        const __half* pB = base + TILE_E;

        // all fragments for both ks slices up-front (8 ldsm)
        uint32_t ah[2][2][4], bh[2][2][4];
#pragma unroll
        for (int ks = 0; ks < 2; ++ks) {
#pragma unroll
            for (int mt = 0; mt < 2; ++mt)
                ldsm4(ah[ks][mt], sm_u32(pA + (ar + mt * 16) * SROW + ks * 16 + ac8));
#pragma unroll
            for (int bt2 = 0; bt2 < 2; ++bt2)
                ldsm4(bh[ks][bt2], sm_u32(pB + (br + bt2 * 16) * SROW + ks * 16 + bc8));
        }
        // 16 MMAs, same-acc reuse distance = 8
#pragma unroll
        for (int ks = 0; ks < 2; ++ks)
#pragma unroll
            for (int mt = 0; mt < 2; ++mt)
#pragma unroll
                for (int nt = 0; nt < 4; ++nt)
                    mma16816h(acc[mt][nt], ah[ks][mt],
                              bh[ks][nt >> 1][(nt & 1) * 2], bh[ks][nt >> 1][(nt & 1) * 2 + 1]);
    }
}

// ============================================================
// K4: GEMM1: feats = rois2048[4608,2048] x conv5_w[512,2048]^T
// ============================================================
__global__ __launch_bounds__(512) void gemm1k() {
    extern __shared__ __half sm[];
    int bm = blockIdx.y * 128, bn = blockIdx.x * 128;
    float acc[2][4][4];
#pragma unroll
    for (int a = 0; a < 2; ++a)
#pragma unroll
        for (int b = 0; b < 4; ++b)
#pragma unroll
            for (int c = 0; c < 4; ++c) acc[a][b][c] = 0.0f;

    gemm_core(d_roisH, CIN, d_wH, CIN, bm, bn, 0, CIN / KT, sm, acc);

    int lane = threadIdx.x & 31, wid = threadIdx.x >> 5;
    int wm = wid >> 2, wn = wid & 3;
    int mrow = wm * 32 + (lane >> 2);
    int ncol = wn * 32 + ((lane & 3) << 1);
#pragma unroll
    for (int mt = 0; mt < 2; ++mt)
#pragma unroll
        for (int nt = 0; nt < 4; ++nt) {
            float* c = acc[mt][nt];
            int n = bn + ncol + nt * 8;
#pragma unroll
            for (int half = 0; half < 2; ++half) {
                int m = bm + mrow + mt * 16 + half * 8;
                int roi = m / 9, bin = m - roi * 9;
                size_t off = (size_t)roi * KFEAT + bin * 512 + n;
                __half2 hp;
                hp.x = __float2half_rn(c[half * 2 + 0]);
                hp.y = __float2half_rn(c[half * 2 + 1]);
                *(__half2*)&d_featsH[off] = hp;
            }
        }
}

// ============================================================
// K5: GEMM2 (split-K=8): regpart = feats[512,4608] x rw[512,4608]^T
// ============================================================
__global__ __launch_bounds__(512) void gemm2k() {
    extern __shared__ __half sm[];
    int bm = blockIdx.y * 128, bn = blockIdx.x * 128;
    int part = blockIdx.z;
    float acc[2][4][4];
#pragma unroll
    for (int a = 0; a < 2; ++a)
#pragma unroll
        for (int b = 0; b < 4; ++b)
#pragma unroll
            for (int c = 0; c < 4; ++c) acc[a][b][c] = 0.0f;

    gemm_core(d_featsH, KFEAT, d_rwH, KFEAT,
              bm, bn, part * (KFEAT / NPART), (KFEAT / NPART) / KT, sm, acc);

    int lane = threadIdx.x & 31, wid = threadIdx.x >> 5;
    int wm = wid >> 2, wn = wid & 3;
    int mrow = wm * 32 + (lane >> 2);
    int ncol = wn * 32 + ((lane & 3) << 1);
    float* C = d_regpart + (size_t)part * NROI * CI;
#pragma unroll
    for (int mt = 0; mt < 2; ++mt)
#pragma unroll
        for (int nt = 0; nt < 4; ++nt) {
            float* c = acc[mt][nt];
            int n = bn + ncol + nt * 8;
#pragma unroll
            for (int half = 0; half < 2; ++half) {
                int m = bm + mrow + mt * 16 + half * 8;
                *(float2*)&C[(size_t)m * CI + n] = make_float2(c[half * 2], c[half * 2 + 1]);
            }
        }
}

// ============================================================
// K6a: per-(b,nb): s = 0.125 * sum_t relu(bias + sum_p parts)
// ============================================================
__global__ void reduce_a(const float* __restrict__ re_b) {
    int b = blockIdx.x, nb = blockIdx.y, j = threadIdx.x;
    float bias = re_b[j];
    float s = 0.0f;
#pragma unroll
    for (int t = 0; t < 8; ++t) {
        int r = (b * 8 + t) * 4 + nb;
        float v = bias;
#pragma unroll
        for (int p = 0; p < NPART; ++p)
            v += d_regpart[(size_t)p * NROI * CI + (size_t)r * CI + j];
        s += fmaxf(v, 0.0f);
    }
    s *= 0.125f;
    d_snb[(b * 4 + nb) * CI + j] = s;
    if (nb >= 2) d_objf[(b * 2 + nb - 2) * CI + j] = s;   // argsort identity: cats never 0
}

// ============================================================
// K6b: pooled = mean over nb; labels
// ============================================================
__global__ void reduce_b(const int* __restrict__ cat, float* __restrict__ out_labels) {
    int b = blockIdx.x, j = threadIdx.x;
    float p = 0.25f * (d_snb[(b * 4 + 0) * CI + j] + d_snb[(b * 4 + 1) * CI + j] +
                       d_snb[(b * 4 + 2) * CI + j] + d_snb[(b * 4 + 3) * CI + j]);
    d_pooled[b * CI + j] = p;
    if (j < 2) out_labels[b * 2 + j] = (float)cat[b * 4 + 2 + j];
}

// ============================================================
// K7: fused small dense heads (two independent GEMMs per stage)
// ============================================================
__global__ __launch_bounds__(256) void small_mm2(
    const float* __restrict__ A0, const float* __restrict__ B0,
    const float* __restrict__ bias0, float* __restrict__ C0, int rows0, int N0,
    const float* __restrict__ A1, const float* __restrict__ B1,
    const float* __restrict__ bias1, float* __restrict__ C1, int N1)
{
    __shared__ float As[512];
    __shared__ float red[256];
    const float *A, *Bm, *bias; float* C; int m, N;
    if ((int)blockIdx.x < rows0) { A = A0; Bm = B0; bias = bias0; C = C0; m = blockIdx.x; N = N0; }
    else { A = A1; Bm = B1; bias = bias1; C = C1; m = blockIdx.x - rows0; N = N1; }
    int j0 = blockIdx.y * 64;
    if (j0 >= N) return;
    int tid = threadIdx.x, jl = tid & 63, ks = tid >> 6;
    for (int k = tid; k < 512; k += 256) As[k] = A[m * 512 + k];
    __syncthreads();
    int j = j0 + jl;
    float acc = 0.0f;
    if (j < N) {
        int k0 = ks * 128;
#pragma unroll 8
        for (int k = k0; k < k0 + 128; ++k) acc += As[k] * Bm[k * N + j];
    }
    red[tid] = acc;
    __syncthreads();
    if (tid < 64 && j < N)
        C[m * N + j] = red[tid] + red[tid + 64] + red[tid + 128] + red[tid + 192] + bias[j];
}

// ============================================================
extern "C" void kernel_launch(void* const* d_in, const int* in_sizes, int n_in,
                              void* d_out, int out_size) {
    const float* x       = (const float*)d_in[0];
    const float* boxes   = (const float*)d_in[1];
    const int*   cat     = (const int*)d_in[2];
    const float* conv5_w = (const float*)d_in[3];
    const float* re_w    = (const float*)d_in[4];
    const float* re_b    = (const float*)d_in[5];
    const float* oc1_w   = (const float*)d_in[6];
    const float* oc1_b   = (const float*)d_in[7];
    const float* oc2_w   = (const float*)d_in[8];
    const float* oc2_b   = (const float*)d_in[9];
    const float* pr1_w   = (const float*)d_in[10];
    const float* pr1_b   = (const float*)d_in[11];
    const float* pr2_w   = (const float*)d_in[12];
    const float* pr2_b   = (const float*)d_in[13];

    float* out     = (float*)d_out;
    float* cls_out = out;                       // 16*174
    float* obj_cls = out + 16 * 174;            // 32*301
    float* labels  = out + 16 * 174 + 32 * 301; // 32

    float *p_objf, *p_pooled, *p_h1, *p_g1;
    cudaGetSymbolAddress((void**)&p_objf,   d_objf);
    cudaGetSymbolAddress((void**)&p_pooled, d_pooled);
    cudaGetSymbolAddress((void**)&p_h1,     d_h1);
    cudaGetSymbolAddress((void**)&p_g1,     d_g1);

    cudaFuncSetAttribute(pool_kernel, cudaFuncAttributeMaxDynamicSharedMemorySize, POOL_SMEM);
    cudaFuncSetAttribute(gemm1k, cudaFuncAttributeMaxDynamicSharedMemorySize, GSMEM_BYTES);
    cudaFuncSetAttribute(gemm2k, cudaFuncAttributeMaxDynamicSharedMemorySize, GSMEM_BYTES);

    // Order keeps gemm1k as the 4th launch (the one ncu captures).
    convw_kernel<<<(CI * CIN) / 256, 256>>>(conv5_w);
    build_table<<<2, 256>>>(boxes);
    pool_kernel<<<dim3(CIN / (32 * PCHUNKS), B_ * T_), 288, POOL_SMEM>>>(x);
    gemm1k<<<dim3(CI / 128, M1 / 128), 512, GSMEM_BYTES>>>();
    convrw_kernel<<<dim3(16, 16, 9), 256>>>(re_w);
    gemm2k<<<dim3(CI / 128, NROI / 128, NPART), 512, GSMEM_BYTES>>>();
    reduce_a<<<dim3(16, 4), 512>>>(re_b);
    reduce_b<<<16, 512>>>(cat, labels);
    small_mm2<<<dim3(48, 8), 256>>>(p_objf, oc1_w, oc1_b, p_h1, 32, 512,
                                    p_pooled, pr1_w, pr1_b, p_g1, 512);
    small_mm2<<<dim3(48, 5), 256>>>(p_h1, oc2_w, oc2_b, obj_cls, 32, 301,
                                    p_g1, pr2_w, pr2_b, cls_out, 174);
}

// round 14
// speedup vs baseline: 2.6557x; 1.0630x over previous
#include <cuda_runtime.h>
#include <cuda_fp16.h>
#include <cstdint>

// ---------------- problem constants ----------------
#define B_    16
#define T_    8
#define CIN   2048
#define CI    512
#define HF    14
#define HW    196
#define NROI  512
#define M1    4608          // NROI*9
#define KFEAT 4608          // CI*9
#define NPART 8             // split-K parts for gemm2

// ---------------- scratch (static device memory) ----------------
__device__ __half d_roisH[(size_t)M1 * CIN];
__device__ __half d_wH[(size_t)CI * CIN];
__device__ __half d_rwH[(size_t)CI * KFEAT];       // re_w transposed+permuted [n][bin*512+o]
__device__ __half d_featsH[(size_t)NROI * KFEAT];  // [roi][bin*512+o]
__device__ float d_regpart[(size_t)NPART * NROI * CI];
__device__ float d_snb[64 * CI];
__device__ float d_objf[32 * CI];
__device__ float d_pooled[16 * CI];
__device__ float d_h1[32 * CI];
__device__ float d_g1[16 * CI];
__device__ int2  d_tap[NROI * 9 * 16];   // {byte-offset into 197-float row, weight bits}

// ---------------- PTX helpers ----------------
__device__ __forceinline__ uint32_t sm_u32(const void* p) {
    return (uint32_t)__cvta_generic_to_shared(p);
}
__device__ __forceinline__ void cpa16(uint32_t dst, const void* src) {
    asm volatile("cp.async.cg.shared.global [%0], [%1], 16;\n" :: "r"(dst), "l"(src));
}
__device__ __forceinline__ void cpa_commit() {
    asm volatile("cp.async.commit_group;\n" ::: "memory");
}
__device__ __forceinline__ void cpa_wait3() {
    asm volatile("cp.async.wait_group 3;\n" ::: "memory");
}
__device__ __forceinline__ void ldsm4(uint32_t* r, uint32_t addr) {
    asm volatile("ldmatrix.sync.aligned.m8n8.x4.shared.b16 {%0,%1,%2,%3}, [%4];"
                 : "=r"(r[0]), "=r"(r[1]), "=r"(r[2]), "=r"(r[3]) : "r"(addr));
}
__device__ __forceinline__ void mma16816h(float* c, const uint32_t* a, uint32_t b0, uint32_t b1) {
    asm volatile("mma.sync.aligned.m16n8k16.row.col.f32.f16.f16.f32 "
                 "{%0,%1,%2,%3},{%4,%5,%6,%7},{%8,%9},{%0,%1,%2,%3};"
                 : "+f"(c[0]), "+f"(c[1]), "+f"(c[2]), "+f"(c[3])
                 : "r"(a[0]), "r"(a[1]), "r"(a[2]), "r"(a[3]), "r"(b0), "r"(b1));
}

// ============================================================
// K0: merged prep: [0] build_table (2 blocks), then convw (4096),
// then convrw (2304) — branch by blockIdx.x
// ============================================================
#define PREP_BT   2
#define PREP_CW   (CI * CIN / 256)          // 4096
#define PREP_CRW  (16 * 16 * 9)             // 2304
__global__ __launch_bounds__(256) void prep_kernel(
    const float* __restrict__ boxes,
    const float* __restrict__ conv5_w,
    const float* __restrict__ re_w)
{
    int bid = blockIdx.x;
    if (bid < PREP_BT) {
        // ---- build ROI tap table ----
        int roi = bid * 256 + threadIdx.x;
        if (roi >= NROI) return;
        float cx = boxes[roi * 4 + 0], cy = boxes[roi * 4 + 1];
        float w  = boxes[roi * 4 + 2], h  = boxes[roi * 4 + 3];
        const float s = 14.0f / 224.0f;
        float x1 = (cx - 0.5f * w) * 224.0f * s;
        float y1 = (cy - 0.5f * h) * 224.0f * s;
        float x2 = (cx + 0.5f * w) * 224.0f * s;
        float y2 = (cy + 0.5f * h) * 224.0f * s;
        float rw = fmaxf(x2 - x1, 1.0f), rh = fmaxf(y2 - y1, 1.0f);
        float bw = rw / 3.0f, bh = rh / 3.0f;
        float ys[6], xs[6];
#pragma unroll
        for (int p = 0; p < 3; ++p)
#pragma unroll
            for (int i = 0; i < 2; ++i) {
                ys[p * 2 + i] = y1 + p * bh + (i + 0.5f) * bh * 0.5f;
                xs[p * 2 + i] = x1 + p * bw + (i + 0.5f) * bw * 0.5f;
            }
#pragma unroll
        for (int ph = 0; ph < 3; ++ph)
#pragma unroll
            for (int pw = 0; pw < 3; ++pw) {
                int bin = ph * 3 + pw;
#pragma unroll
                for (int iy = 0; iy < 2; ++iy)
#pragma unroll
                    for (int ix = 0; ix < 2; ++ix) {
                        int smp = iy * 2 + ix;
                        float yy = ys[ph * 2 + iy];
                        float xx = xs[pw * 2 + ix];
                        bool valid = (yy > -1.0f) && (yy < 14.0f) && (xx > -1.0f) && (xx < 14.0f);
                        float y = fminf(fmaxf(yy, 0.0f), 13.0f);
                        float x = fminf(fmaxf(xx, 0.0f), 13.0f);
                        int y0 = (int)floorf(y), x0 = (int)floorf(x);
                        int y1i = min(y0 + 1, 13), x1i = min(x0 + 1, 13);
                        float ly = y - (float)y0, lx = x - (float)x0;
                        float hy = 1.0f - ly, hx = 1.0f - lx;
                        float q = valid ? 0.25f : 0.0f;
                        int base = (roi * 9 + bin) * 16 + smp * 4;
                        d_tap[base + 0] = make_int2((y0 * HF + x0) * 4,   __float_as_int(hy * hx * q));
                        d_tap[base + 1] = make_int2((y0 * HF + x1i) * 4,  __float_as_int(hy * lx * q));
                        d_tap[base + 2] = make_int2((y1i * HF + x0) * 4,  __float_as_int(ly * hx * q));
                        d_tap[base + 3] = make_int2((y1i * HF + x1i) * 4, __float_as_int(ly * lx * q));
                    }
            }
    } else if (bid < PREP_BT + PREP_CW) {
        // ---- conv5_w -> fp16 ----
        int i = (bid - PREP_BT) * 256 + threadIdx.x;
        d_wH[i] = __float2half_rn(conv5_w[i]);
    } else {
        // ---- re_w -> transposed+permuted fp16 ----
        __shared__ float t[32][33];
        int cb = bid - PREP_BT - PREP_CW;          // 0..2303 = (o16,n16,bin9)
        int bin = cb / 256;
        int rem = cb - bin * 256;
        int o0 = (rem >> 4) * 32, n0 = (rem & 15) * 32;
        int tx = threadIdx.x & 31, ty = threadIdx.x >> 5;
        for (int r = ty; r < 32; r += 8)
            t[r][tx] = re_w[((size_t)((o0 + r) * 9 + bin)) * 512 + n0 + tx];
        __syncthreads();
        for (int r = ty; r < 32; r += 8) {
            size_t off = (size_t)(n0 + r) * KFEAT + bin * 512 + o0 + tx;
            d_rwH[off] = __float2half_rn(t[tx][r]);
        }
    }
}

// ============================================================
// K2: pooling in 2048-ch space -> fp16
// 4 chunks of 32 channels per block, 2 smem buffers (dynamic),
// register-staged LDG double-buffering
// ============================================================
#define PCHUNKS 4
#define PLDG    6
#define PBUF_E  (32 * 197)
#define POOL_SMEM (2 * PBUF_E * 4 + 576 * 8)
__global__ __launch_bounds__(288) void pool_kernel(const float* __restrict__ x) {
    extern __shared__ float psm[];
    float* pl0 = psm;
    float* pl1 = psm + PBUF_E;
    int2*  taps = (int2*)(psm + 2 * PBUF_E);

    int bt = blockIdx.y;
    int tid = threadIdx.x, lane = tid & 31, wid = tid >> 5;
    int cbase = blockIdx.x * (32 * PCHUNKS);

    size_t xbase = ((size_t)(bt >> 3) * CIN + cbase) * (size_t)(T_ * HW) + (size_t)(bt & 7) * HW;

    for (int i = tid; i < 576; i += 288) taps[i] = d_tap[bt * 576 + i];

    float4 v[PLDG];
    auto ldgc = [&](int c) {
#pragma unroll
        for (int q = 0; q < PLDG; ++q) {
            int i = tid + q * 288;
            if (i < 1568) {
                int ch = i / 49, p = i - ch * 49;
                v[q] = *(const float4*)(x + xbase + (size_t)(c * 32 + ch) * (T_ * HW) + p * 4);
            }
        }
    };
    auto stsc = [&](float* buf) {
#pragma unroll
        for (int q = 0; q < PLDG; ++q) {
            int i = tid + q * 288;
            if (i < 1568) {
                int ch = i / 49, p = i - ch * 49;
                float* d = buf + ch * 197 + p * 4;
                d[0] = v[q].x; d[1] = v[q].y; d[2] = v[q].z; d[3] = v[q].w;
            }
        }
    };

    ldgc(0);
    stsc(pl0);
    __syncthreads();

#pragma unroll
    for (int c = 0; c < PCHUNKS; ++c) {
        if (c + 1 < PCHUNKS) ldgc(c + 1);

        const char* bp = (const char*)((c & 1) ? (pl1 + lane * 197) : (pl0 + lane * 197));
#pragma unroll
        for (int j = 0; j < 4; ++j) {
            int e = wid + 9 * j;
            const int2* tp = &taps[e * 16];
            float a = 0.0f;
#pragma unroll
            for (int t = 0; t < 16; ++t) {
                int2 pw = tp[t];
                a += __int_as_float(pw.y) * *(const float*)(bp + pw.x);
            }
            size_t off = (size_t)(bt * 36 + e) * CIN + cbase + c * 32 + lane;
            d_roisH[off] = __float2half_rn(a);
        }

        if (c + 1 < PCHUNKS) {
            stsc(((c + 1) & 1) ? pl1 : pl0);
            __syncthreads();
        }
    }
}

// ============================================================
// GEMM core: 64x128 tile, 256 threads (8 warps, 2x4 grid, warp 32x32),
// single-pass fp16, 5-stage cp.async -> 2 CTAs/SM co-residency
// ============================================================
#define KT     32
#define SROW   40
#define AROWS  64
#define BROWS  128
#define STAGE_E ((AROWS + BROWS) * SROW)
#define NSTAGE 5
#define GSMEM_BYTES (NSTAGE * STAGE_E * 2)

__device__ __forceinline__ void gemm_core(
    const __half* __restrict__ gA, int lda,
    const __half* __restrict__ gB, int ldb,
    int bm, int bn, int kbase, int niter,
    __half* sm, float (&acc)[2][4][4])
{
    int tid = threadIdx.x, lane = tid & 31, wid = tid >> 5;
    int wm = wid >> 2, wn = wid & 3;     // 2x4 warp grid, warp tile 32x32

    auto ldg = [&](int t) {
        int s = t % NSTAGE;
        int k0 = kbase + t * KT;
        __half* base = sm + s * STAGE_E;
#pragma unroll
        for (int q = 0; q < 3; ++q) {    // 768 cp.async over 256 threads
            int idx = tid + q * 256;
            int row = idx >> 2, c = idx & 3;
            __half* pd = base + row * SROW + c * 8;
            const __half* src = (row < AROWS)
                ? gA + (size_t)(bm + row) * lda + k0 + c * 8
                : gB + (size_t)(bn + row - AROWS) * ldb + k0 + c * 8;
            cpa16(sm_u32(pd), src);
        }
    };

    int ar  = wm * 32 + (lane & 15);
    int ac8 = (lane >> 4) * 8;
    int br  = wn * 32 + (lane & 7) + ((lane >> 4) << 3);
    int bc8 = ((lane >> 3) & 1) * 8;

#pragma unroll
    for (int s = 0; s < 4; ++s) {
        if (s < niter) ldg(s);
        cpa_commit();
    }

#pragma unroll 1
    for (int t = 0; t < niter; ++t) {
        cpa_wait3();
        __syncthreads();
        if (t + 4 < niter) ldg(t + 4);
        cpa_commit();

        __half* base = sm + (t % NSTAGE) * STAGE_E;
        const __half* pA = base;
        const __half* pB = base + AROWS * SROW;

        uint32_t ah[2][2][4], bh[2][2][4];
#pragma unroll
        for (int ks = 0; ks < 2; ++ks) {
#pragma unroll
            for (int mt = 0; mt < 2; ++mt)
                ldsm4(ah[ks][mt], sm_u32(pA + (ar + mt * 16) * SROW + ks * 16 + ac8));
#pragma unroll
            for (int bt2 = 0; bt2 < 2; ++bt2)
                ldsm4(bh[ks][bt2], sm_u32(pB + (br + bt2 * 16) * SROW + ks * 16 + bc8));
        }
#pragma unroll
        for (int ks = 0; ks < 2; ++ks)
#pragma unroll
            for (int mt = 0; mt < 2; ++mt)
#pragma unroll
                for (int nt = 0; nt < 4; ++nt)
                    mma16816h(acc[mt][nt], ah[ks][mt],
                              bh[ks][nt >> 1][(nt & 1) * 2], bh[ks][nt >> 1][(nt & 1) * 2 + 1]);
    }
}

// ============================================================
// K4: GEMM1: feats = rois2048[4608,2048] x conv5_w[512,2048]^T
// grid (N/128=4, M/64=72), 256 threads
// ============================================================
__global__ __launch_bounds__(256) void gemm1k() {
    extern __shared__ __half sm[];
    int bm = blockIdx.y * 64, bn = blockIdx.x * 128;
    float acc[2][4][4];
#pragma unroll
    for (int a = 0; a < 2; ++a)
#pragma unroll
        for (int b = 0; b < 4; ++b)
#pragma unroll
            for (int c = 0; c < 4; ++c) acc[a][b][c] = 0.0f;

    gemm_core(d_roisH, CIN, d_wH, CIN, bm, bn, 0, CIN / KT, sm, acc);

    int lane = threadIdx.x & 31, wid = threadIdx.x >> 5;
    int wm = wid >> 2, wn = wid & 3;
    int mrow = wm * 32 + (lane >> 2);
    int ncol = wn * 32 + ((lane & 3) << 1);
#pragma unroll
    for (int mt = 0; mt < 2; ++mt)
#pragma unroll
        for (int nt = 0; nt < 4; ++nt) {
            float* c = acc[mt][nt];
            int n = bn + ncol + nt * 8;
#pragma unroll
            for (int half = 0; half < 2; ++half) {
                int m = bm + mrow + mt * 16 + half * 8;
                int roi = m / 9, bin = m - roi * 9;
                size_t off = (size_t)roi * KFEAT + bin * 512 + n;
                __half2 hp;
                hp.x = __float2half_rn(c[half * 2 + 0]);
                hp.y = __float2half_rn(c[half * 2 + 1]);
                *(__half2*)&d_featsH[off] = hp;
            }
        }
}

// ============================================================
// K5: GEMM2 (split-K=8): regpart = feats[512,4608] x rw[512,4608]^T
// grid (4, 8, NPART), 256 threads
// ============================================================
__global__ __launch_bounds__(256) void gemm2k() {
    extern __shared__ __half sm[];
    int bm = blockIdx.y * 64, bn = blockIdx.x * 128;
    int part = blockIdx.z;
    float acc[2][4][4];
#pragma unroll
    for (int a = 0; a < 2; ++a)
#pragma unroll
        for (int b = 0; b < 4; ++b)
#pragma unroll
            for (int c = 0; c < 4; ++c) acc[a][b][c] = 0.0f;

    gemm_core(d_featsH, KFEAT, d_rwH, KFEAT,
              bm, bn, part * (KFEAT / NPART), (KFEAT / NPART) / KT, sm, acc);

    int lane = threadIdx.x & 31, wid = threadIdx.x >> 5;
    int wm = wid >> 2, wn = wid & 3;
    int mrow = wm * 32 + (lane >> 2);
    int ncol = wn * 32 + ((lane & 3) << 1);
    float* C = d_regpart + (size_t)part * NROI * CI;
#pragma unroll
    for (int mt = 0; mt < 2; ++mt)
#pragma unroll
        for (int nt = 0; nt < 4; ++nt) {
            float* c = acc[mt][nt];
            int n = bn + ncol + nt * 8;
#pragma unroll
            for (int half = 0; half < 2; ++half) {
                int m = bm + mrow + mt * 16 + half * 8;
                *(float2*)&C[(size_t)m * CI + n] = make_float2(c[half * 2], c[half * 2 + 1]);
            }
        }
}

// ============================================================
// K6a: per-(b,nb): s = 0.125 * sum_t relu(bias + sum_p parts)
// ============================================================
__global__ void reduce_a(const float* __restrict__ re_b) {
    int b = blockIdx.x, nb = blockIdx.y, j = threadIdx.x;
    float bias = re_b[j];
    float s = 0.0f;
#pragma unroll
    for (int t = 0; t < 8; ++t) {
        int r = (b * 8 + t) * 4 + nb;
        float v = bias;
#pragma unroll
        for (int p = 0; p < NPART; ++p)
            v += d_regpart[(size_t)p * NROI * CI + (size_t)r * CI + j];
        s += fmaxf(v, 0.0f);
    }
    s *= 0.125f;
    d_snb[(b * 4 + nb) * CI + j] = s;
    if (nb >= 2) d_objf[(b * 2 + nb - 2) * CI + j] = s;   // argsort identity: cats never 0
}

// ============================================================
// K6b: pooled = mean over nb; labels
// ============================================================
__global__ void reduce_b(const int* __restrict__ cat, float* __restrict__ out_labels) {
    int b = blockIdx.x, j = threadIdx.x;
    float p = 0.25f * (d_snb[(b * 4 + 0) * CI + j] + d_snb[(b * 4 + 1) * CI + j] +
                       d_snb[(b * 4 + 2) * CI + j] + d_snb[(b * 4 + 3) * CI + j]);
    d_pooled[b * CI + j] = p;
    if (j < 2) out_labels[b * 2 + j] = (float)cat[b * 4 + 2 + j];
}

// ============================================================
// K7: fused small dense heads
// ============================================================
__global__ __launch_bounds__(256) void small_mm2(
    const float* __restrict__ A0, const float* __restrict__ B0,
    const float* __restrict__ bias0, float* __restrict__ C0, int rows0, int N0,
    const float* __restrict__ A1, const float* __restrict__ B1,
    const float* __restrict__ bias1, float* __restrict__ C1, int N1)
{
    __shared__ float As[512];
    __shared__ float red[256];
    const float *A, *Bm, *bias; float* C; int m, N;
    if ((int)blockIdx.x < rows0) { A = A0; Bm = B0; bias = bias0; C = C0; m = blockIdx.x; N = N0; }
    else { A = A1; Bm = B1; bias = bias1; C = C1; m = blockIdx.x - rows0; N = N1; }
    int j0 = blockIdx.y * 64;
    if (j0 >= N) return;
    int tid = threadIdx.x, jl = tid & 63, ks = tid >> 6;
    for (int k = tid; k < 512; k += 256) As[k] = A[m * 512 + k];
    __syncthreads();
    int j = j0 + jl;
    float acc = 0.0f;
    if (j < N) {
        int k0 = ks * 128;
#pragma unroll 8
        for (int k = k0; k < k0 + 128; ++k) acc += As[k] * Bm[k * N + j];
    }
    red[tid] = acc;
    __syncthreads();
    if (tid < 64 && j < N)
        C[m * N + j] = red[tid] + red[tid + 64] + red[tid + 128] + red[tid + 192] + bias[j];
}

// ============================================================
extern "C" void kernel_launch(void* const* d_in, const int* in_sizes, int n_in,
                              void* d_out, int out_size) {
    const float* x       = (const float*)d_in[0];
    const float* boxes   = (const float*)d_in[1];
    const int*   cat     = (const int*)d_in[2];
    const float* conv5_w = (const float*)d_in[3];
    const float* re_w    = (const float*)d_in[4];
    const float* re_b    = (const float*)d_in[5];
    const float* oc1_w   = (const float*)d_in[6];
    const float* oc1_b   = (const float*)d_in[7];
    const float* oc2_w   = (const float*)d_in[8];
    const float* oc2_b   = (const float*)d_in[9];
    const float* pr1_w   = (const float*)d_in[10];
    const float* pr1_b   = (const float*)d_in[11];
    const float* pr2_w   = (const float*)d_in[12];
    const float* pr2_b   = (const float*)d_in[13];

    float* out     = (float*)d_out;
    float* cls_out = out;                       // 16*174
    float* obj_cls = out + 16 * 174;            // 32*301
    float* labels  = out + 16 * 174 + 32 * 301; // 32

    float *p_objf, *p_pooled, *p_h1, *p_g1;
    cudaGetSymbolAddress((void**)&p_objf,   d_objf);
    cudaGetSymbolAddress((void**)&p_pooled, d_pooled);
    cudaGetSymbolAddress((void**)&p_h1,     d_h1);
    cudaGetSymbolAddress((void**)&p_g1,     d_g1);

    cudaFuncSetAttribute(pool_kernel, cudaFuncAttributeMaxDynamicSharedMemorySize, POOL_SMEM);
    cudaFuncSetAttribute(gemm1k, cudaFuncAttributeMaxDynamicSharedMemorySize, GSMEM_BYTES);
    cudaFuncSetAttribute(gemm2k, cudaFuncAttributeMaxDynamicSharedMemorySize, GSMEM_BYTES);

    prep_kernel<<<PREP_BT + PREP_CW + PREP_CRW, 256>>>(boxes, conv5_w, re_w);
    pool_kernel<<<dim3(CIN / (32 * PCHUNKS), B_ * T_), 288, POOL_SMEM>>>(x);
    gemm1k<<<dim3(CI / 128, M1 / 64), 256, GSMEM_BYTES>>>();
    gemm2k<<<dim3(CI / 128, NROI / 64, NPART), 256, GSMEM_BYTES>>>();
    reduce_a<<<dim3(16, 4), 512>>>(re_b);
    reduce_b<<<16, 512>>>(cat, labels);
    small_mm2<<<dim3(48, 8), 256>>>(p_objf, oc1_w, oc1_b, p_h1, 32, 512,
                                    p_pooled, pr1_w, pr1_b, p_g1, 512);
    small_mm2<<<dim3(48, 5), 256>>>(p_h1, oc2_w, oc2_b, obj_cls, 32, 301,
                                    p_g1, pr2_w, pr2_b, cls_out, 174);
}